// round 1
// baseline (speedup 1.0000x reference)
#include <cuda_runtime.h>
#include <math.h>

#define NL 6
#define NH 6
#define NE 384
#define HS 64
#define NT 256
#define NB 64
#define NV 65
#define MTOT (NB*NT)      /* 16384 rows */
#define FF (4*NE)         /* 1536 */
#define LNEPS 1e-5f

// ---------------- scratch (__device__ globals: allocation-free) ----------------
__device__ float g_x[MTOT*NE];
__device__ float g_h[MTOT*NE];
__device__ float g_q[MTOT*NE];
__device__ float g_k[MTOT*NE];
__device__ float g_v[MTOT*NE];
__device__ float g_o[MTOT*NE];
__device__ float g_mlp[MTOT*FF];
__device__ float g_logits[MTOT*NV];
__device__ double g_loss;

// ---------------- embedding ----------------
__global__ void embed_kernel(const int* __restrict__ idx,
                             const float* __restrict__ tok,
                             const float* __restrict__ pos) {
    int i = blockIdx.x * blockDim.x + threadIdx.x;
    if (i >= MTOT * NE) return;
    int r = i / NE, e = i - r * NE;
    int t = r & (NT - 1);
    g_x[i] = tok[idx[r] * NE + e] + pos[t * NE + e];
}

// ---------------- layernorm (one block of 128 threads per row) ----------------
__global__ void ln_kernel(const float* __restrict__ in, float* __restrict__ out,
                          const float* __restrict__ gw, const float* __restrict__ bw) {
    int r = blockIdx.x;
    const float* row = in + (size_t)r * NE;
    int tid = threadIdx.x;
    float v0 = row[tid], v1 = row[tid + 128], v2 = row[tid + 256];
    float s = v0 + v1 + v2;
    float sq = v0 * v0 + v1 * v1 + v2 * v2;
    __shared__ float sm[8];
    #pragma unroll
    for (int o = 16; o; o >>= 1) {
        s  += __shfl_xor_sync(0xffffffffu, s, o);
        sq += __shfl_xor_sync(0xffffffffu, sq, o);
    }
    if ((tid & 31) == 0) { sm[tid >> 5] = s; sm[4 + (tid >> 5)] = sq; }
    __syncthreads();
    s  = sm[0] + sm[1] + sm[2] + sm[3];
    sq = sm[4] + sm[5] + sm[6] + sm[7];
    float mean = s * (1.0f / NE);
    float var  = sq * (1.0f / NE) - mean * mean;
    float inv  = rsqrtf(var + LNEPS);
    float* orow = out + (size_t)r * NE;
    orow[tid]       = (v0 - mean) * inv * gw[tid]       + bw[tid];
    orow[tid + 128] = (v1 - mean) * inv * gw[tid + 128] + bw[tid + 128];
    orow[tid + 256] = (v2 - mean) * inv * gw[tid + 256] + bw[tid + 256];
}

// ---------------- generic tiled GEMM: C = A[M,K] @ B[K,N] + bias (+res)(+relu) --
// 64x64 tile, 256 threads, 4x4 per thread, BK=16.
template<bool RELU, bool RES, bool NBND>
__global__ void gemm_kernel(const float* __restrict__ A, const float* __restrict__ Bm,
                            const float* __restrict__ bias, const float* __restrict__ res,
                            float* __restrict__ C, int N, int K) {
    __shared__ float As[16][64];
    __shared__ float Bs[16][68];
    int tid = threadIdx.x;
    int tx = tid & 15, ty = tid >> 4;
    int rowBase = blockIdx.x * 64, colBase = blockIdx.y * 64;
    float acc[4][4] = {};
    int la_m = tid >> 2, la_k = (tid & 3) * 4;
    int lb_k = tid >> 4, lb_n = (tid & 15) * 4;
    for (int k0 = 0; k0 < K; k0 += 16) {
        float4 a4 = *(const float4*)(A + (size_t)(rowBase + la_m) * K + k0 + la_k);
        As[la_k + 0][la_m] = a4.x; As[la_k + 1][la_m] = a4.y;
        As[la_k + 2][la_m] = a4.z; As[la_k + 3][la_m] = a4.w;
        #pragma unroll
        for (int u = 0; u < 4; u++) {
            int n = colBase + lb_n + u;
            float val = 0.f;
            if (!NBND || n < N) val = Bm[(size_t)(k0 + lb_k) * N + n];
            Bs[lb_k][lb_n + u] = val;
        }
        __syncthreads();
        #pragma unroll
        for (int kk = 0; kk < 16; kk++) {
            float4 a = *(float4*)&As[kk][ty * 4];
            float4 b = *(float4*)&Bs[kk][tx * 4];
            float av[4] = {a.x, a.y, a.z, a.w};
            float bv[4] = {b.x, b.y, b.z, b.w};
            #pragma unroll
            for (int i = 0; i < 4; i++)
                #pragma unroll
                for (int j = 0; j < 4; j++)
                    acc[i][j] += av[i] * bv[j];
        }
        __syncthreads();
    }
    #pragma unroll
    for (int i = 0; i < 4; i++) {
        int r = rowBase + ty * 4 + i;
        #pragma unroll
        for (int j = 0; j < 4; j++) {
            int c = colBase + tx * 4 + j;
            if (NBND && c >= N) continue;
            float v = acc[i][j] + bias[c];
            if (RES) v += res[(size_t)r * N + c];
            if (RELU) v = fmaxf(v, 0.f);
            C[(size_t)r * N + c] = v;
        }
    }
}

// ---------------- fused QKV GEMM: weights [H,E,HS], out [b,h,t,s] ----------------
__global__ void gemm_qkv_kernel(const float* __restrict__ A,
                                const float* __restrict__ Wq, const float* __restrict__ Wk,
                                const float* __restrict__ Wv,
                                float* __restrict__ Oq, float* __restrict__ Ok,
                                float* __restrict__ Ov) {
    const float* Bm = (blockIdx.z == 0) ? Wq : (blockIdx.z == 1) ? Wk : Wv;
    float* Om       = (blockIdx.z == 0) ? Oq : (blockIdx.z == 1) ? Ok : Ov;
    __shared__ float As[16][64];
    __shared__ float Bs[16][68];
    int tid = threadIdx.x;
    int tx = tid & 15, ty = tid >> 4;
    int rowBase = blockIdx.x * 64, colBase = blockIdx.y * 64;
    float acc[4][4] = {};
    int la_m = tid >> 2, la_k = (tid & 3) * 4;
    int lb_k = tid >> 4, lb_n = (tid & 15) * 4;
    for (int k0 = 0; k0 < NE; k0 += 16) {
        float4 a4 = *(const float4*)(A + (size_t)(rowBase + la_m) * NE + k0 + la_k);
        As[la_k + 0][la_m] = a4.x; As[la_k + 1][la_m] = a4.y;
        As[la_k + 2][la_m] = a4.z; As[la_k + 3][la_m] = a4.w;
        #pragma unroll
        for (int u = 0; u < 4; u++) {
            int n = colBase + lb_n + u;   // n in [0,384)
            int h = n >> 6, s = n & 63;
            Bs[lb_k][lb_n + u] = Bm[((size_t)h * NE + (k0 + lb_k)) * HS + s];
        }
        __syncthreads();
        #pragma unroll
        for (int kk = 0; kk < 16; kk++) {
            float4 a = *(float4*)&As[kk][ty * 4];
            float4 b = *(float4*)&Bs[kk][tx * 4];
            float av[4] = {a.x, a.y, a.z, a.w};
            float bv[4] = {b.x, b.y, b.z, b.w};
            #pragma unroll
            for (int i = 0; i < 4; i++)
                #pragma unroll
                for (int j = 0; j < 4; j++)
                    acc[i][j] += av[i] * bv[j];
        }
        __syncthreads();
    }
    #pragma unroll
    for (int i = 0; i < 4; i++) {
        int r = rowBase + ty * 4 + i;
        int b = r >> 8, t = r & (NT - 1);
        #pragma unroll
        for (int j = 0; j < 4; j++) {
            int c = colBase + tx * 4 + j;
            int h = c >> 6, s = c & 63;
            Om[(((size_t)(b * NH + h)) * NT + t) * HS + s] = acc[i][j];
        }
    }
}

// ---------------- attention: one CTA per (b,h) ----------------
// dyn smem: Ks[256*65] Vs[256*65] qrow[64] arow[256] pb[256] red[9]
#define ATTN_SMEM ((2 * NT * 65 + 64 + 256 + 256 + 9) * (int)sizeof(float))
__global__ void attn_kernel(const float* __restrict__ q, const float* __restrict__ k,
                            const float* __restrict__ v, float* __restrict__ o) {
    extern __shared__ float sm[];
    float* Ks   = sm;
    float* Vs   = Ks + NT * 65;
    float* qrow = Vs + NT * 65;
    float* arow = qrow + 64;
    float* pb   = arow + NT;
    float* red  = pb + NT;
    int bh = blockIdx.x;
    int tid = threadIdx.x;
    const float* kbase = k + (size_t)bh * NT * HS;
    const float* vbase = v + (size_t)bh * NT * HS;
    for (int i = tid; i < NT * HS / 4; i += 256) {
        int u = i >> 4, c = (i & 15) << 2;
        float4 kk4 = *(const float4*)(kbase + u * HS + c);
        float4 vv4 = *(const float4*)(vbase + u * HS + c);
        Ks[u * 65 + c + 0] = kk4.x; Ks[u * 65 + c + 1] = kk4.y;
        Ks[u * 65 + c + 2] = kk4.z; Ks[u * 65 + c + 3] = kk4.w;
        Vs[u * 65 + c + 0] = vv4.x; Vs[u * 65 + c + 1] = vv4.y;
        Vs[u * 65 + c + 2] = vv4.z; Vs[u * 65 + c + 3] = vv4.w;
    }
    __syncthreads();
    int b = bh / NH, h = bh - b * NH;
    const float scale = rsqrtf((float)NE);   // reference uses E^-0.5
    const float* qbase = q + (size_t)bh * NT * HS;
    float* obase = o + (size_t)(b * NT) * NE + h * HS;
    int lane = tid & 31, wid = tid >> 5;
    for (int t = 0; t < NT; t++) {
        if (tid < HS) qrow[tid] = qbase[t * HS + tid];
        __syncthreads();
        float s;
        if (tid <= t) {
            s = 0.f;
            const float* kr = Ks + tid * 65;
            #pragma unroll 16
            for (int i = 0; i < HS; i++) s += qrow[i] * kr[i];
            s *= scale;
        } else s = -1e30f;
        // block max
        float m = s;
        #pragma unroll
        for (int off = 16; off; off >>= 1) m = fmaxf(m, __shfl_xor_sync(0xffffffffu, m, off));
        if (lane == 0) red[wid] = m;
        __syncthreads();
        if (tid < 32) {
            float mm = (tid < 8) ? red[tid] : -1e30f;
            #pragma unroll
            for (int off = 4; off; off >>= 1) mm = fmaxf(mm, __shfl_xor_sync(0xffffffffu, mm, off));
            if (tid == 0) red[8] = mm;
        }
        __syncthreads();
        m = red[8];
        float p = (tid <= t) ? expf(s - m) : 0.f;
        float su = p;
        #pragma unroll
        for (int off = 16; off; off >>= 1) su += __shfl_xor_sync(0xffffffffu, su, off);
        if (lane == 0) red[wid] = su;
        __syncthreads();
        if (tid < 32) {
            float ss = (tid < 8) ? red[tid] : 0.f;
            #pragma unroll
            for (int off = 4; off; off >>= 1) ss += __shfl_xor_sync(0xffffffffu, ss, off);
            if (tid == 0) red[8] = ss;
        }
        __syncthreads();
        arow[tid] = p / red[8];
        __syncthreads();
        // out: o[t][s] = sum_u arow[u] * V[u][s]
        int qtr = tid >> 6, sidx = tid & 63;
        float acc = 0.f;
        const float* vp = Vs + (qtr * 64) * 65 + sidx;
        const float* ap = arow + qtr * 64;
        #pragma unroll 16
        for (int uu = 0; uu < 64; uu++) acc += ap[uu] * vp[uu * 65];
        pb[tid] = acc;
        __syncthreads();
        if (tid < HS)
            obase[(size_t)t * NE + tid] = pb[tid] + pb[64 + tid] + pb[128 + tid] + pb[192 + tid];
        __syncthreads();
    }
}

// ---------------- loss ----------------
__global__ void zero_loss_kernel() { g_loss = 0.0; }

__global__ void loss_kernel(const float* __restrict__ logits, const int* __restrict__ tgt) {
    int row = blockIdx.x * 8 + (threadIdx.x >> 5);
    int lane = threadIdx.x & 31;
    const float* lp = logits + (size_t)row * NV;
    float v0 = lp[lane];
    float v1 = (lane + 32 < NV) ? lp[lane + 32] : -1e30f;
    float v2 = (lane + 64 < NV) ? lp[lane + 64] : -1e30f;
    float m = fmaxf(v0, fmaxf(v1, v2));
    #pragma unroll
    for (int off = 16; off; off >>= 1) m = fmaxf(m, __shfl_xor_sync(0xffffffffu, m, off));
    float su = expf(v0 - m);
    if (lane + 32 < NV) su += expf(v1 - m);
    if (lane + 64 < NV) su += expf(v2 - m);
    #pragma unroll
    for (int off = 16; off; off >>= 1) su += __shfl_xor_sync(0xffffffffu, su, off);
    if (lane == 0) {
        float lt = lp[tgt[row]];
        double nl = -((double)lt - (double)m - (double)logf(su));
        atomicAdd(&g_loss, nl);
    }
}

__global__ void finalize_loss_kernel(float* __restrict__ out) {
    out[0] = (float)(g_loss / (double)MTOT);
}

// ---------------- launch ----------------
extern "C" void kernel_launch(void* const* d_in, const int* in_sizes, int n_in,
                              void* d_out, int out_size) {
    const int*   idx  = (const int*)d_in[0];
    const int*   tgt  = (const int*)d_in[1];
    const float* tok  = (const float*)d_in[2];
    const float* pos  = (const float*)d_in[3];
    const float* Wq   = (const float*)d_in[4];
    const float* Wk   = (const float*)d_in[5];
    const float* Wv   = (const float*)d_in[6];
    const float* Wpr  = (const float*)d_in[7];
    const float* bpr  = (const float*)d_in[8];
    const float* ln1g = (const float*)d_in[9];
    const float* ln1b = (const float*)d_in[10];
    const float* ln2g = (const float*)d_in[11];
    const float* ln2b = (const float*)d_in[12];
    const float* W1   = (const float*)d_in[13];
    const float* b1   = (const float*)d_in[14];
    const float* W2   = (const float*)d_in[15];
    const float* b2   = (const float*)d_in[16];
    const float* lnfg = (const float*)d_in[17];
    const float* lnfb = (const float*)d_in[18];
    const float* Wlm  = (const float*)d_in[19];
    const float* blm  = (const float*)d_in[20];
    float* out = (float*)d_out;

    float *px, *ph, *pq, *pk, *pv, *po, *pm, *plog;
    cudaGetSymbolAddress((void**)&px, g_x);
    cudaGetSymbolAddress((void**)&ph, g_h);
    cudaGetSymbolAddress((void**)&pq, g_q);
    cudaGetSymbolAddress((void**)&pk, g_k);
    cudaGetSymbolAddress((void**)&pv, g_v);
    cudaGetSymbolAddress((void**)&po, g_o);
    cudaGetSymbolAddress((void**)&pm, g_mlp);
    cudaGetSymbolAddress((void**)&plog, g_logits);

    // persistent attribute; set on the (uncaptured) correctness call, redundant later
    cudaFuncSetAttribute(attn_kernel, cudaFuncAttributeMaxDynamicSharedMemorySize, ATTN_SMEM);

    embed_kernel<<<(MTOT * NE + 255) / 256, 256>>>(idx, tok, pos);

    const size_t wqkvStride = (size_t)NH * NE * HS;   // per-layer
    for (int l = 0; l < NL; l++) {
        ln_kernel<<<MTOT, 128>>>(px, ph, ln1g + l * NE, ln1b + l * NE);
        dim3 gq(MTOT / 64, NE / 64, 3);
        gemm_qkv_kernel<<<gq, 256>>>(ph, Wq + l * wqkvStride, Wk + l * wqkvStride,
                                     Wv + l * wqkvStride, pq, pk, pv);
        attn_kernel<<<NB * NH, 256, ATTN_SMEM>>>(pq, pk, pv, po);
        // x = x + o @ Wproj + bproj
        gemm_kernel<false, true, false><<<dim3(MTOT / 64, NE / 64), 256>>>(
            po, Wpr + (size_t)l * NE * NE, bpr + l * NE, px, px, NE, NE);
        ln_kernel<<<MTOT, 128>>>(px, ph, ln2g + l * NE, ln2b + l * NE);
        gemm_kernel<true, false, false><<<dim3(MTOT / 64, FF / 64), 256>>>(
            ph, W1 + (size_t)l * NE * FF, b1 + l * FF, nullptr, pm, FF, NE);
        gemm_kernel<false, true, false><<<dim3(MTOT / 64, NE / 64), 256>>>(
            pm, W2 + (size_t)l * FF * NE, b2 + l * NE, px, px, NE, FF);
    }
    ln_kernel<<<MTOT, 128>>>(px, ph, lnfg, lnfb);

    const int NLOG = MTOT * NV;
    float* logits = (out_size >= NLOG) ? out : plog;
    gemm_kernel<false, false, true><<<dim3(MTOT / 64, (NV + 63) / 64), 256>>>(
        ph, Wlm, blm, nullptr, logits, NV, NE);

    zero_loss_kernel<<<1, 1>>>();
    loss_kernel<<<MTOT / 8, 256>>>(logits, tgt);
    if (out_size > NLOG)       finalize_loss_kernel<<<1, 1>>>(out + NLOG);
    else if (out_size >= 1 && out_size < NLOG) finalize_loss_kernel<<<1, 1>>>(out);
}

// round 3
// speedup vs baseline: 1.4588x; 1.4588x over previous
#include <cuda_runtime.h>
#include <cuda_bf16.h>
#include <cstdint>
#include <math.h>

#define NL 6
#define NH 6
#define NE 384
#define HS 64
#define NT 256
#define NB 64
#define NV 65
#define MTOT (NB*NT)      /* 16384 rows */
#define FF (4*NE)         /* 1536 */
#define NQKV (3*NE)       /* 1152 */
#define LNEPS 1e-5f

// ================= scratch =================
__device__ __align__(256) float g_x[MTOT*NE];
__device__ __align__(256) float g_hf[MTOT*NE];
__device__ __align__(256) float g_q[MTOT*NE];
__device__ __align__(256) float g_k[MTOT*NE];
__device__ __align__(256) float g_v[MTOT*NE];
__device__ __align__(256) __nv_bfloat16 g_hh[MTOT*NE];
__device__ __align__(256) __nv_bfloat16 g_hl[MTOT*NE];
__device__ __align__(256) __nv_bfloat16 g_oh[MTOT*NE];
__device__ __align__(256) __nv_bfloat16 g_ol[MTOT*NE];
__device__ __align__(256) __nv_bfloat16 g_mh[MTOT*FF];
__device__ __align__(256) __nv_bfloat16 g_ml[MTOT*FF];
__device__ __align__(256) float g_logits[MTOT*NV];
__device__ double g_loss;
__device__ __align__(256) __nv_bfloat16 g_wqkv_h[NL*NQKV*NE];
__device__ __align__(256) __nv_bfloat16 g_wqkv_l[NL*NQKV*NE];
__device__ __align__(256) __nv_bfloat16 g_wpr_h[NL*NE*NE];
__device__ __align__(256) __nv_bfloat16 g_wpr_l[NL*NE*NE];
__device__ __align__(256) __nv_bfloat16 g_w1_h[NL*FF*NE];
__device__ __align__(256) __nv_bfloat16 g_w1_l[NL*FF*NE];
__device__ __align__(256) __nv_bfloat16 g_w2_h[NL*NE*FF];
__device__ __align__(256) __nv_bfloat16 g_w2_l[NL*NE*FF];

__device__ __forceinline__ void split_bf16(float v, __nv_bfloat16& hi, __nv_bfloat16& lo) {
    hi = __float2bfloat16(v);
    lo = __float2bfloat16(v - __bfloat162float(hi));
}

// ================= PTX helpers (base ISA only: sm_80+) =================
__device__ __forceinline__ uint32_t smem_u32(const void* p) {
    uint32_t a;
    asm("{ .reg .u64 t; cvta.to.shared.u64 t, %1; cvt.u32.u64 %0, t; }" : "=r"(a) : "l"(p));
    return a;
}
__device__ __forceinline__ void cp16(uint32_t dst, const void* src) {
    asm volatile("cp.async.cg.shared.global [%0], [%1], 16;" :: "r"(dst), "l"(src));
}
#define CP_COMMIT() asm volatile("cp.async.commit_group;" ::: "memory")
#define CP_WAIT1()  asm volatile("cp.async.wait_group 1;" ::: "memory")
__device__ __forceinline__ void ldm_x4(uint32_t& r0, uint32_t& r1, uint32_t& r2, uint32_t& r3, uint32_t addr) {
    asm volatile("ldmatrix.sync.aligned.m8n8.x4.shared.b16 {%0,%1,%2,%3}, [%4];"
        : "=r"(r0), "=r"(r1), "=r"(r2), "=r"(r3) : "r"(addr));
}
__device__ __forceinline__ void mma_bf16(float* c, uint32_t a0, uint32_t a1, uint32_t a2, uint32_t a3,
                                         uint32_t b0, uint32_t b1) {
    asm volatile("mma.sync.aligned.m16n8k16.row.col.f32.bf16.bf16.f32 "
        "{%0,%1,%2,%3}, {%4,%5,%6,%7}, {%8,%9}, {%0,%1,%2,%3};"
        : "+f"(c[0]), "+f"(c[1]), "+f"(c[2]), "+f"(c[3])
        : "r"(a0), "r"(a1), "r"(a2), "r"(a3), "r"(b0), "r"(b1));
}

// ================= weight prep =================
__global__ void prep_qkv_kernel(const float* __restrict__ Wq, const float* __restrict__ Wk,
                                const float* __restrict__ Wv,
                                __nv_bfloat16* __restrict__ Th, __nv_bfloat16* __restrict__ Tl) {
    int i = blockIdx.x * 256 + threadIdx.x;
    if (i >= NL * NQKV * NE) return;
    int e = i % NE; int n = (i / NE) % NQKV; int l = i / (NE * NQKV);
    int which = n / NE, rem = n % NE, h = rem >> 6, s = rem & 63;
    const float* W = (which == 0) ? Wq : (which == 1) ? Wk : Wv;
    float v = W[(((size_t)l * NH + h) * NE + e) * HS + s];
    split_bf16(v, Th[i], Tl[i]);
}
__global__ void prep_t_kernel(const float* __restrict__ W, __nv_bfloat16* __restrict__ Th,
                              __nv_bfloat16* __restrict__ Tl, int Kd, int Nd) {
    int i = blockIdx.x * 256 + threadIdx.x;
    if (i >= NL * Kd * Nd) return;
    int k = i % Kd; int n = (i / Kd) % Nd; int l = i / (Kd * Nd);
    float v = W[((size_t)l * Kd + k) * Nd + n];
    split_bf16(v, Th[i], Tl[i]);
}

// ================= embedding =================
__global__ void embed_kernel(const int* __restrict__ idx, const float* __restrict__ tok,
                             const float* __restrict__ pos) {
    int i = blockIdx.x * blockDim.x + threadIdx.x;
    if (i >= MTOT * NE) return;
    int r = i / NE, e = i - r * NE;
    int t = r & (NT - 1);
    g_x[i] = tok[idx[r] * NE + e] + pos[t * NE + e];
}

// ================= layernorm =================
template<bool BF16OUT>
__global__ void ln_kernel(const float* __restrict__ in, float* __restrict__ outf,
                          __nv_bfloat16* __restrict__ oh, __nv_bfloat16* __restrict__ ol,
                          const float* __restrict__ gw, const float* __restrict__ bw) {
    int r = blockIdx.x;
    const float* row = in + (size_t)r * NE;
    int tid = threadIdx.x;
    float v0 = row[tid], v1 = row[tid + 128], v2 = row[tid + 256];
    float s = v0 + v1 + v2;
    float sq = v0 * v0 + v1 * v1 + v2 * v2;
    __shared__ float sm[8];
    #pragma unroll
    for (int o = 16; o; o >>= 1) {
        s  += __shfl_xor_sync(0xffffffffu, s, o);
        sq += __shfl_xor_sync(0xffffffffu, sq, o);
    }
    if ((tid & 31) == 0) { sm[tid >> 5] = s; sm[4 + (tid >> 5)] = sq; }
    __syncthreads();
    s  = sm[0] + sm[1] + sm[2] + sm[3];
    sq = sm[4] + sm[5] + sm[6] + sm[7];
    float mean = s * (1.0f / NE);
    float var  = sq * (1.0f / NE) - mean * mean;
    float inv  = rsqrtf(var + LNEPS);
    #pragma unroll
    for (int u = 0; u < 3; u++) {
        int c = tid + u * 128;
        float vv = (u == 0) ? v0 : (u == 1) ? v1 : v2;
        float y = (vv - mean) * inv * gw[c] + bw[c];
        if (BF16OUT) split_bf16(y, oh[(size_t)r * NE + c], ol[(size_t)r * NE + c]);
        else outf[(size_t)r * NE + c] = y;
    }
}

// ================= HMMA GEMM: C[M,N] = A[M,K] @ Bt[N,K]^T, hi/lo 3-term ========
// TYPE 0: QKV scatter fp32 [b,h,t,s]; TYPE 1: res+acc+bias fp32; TYPE 2: relu->hi/lo
#define TM 128
#define TN 128
#define BK 32
#define HM_THREADS 512
#define PITCH 40                       /* halves per smem row (80B) */
#define TILE_H (128*PITCH)             /* halves per tile */
#define TILE_B (TILE_H*2)              /* 10240 bytes */
#define STAGE_B (4*TILE_B)             /* Ah Al Bh Bl = 40960 */
#define HM_SMEM (2*STAGE_B)            /* 81920 */

template<int TYPE>
__global__ void __launch_bounds__(HM_THREADS, 1)
gemm_hmma(const __nv_bfloat16* __restrict__ Ah, const __nv_bfloat16* __restrict__ Al,
          const __nv_bfloat16* __restrict__ Bh, const __nv_bfloat16* __restrict__ Bl,
          const float* __restrict__ bias, const float* __restrict__ res,
          float* __restrict__ out0, float* __restrict__ out1, float* __restrict__ out2,
          __nv_bfloat16* __restrict__ obh, __nv_bfloat16* __restrict__ obl,
          int K) {
    extern __shared__ __align__(128) char smem[];
    const uint32_t sbase = smem_u32(smem);
    const int tid = threadIdx.x;
    const int lane = tid & 31, wid = tid >> 5;
    const int warp_m = wid >> 2, warp_n = wid & 3;   // 4x4 warps of 32x32
    const int m0 = blockIdx.x * TM, n0 = blockIdx.y * TN;

    const int lrow = tid >> 2, lc = tid & 3;         // loader: row 0..127, 16B chunk 0..3
    const uint32_t ldst = (uint32_t)(lrow * 80 + lc * 16);
    const __nv_bfloat16* srcA_h = Ah + (size_t)(m0 + lrow) * K + lc * 8;
    const __nv_bfloat16* srcA_l = Al + (size_t)(m0 + lrow) * K + lc * 8;
    const __nv_bfloat16* srcB_h = Bh + (size_t)(n0 + lrow) * K + lc * 8;
    const __nv_bfloat16* srcB_l = Bl + (size_t)(n0 + lrow) * K + lc * 8;

    const int nc = K / BK;
    // prologue: stages 0,1
    #pragma unroll
    for (int st = 0; st < 2; st++) {
        uint32_t b = sbase + st * STAGE_B + ldst;
        int k0 = st * BK;
        cp16(b + 0 * TILE_B, srcA_h + k0);
        cp16(b + 1 * TILE_B, srcA_l + k0);
        cp16(b + 2 * TILE_B, srcB_h + k0);
        cp16(b + 3 * TILE_B, srcB_l + k0);
        CP_COMMIT();
    }

    float acc[2][4][4];
    #pragma unroll
    for (int i = 0; i < 2; i++)
        #pragma unroll
        for (int j = 0; j < 4; j++)
            #pragma unroll
            for (int q = 0; q < 4; q++) acc[i][j][q] = 0.f;

    // frag smem addresses (lane-dependent)
    const int a_row = warp_m * 32 + (lane & 15);
    const int a_colsel = (lane >> 4) * 8;
    const int b_row = warp_n * 32 + (lane & 7) + ((lane >> 4) << 3);
    const int b_colsel = ((lane >> 3) & 1) * 8;

    for (int c = 0; c < nc; c++) {
        CP_WAIT1();
        __syncthreads();
        uint32_t stage = sbase + (c & 1) * STAGE_B;
        #pragma unroll
        for (int k16 = 0; k16 < BK; k16 += 16) {
            uint32_t ah[2][4], al[2][4], bh[2][4], bl[2][4];
            #pragma unroll
            for (int mf2 = 0; mf2 < 2; mf2++) {
                uint32_t addr = stage + ((a_row + mf2 * 16) * PITCH + k16 + a_colsel) * 2;
                ldm_x4(ah[mf2][0], ah[mf2][1], ah[mf2][2], ah[mf2][3], addr + 0 * TILE_B);
                ldm_x4(al[mf2][0], al[mf2][1], al[mf2][2], al[mf2][3], addr + 1 * TILE_B);
            }
            #pragma unroll
            for (int np = 0; np < 2; np++) {
                uint32_t addr = stage + ((b_row + np * 16) * PITCH + k16 + b_colsel) * 2;
                ldm_x4(bh[np][0], bh[np][1], bh[np][2], bh[np][3], addr + 2 * TILE_B);
                ldm_x4(bl[np][0], bl[np][1], bl[np][2], bl[np][3], addr + 3 * TILE_B);
            }
            #pragma unroll
            for (int mf = 0; mf < 2; mf++)
                #pragma unroll
                for (int np = 0; np < 2; np++)
                    #pragma unroll
                    for (int sub = 0; sub < 2; sub++) {
                        float* cp = acc[mf][np * 2 + sub];
                        mma_bf16(cp, ah[mf][0], ah[mf][1], ah[mf][2], ah[mf][3],
                                 bh[np][sub * 2], bh[np][sub * 2 + 1]);
                        mma_bf16(cp, ah[mf][0], ah[mf][1], ah[mf][2], ah[mf][3],
                                 bl[np][sub * 2], bl[np][sub * 2 + 1]);
                        mma_bf16(cp, al[mf][0], al[mf][1], al[mf][2], al[mf][3],
                                 bh[np][sub * 2], bh[np][sub * 2 + 1]);
                    }
        }
        __syncthreads();
        if (c + 2 < nc) {
            uint32_t b = sbase + (c & 1) * STAGE_B + ldst;
            int k0 = (c + 2) * BK;
            cp16(b + 0 * TILE_B, srcA_h + k0);
            cp16(b + 1 * TILE_B, srcA_l + k0);
            cp16(b + 2 * TILE_B, srcB_h + k0);
            cp16(b + 3 * TILE_B, srcB_l + k0);
        }
        CP_COMMIT();
    }

    // epilogue
    #pragma unroll
    for (int mf = 0; mf < 2; mf++) {
        #pragma unroll
        for (int nf = 0; nf < 4; nf++) {
            #pragma unroll
            for (int i = 0; i < 4; i++) {
                int r = m0 + warp_m * 32 + mf * 16 + (lane >> 2) + ((i >> 1) << 3);
                int n = n0 + warp_n * 32 + nf * 8 + ((lane & 3) << 1) + (i & 1);
                float v = acc[mf][nf][i];
                if (TYPE == 0) {
                    int b = r >> 8, t = r & (NT - 1);
                    int which = n / NE, rem = n - which * NE;
                    int h = rem >> 6, s = rem & 63;
                    float* dst = (which == 0) ? out0 : (which == 1) ? out1 : out2;
                    dst[(((size_t)(b * NH + h)) * NT + t) * HS + s] = v;
                } else if (TYPE == 1) {
                    size_t o = (size_t)r * NE + n;
                    out0[o] = res[o] + v + bias[n];
                } else {
                    float y = fmaxf(v + bias[n], 0.f);
                    size_t o = (size_t)r * FF + n;
                    split_bf16(y, obh[o], obl[o]);
                }
            }
        }
    }
}

// ================= fp32 SIMT gemm for LM head (N=65) =================
__global__ void gemm_lm_kernel(const float* __restrict__ A, const float* __restrict__ Bm,
                               const float* __restrict__ bias, float* __restrict__ C,
                               int N, int K) {
    __shared__ float As[16][64];
    __shared__ float Bs[16][68];
    int tid = threadIdx.x;
    int tx = tid & 15, ty = tid >> 4;
    int rowBase = blockIdx.x * 64, colBase = blockIdx.y * 64;
    float acc[4][4] = {};
    int la_m = tid >> 2, la_k = (tid & 3) * 4;
    int lb_k = tid >> 4, lb_n = (tid & 15) * 4;
    for (int k0 = 0; k0 < K; k0 += 16) {
        float4 a4 = *(const float4*)(A + (size_t)(rowBase + la_m) * K + k0 + la_k);
        As[la_k + 0][la_m] = a4.x; As[la_k + 1][la_m] = a4.y;
        As[la_k + 2][la_m] = a4.z; As[la_k + 3][la_m] = a4.w;
        #pragma unroll
        for (int u = 0; u < 4; u++) {
            int n = colBase + lb_n + u;
            Bs[lb_k][lb_n + u] = (n < N) ? Bm[(size_t)(k0 + lb_k) * N + n] : 0.f;
        }
        __syncthreads();
        #pragma unroll
        for (int kk = 0; kk < 16; kk++) {
            float4 a = *(float4*)&As[kk][ty * 4];
            float4 b = *(float4*)&Bs[kk][tx * 4];
            float av[4] = {a.x, a.y, a.z, a.w};
            float bv[4] = {b.x, b.y, b.z, b.w};
            #pragma unroll
            for (int i = 0; i < 4; i++)
                #pragma unroll
                for (int j = 0; j < 4; j++)
                    acc[i][j] += av[i] * bv[j];
        }
        __syncthreads();
    }
    #pragma unroll
    for (int i = 0; i < 4; i++) {
        int r = rowBase + ty * 4 + i;
        #pragma unroll
        for (int j = 0; j < 4; j++) {
            int c = colBase + tx * 4 + j;
            if (c >= N) continue;
            C[(size_t)r * N + c] = acc[i][j] + bias[c];
        }
    }
}

// ================= attention =================
#define ATTN_SMEM ((2 * NT * 65 + 64 + 256 + 256 + 9) * (int)sizeof(float))
__global__ void attn_kernel(const float* __restrict__ q, const float* __restrict__ k,
                            const float* __restrict__ v,
                            __nv_bfloat16* __restrict__ o_hi, __nv_bfloat16* __restrict__ o_lo) {
    extern __shared__ float sm[];
    float* Ks   = sm;
    float* Vs   = Ks + NT * 65;
    float* qrow = Vs + NT * 65;
    float* arow = qrow + 64;
    float* pb   = arow + NT;
    float* red  = pb + NT;
    int bh = blockIdx.x;
    int tid = threadIdx.x;
    const float* kbase = k + (size_t)bh * NT * HS;
    const float* vbase = v + (size_t)bh * NT * HS;
    for (int i = tid; i < NT * HS / 4; i += 256) {
        int u = i >> 4, c = (i & 15) << 2;
        float4 kk4 = *(const float4*)(kbase + u * HS + c);
        float4 vv4 = *(const float4*)(vbase + u * HS + c);
        Ks[u * 65 + c + 0] = kk4.x; Ks[u * 65 + c + 1] = kk4.y;
        Ks[u * 65 + c + 2] = kk4.z; Ks[u * 65 + c + 3] = kk4.w;
        Vs[u * 65 + c + 0] = vv4.x; Vs[u * 65 + c + 1] = vv4.y;
        Vs[u * 65 + c + 2] = vv4.z; Vs[u * 65 + c + 3] = vv4.w;
    }
    __syncthreads();
    int b = bh / NH, h = bh - b * NH;
    const float scale = rsqrtf((float)NE);
    const float* qbase = q + (size_t)bh * NT * HS;
    int lane = tid & 31, wid = tid >> 5;
    for (int t = 0; t < NT; t++) {
        if (tid < HS) qrow[tid] = qbase[t * HS + tid];
        __syncthreads();
        float s;
        if (tid <= t) {
            s = 0.f;
            const float* kr = Ks + tid * 65;
            #pragma unroll 16
            for (int i = 0; i < HS; i++) s += qrow[i] * kr[i];
            s *= scale;
        } else s = -1e30f;
        float m = s;
        #pragma unroll
        for (int off = 16; off; off >>= 1) m = fmaxf(m, __shfl_xor_sync(0xffffffffu, m, off));
        if (lane == 0) red[wid] = m;
        __syncthreads();
        if (tid < 32) {
            float mm = (tid < 8) ? red[tid] : -1e30f;
            #pragma unroll
            for (int off = 4; off; off >>= 1) mm = fmaxf(mm, __shfl_xor_sync(0xffffffffu, mm, off));
            if (tid == 0) red[8] = mm;
        }
        __syncthreads();
        m = red[8];
        float p = (tid <= t) ? expf(s - m) : 0.f;
        float su = p;
        #pragma unroll
        for (int off = 16; off; off >>= 1) su += __shfl_xor_sync(0xffffffffu, su, off);
        if (lane == 0) red[wid] = su;
        __syncthreads();
        if (tid < 32) {
            float ss = (tid < 8) ? red[tid] : 0.f;
            #pragma unroll
            for (int off = 4; off; off >>= 1) ss += __shfl_xor_sync(0xffffffffu, ss, off);
            if (tid == 0) red[8] = ss;
        }
        __syncthreads();
        arow[tid] = p / red[8];
        __syncthreads();
        int qtr = tid >> 6, sidx = tid & 63;
        float acc = 0.f;
        const float* vp = Vs + (qtr * 64) * 65 + sidx;
        const float* ap = arow + qtr * 64;
        #pragma unroll 16
        for (int uu = 0; uu < 64; uu++) acc += ap[uu] * vp[uu * 65];
        pb[tid] = acc;
        __syncthreads();
        if (tid < HS) {
            float val = pb[tid] + pb[64 + tid] + pb[128 + tid] + pb[192 + tid];
            size_t oidx = (size_t)(b * NT + t) * NE + h * HS + tid;
            split_bf16(val, o_hi[oidx], o_lo[oidx]);
        }
        __syncthreads();
    }
}

// ================= loss =================
__global__ void zero_loss_kernel() { g_loss = 0.0; }

__global__ void loss_kernel(const float* __restrict__ logits, const int* __restrict__ tgt) {
    int row = blockIdx.x * 8 + (threadIdx.x >> 5);
    int lane = threadIdx.x & 31;
    const float* lp = logits + (size_t)row * NV;
    float v0 = lp[lane];
    float v1 = (lane + 32 < NV) ? lp[lane + 32] : -1e30f;
    float v2 = (lane + 64 < NV) ? lp[lane + 64] : -1e30f;
    float m = fmaxf(v0, fmaxf(v1, v2));
    #pragma unroll
    for (int off = 16; off; off >>= 1) m = fmaxf(m, __shfl_xor_sync(0xffffffffu, m, off));
    float su = expf(v0 - m);
    if (lane + 32 < NV) su += expf(v1 - m);
    if (lane + 64 < NV) su += expf(v2 - m);
    #pragma unroll
    for (int off = 16; off; off >>= 1) su += __shfl_xor_sync(0xffffffffu, su, off);
    if (lane == 0) {
        float lt = lp[tgt[row]];
        double nl = -((double)lt - (double)m - (double)logf(su));
        atomicAdd(&g_loss, nl);
    }
}

__global__ void finalize_loss_kernel(float* __restrict__ out) {
    out[0] = (float)(g_loss / (double)MTOT);
}

// ================= launch =================
extern "C" void kernel_launch(void* const* d_in, const int* in_sizes, int n_in,
                              void* d_out, int out_size) {
    const int*   idx  = (const int*)d_in[0];
    const int*   tgt  = (const int*)d_in[1];
    const float* tok  = (const float*)d_in[2];
    const float* pos  = (const float*)d_in[3];
    const float* Wq   = (const float*)d_in[4];
    const float* Wk   = (const float*)d_in[5];
    const float* Wv   = (const float*)d_in[6];
    const float* Wpr  = (const float*)d_in[7];
    const float* bpr  = (const float*)d_in[8];
    const float* ln1g = (const float*)d_in[9];
    const float* ln1b = (const float*)d_in[10];
    const float* ln2g = (const float*)d_in[11];
    const float* ln2b = (const float*)d_in[12];
    const float* W1   = (const float*)d_in[13];
    const float* b1   = (const float*)d_in[14];
    const float* W2   = (const float*)d_in[15];
    const float* b2   = (const float*)d_in[16];
    const float* lnfg = (const float*)d_in[17];
    const float* lnfb = (const float*)d_in[18];
    const float* Wlm  = (const float*)d_in[19];
    const float* blm  = (const float*)d_in[20];
    float* out = (float*)d_out;

    float *px, *phf, *pq, *pk, *pv, *plog;
    __nv_bfloat16 *phh, *phl, *poh, *pol, *pmh, *pml;
    __nv_bfloat16 *wqh, *wql, *wph, *wpl, *w1h, *w1l, *w2h, *w2l;
    cudaGetSymbolAddress((void**)&px, g_x);
    cudaGetSymbolAddress((void**)&phf, g_hf);
    cudaGetSymbolAddress((void**)&pq, g_q);
    cudaGetSymbolAddress((void**)&pk, g_k);
    cudaGetSymbolAddress((void**)&pv, g_v);
    cudaGetSymbolAddress((void**)&plog, g_logits);
    cudaGetSymbolAddress((void**)&phh, g_hh);
    cudaGetSymbolAddress((void**)&phl, g_hl);
    cudaGetSymbolAddress((void**)&poh, g_oh);
    cudaGetSymbolAddress((void**)&pol, g_ol);
    cudaGetSymbolAddress((void**)&pmh, g_mh);
    cudaGetSymbolAddress((void**)&pml, g_ml);
    cudaGetSymbolAddress((void**)&wqh, g_wqkv_h);
    cudaGetSymbolAddress((void**)&wql, g_wqkv_l);
    cudaGetSymbolAddress((void**)&wph, g_wpr_h);
    cudaGetSymbolAddress((void**)&wpl, g_wpr_l);
    cudaGetSymbolAddress((void**)&w1h, g_w1_h);
    cudaGetSymbolAddress((void**)&w1l, g_w1_l);
    cudaGetSymbolAddress((void**)&w2h, g_w2_h);
    cudaGetSymbolAddress((void**)&w2l, g_w2_l);

    cudaFuncSetAttribute(attn_kernel, cudaFuncAttributeMaxDynamicSharedMemorySize, ATTN_SMEM);
    cudaFuncSetAttribute(gemm_hmma<0>, cudaFuncAttributeMaxDynamicSharedMemorySize, HM_SMEM);
    cudaFuncSetAttribute(gemm_hmma<1>, cudaFuncAttributeMaxDynamicSharedMemorySize, HM_SMEM);
    cudaFuncSetAttribute(gemm_hmma<2>, cudaFuncAttributeMaxDynamicSharedMemorySize, HM_SMEM);

    // weight prep (hi/lo bf16, transposed to [N,K])
    prep_qkv_kernel<<<(NL * NQKV * NE + 255) / 256, 256>>>(Wq, Wk, Wv, wqh, wql);
    prep_t_kernel<<<(NL * NE * NE + 255) / 256, 256>>>(Wpr, wph, wpl, NE, NE);
    prep_t_kernel<<<(NL * NE * FF + 255) / 256, 256>>>(W1, w1h, w1l, NE, FF);
    prep_t_kernel<<<(NL * FF * NE + 255) / 256, 256>>>(W2, w2h, w2l, FF, NE);

    embed_kernel<<<(MTOT * NE + 255) / 256, 256>>>(idx, tok, pos);

    for (int l = 0; l < NL; l++) {
        ln_kernel<true><<<MTOT, 128>>>(px, nullptr, phh, phl, ln1g + l * NE, ln1b + l * NE);
        gemm_hmma<0><<<dim3(MTOT / TM, NQKV / TN), HM_THREADS, HM_SMEM>>>(
            phh, phl, wqh + (size_t)l * NQKV * NE, wql + (size_t)l * NQKV * NE,
            nullptr, nullptr, pq, pk, pv, nullptr, nullptr, NE);
        attn_kernel<<<NB * NH, 256, ATTN_SMEM>>>(pq, pk, pv, poh, pol);
        gemm_hmma<1><<<dim3(MTOT / TM, NE / TN), HM_THREADS, HM_SMEM>>>(
            poh, pol, wph + (size_t)l * NE * NE, wpl + (size_t)l * NE * NE,
            bpr + l * NE, px, px, nullptr, nullptr, nullptr, nullptr, NE);
        ln_kernel<true><<<MTOT, 128>>>(px, nullptr, phh, phl, ln2g + l * NE, ln2b + l * NE);
        gemm_hmma<2><<<dim3(MTOT / TM, FF / TN), HM_THREADS, HM_SMEM>>>(
            phh, phl, w1h + (size_t)l * FF * NE, w1l + (size_t)l * FF * NE,
            b1 + l * FF, nullptr, nullptr, nullptr, nullptr, pmh, pml, NE);
        gemm_hmma<1><<<dim3(MTOT / TM, NE / TN), HM_THREADS, HM_SMEM>>>(
            pmh, pml, w2h + (size_t)l * NE * FF, w2l + (size_t)l * NE * FF,
            b2 + l * NE, px, px, nullptr, nullptr, nullptr, nullptr, FF);
    }
    ln_kernel<false><<<MTOT, 128>>>(px, phf, nullptr, nullptr, lnfg, lnfb);

    const int NLOG = MTOT * NV;
    float* logits = (out_size >= NLOG) ? out : plog;
    gemm_lm_kernel<<<dim3(MTOT / 64, (NV + 63) / 64), 256>>>(phf, Wlm, blm, logits, NV, NE);

    zero_loss_kernel<<<1, 1>>>();
    loss_kernel<<<MTOT / 8, 256>>>(logits, tgt);
    if (out_size > NLOG)       finalize_loss_kernel<<<1, 1>>>(out + NLOG);
    else if (out_size >= 1 && out_size < NLOG) finalize_loss_kernel<<<1, 1>>>(out);
}

// round 4
// speedup vs baseline: 2.4102x; 1.6522x over previous
#include <cuda_runtime.h>
#include <cuda_bf16.h>
#include <cstdint>
#include <math.h>

#define NL 6
#define NH 6
#define NE 384
#define HS 64
#define NT 256
#define NB 64
#define NV 65
#define MTOT (NB*NT)      /* 16384 rows */
#define FF (4*NE)         /* 1536 */
#define NQKV (3*NE)       /* 1152 */
#define LNEPS 1e-5f

// ================= scratch =================
__device__ __align__(256) float g_x[MTOT*NE];
__device__ __align__(256) float g_hf[MTOT*NE];
__device__ __align__(256) __nv_bfloat16 g_hh[MTOT*NE];
__device__ __align__(256) __nv_bfloat16 g_hl[MTOT*NE];
__device__ __align__(256) __nv_bfloat16 g_qkvh[3*MTOT*NE];
__device__ __align__(256) __nv_bfloat16 g_qkvl[3*MTOT*NE];
__device__ __align__(256) __nv_bfloat16 g_oh[MTOT*NE];
__device__ __align__(256) __nv_bfloat16 g_ol[MTOT*NE];
__device__ __align__(256) __nv_bfloat16 g_mh[MTOT*FF];
__device__ __align__(256) __nv_bfloat16 g_ml[MTOT*FF];
__device__ __align__(256) float g_logits[MTOT*NV];
__device__ double g_loss;
__device__ __align__(256) __nv_bfloat16 g_wqkv_h[NL*NQKV*NE];
__device__ __align__(256) __nv_bfloat16 g_wqkv_l[NL*NQKV*NE];
__device__ __align__(256) __nv_bfloat16 g_wpr_h[NL*NE*NE];
__device__ __align__(256) __nv_bfloat16 g_wpr_l[NL*NE*NE];
__device__ __align__(256) __nv_bfloat16 g_w1_h[NL*FF*NE];
__device__ __align__(256) __nv_bfloat16 g_w1_l[NL*FF*NE];
__device__ __align__(256) __nv_bfloat16 g_w2_h[NL*NE*FF];
__device__ __align__(256) __nv_bfloat16 g_w2_l[NL*NE*FF];

__device__ __forceinline__ void split_bf16(float v, __nv_bfloat16& hi, __nv_bfloat16& lo) {
    hi = __float2bfloat16(v);
    lo = __float2bfloat16(v - __bfloat162float(hi));
}

// ================= PTX helpers (base ISA: sm_80+) =================
__device__ __forceinline__ uint32_t smem_u32(const void* p) {
    uint32_t a;
    asm("{ .reg .u64 t; cvta.to.shared.u64 t, %1; cvt.u32.u64 %0, t; }" : "=r"(a) : "l"(p));
    return a;
}
__device__ __forceinline__ void cp16(uint32_t dst, const void* src) {
    asm volatile("cp.async.cg.shared.global [%0], [%1], 16;" :: "r"(dst), "l"(src));
}
#define CP_COMMIT() asm volatile("cp.async.commit_group;" ::: "memory")
#define CP_WAIT1()  asm volatile("cp.async.wait_group 1;" ::: "memory")
#define CP_WAIT0()  asm volatile("cp.async.wait_group 0;" ::: "memory")
__device__ __forceinline__ void ldm_x4(uint32_t& r0, uint32_t& r1, uint32_t& r2, uint32_t& r3, uint32_t addr) {
    asm volatile("ldmatrix.sync.aligned.m8n8.x4.shared.b16 {%0,%1,%2,%3}, [%4];"
        : "=r"(r0), "=r"(r1), "=r"(r2), "=r"(r3) : "r"(addr));
}
__device__ __forceinline__ void ldm_x4_t(uint32_t& r0, uint32_t& r1, uint32_t& r2, uint32_t& r3, uint32_t addr) {
    asm volatile("ldmatrix.sync.aligned.m8n8.x4.trans.shared.b16 {%0,%1,%2,%3}, [%4];"
        : "=r"(r0), "=r"(r1), "=r"(r2), "=r"(r3) : "r"(addr));
}
__device__ __forceinline__ void mma_bf16(float* c, uint32_t a0, uint32_t a1, uint32_t a2, uint32_t a3,
                                         uint32_t b0, uint32_t b1) {
    asm volatile("mma.sync.aligned.m16n8k16.row.col.f32.bf16.bf16.f32 "
        "{%0,%1,%2,%3}, {%4,%5,%6,%7}, {%8,%9}, {%0,%1,%2,%3};"
        : "+f"(c[0]), "+f"(c[1]), "+f"(c[2]), "+f"(c[3])
        : "r"(a0), "r"(a1), "r"(a2), "r"(a3), "r"(b0), "r"(b1));
}
__device__ __forceinline__ void packsplit(float x, float y, uint32_t& hi, uint32_t& lo) {
    __nv_bfloat16 hx = __float2bfloat16(x), hy = __float2bfloat16(y);
    __nv_bfloat162 h2; h2.x = hx; h2.y = hy;
    hi = *reinterpret_cast<uint32_t*>(&h2);
    __nv_bfloat162 l2;
    l2.x = __float2bfloat16(x - __bfloat162float(hx));
    l2.y = __float2bfloat16(y - __bfloat162float(hy));
    lo = *reinterpret_cast<uint32_t*>(&l2);
}

// ================= weight prep =================
__global__ void prep_qkv_kernel(const float* __restrict__ Wq, const float* __restrict__ Wk,
                                const float* __restrict__ Wv,
                                __nv_bfloat16* __restrict__ Th, __nv_bfloat16* __restrict__ Tl) {
    int i = blockIdx.x * 256 + threadIdx.x;
    if (i >= NL * NQKV * NE) return;
    int e = i % NE; int n = (i / NE) % NQKV; int l = i / (NE * NQKV);
    int which = n / NE, rem = n % NE, h = rem >> 6, s = rem & 63;
    const float* W = (which == 0) ? Wq : (which == 1) ? Wk : Wv;
    float v = W[(((size_t)l * NH + h) * NE + e) * HS + s];
    split_bf16(v, Th[i], Tl[i]);
}
__global__ void prep_t_kernel(const float* __restrict__ W, __nv_bfloat16* __restrict__ Th,
                              __nv_bfloat16* __restrict__ Tl, int Kd, int Nd) {
    int i = blockIdx.x * 256 + threadIdx.x;
    if (i >= NL * Kd * Nd) return;
    int k = i % Kd; int n = (i / Kd) % Nd; int l = i / (Kd * Nd);
    float v = W[((size_t)l * Kd + k) * Nd + n];
    split_bf16(v, Th[i], Tl[i]);
}

// ================= embedding =================
__global__ void embed_kernel(const int* __restrict__ idx, const float* __restrict__ tok,
                             const float* __restrict__ pos) {
    int i = blockIdx.x * blockDim.x + threadIdx.x;
    if (i >= MTOT * NE) return;
    int r = i / NE, e = i - r * NE;
    int t = r & (NT - 1);
    g_x[i] = tok[idx[r] * NE + e] + pos[t * NE + e];
}

// ================= layernorm =================
template<bool BF16OUT>
__global__ void ln_kernel(const float* __restrict__ in, float* __restrict__ outf,
                          __nv_bfloat16* __restrict__ oh, __nv_bfloat16* __restrict__ ol,
                          const float* __restrict__ gw, const float* __restrict__ bw) {
    int r = blockIdx.x;
    const float* row = in + (size_t)r * NE;
    int tid = threadIdx.x;
    float v0 = row[tid], v1 = row[tid + 128], v2 = row[tid + 256];
    float s = v0 + v1 + v2;
    float sq = v0 * v0 + v1 * v1 + v2 * v2;
    __shared__ float sm[8];
    #pragma unroll
    for (int o = 16; o; o >>= 1) {
        s  += __shfl_xor_sync(0xffffffffu, s, o);
        sq += __shfl_xor_sync(0xffffffffu, sq, o);
    }
    if ((tid & 31) == 0) { sm[tid >> 5] = s; sm[4 + (tid >> 5)] = sq; }
    __syncthreads();
    s  = sm[0] + sm[1] + sm[2] + sm[3];
    sq = sm[4] + sm[5] + sm[6] + sm[7];
    float mean = s * (1.0f / NE);
    float var  = sq * (1.0f / NE) - mean * mean;
    float inv  = rsqrtf(var + LNEPS);
    #pragma unroll
    for (int u = 0; u < 3; u++) {
        int c = tid + u * 128;
        float vv = (u == 0) ? v0 : (u == 1) ? v1 : v2;
        float y = (vv - mean) * inv * gw[c] + bw[c];
        if (BF16OUT) split_bf16(y, oh[(size_t)r * NE + c], ol[(size_t)r * NE + c]);
        else outf[(size_t)r * NE + c] = y;
    }
}

// ================= HMMA GEMM: C[M,N] = A[M,K] @ Bt[N,K]^T, hi/lo 3-term ========
// TYPE 0: QKV -> hi/lo bf16 scatter into g_qkv[3][b,h,t,s]
// TYPE 1: res+acc+bias fp32; TYPE 2: relu->hi/lo bf16
#define TM 128
#define TN 128
#define BK 32
#define HM_THREADS 512
#define PITCH 40
#define TILE_H (128*PITCH)
#define TILE_B (TILE_H*2)
#define STAGE_B (4*TILE_B)
#define HM_SMEM (2*STAGE_B)

template<int TYPE>
__global__ void __launch_bounds__(HM_THREADS, 1)
gemm_hmma(const __nv_bfloat16* __restrict__ Ah, const __nv_bfloat16* __restrict__ Al,
          const __nv_bfloat16* __restrict__ Bh, const __nv_bfloat16* __restrict__ Bl,
          const float* __restrict__ bias, const float* __restrict__ res,
          float* __restrict__ out0,
          __nv_bfloat16* __restrict__ obh, __nv_bfloat16* __restrict__ obl,
          int K) {
    extern __shared__ __align__(128) char smem[];
    const uint32_t sbase = smem_u32(smem);
    const int tid = threadIdx.x;
    const int lane = tid & 31, wid = tid >> 5;
    const int warp_m = wid >> 2, warp_n = wid & 3;
    const int m0 = blockIdx.x * TM, n0 = blockIdx.y * TN;

    const int lrow = tid >> 2, lc = tid & 3;
    const uint32_t ldst = (uint32_t)(lrow * 80 + lc * 16);
    const __nv_bfloat16* srcA_h = Ah + (size_t)(m0 + lrow) * K + lc * 8;
    const __nv_bfloat16* srcA_l = Al + (size_t)(m0 + lrow) * K + lc * 8;
    const __nv_bfloat16* srcB_h = Bh + (size_t)(n0 + lrow) * K + lc * 8;
    const __nv_bfloat16* srcB_l = Bl + (size_t)(n0 + lrow) * K + lc * 8;

    const int nc = K / BK;
    #pragma unroll
    for (int st = 0; st < 2; st++) {
        uint32_t b = sbase + st * STAGE_B + ldst;
        int k0 = st * BK;
        cp16(b + 0 * TILE_B, srcA_h + k0);
        cp16(b + 1 * TILE_B, srcA_l + k0);
        cp16(b + 2 * TILE_B, srcB_h + k0);
        cp16(b + 3 * TILE_B, srcB_l + k0);
        CP_COMMIT();
    }

    float acc[2][4][4];
    #pragma unroll
    for (int i = 0; i < 2; i++)
        #pragma unroll
        for (int j = 0; j < 4; j++)
            #pragma unroll
            for (int q = 0; q < 4; q++) acc[i][j][q] = 0.f;

    const int a_row = warp_m * 32 + (lane & 15);
    const int a_colsel = (lane >> 4) * 8;
    const int b_row = warp_n * 32 + (lane & 7) + ((lane >> 4) << 3);
    const int b_colsel = ((lane >> 3) & 1) * 8;

    for (int c = 0; c < nc; c++) {
        CP_WAIT1();
        __syncthreads();
        uint32_t stage = sbase + (c & 1) * STAGE_B;
        #pragma unroll
        for (int k16 = 0; k16 < BK; k16 += 16) {
            uint32_t ah[2][4], al[2][4], bh[2][4], bl[2][4];
            #pragma unroll
            for (int mf2 = 0; mf2 < 2; mf2++) {
                uint32_t addr = stage + ((a_row + mf2 * 16) * PITCH + k16 + a_colsel) * 2;
                ldm_x4(ah[mf2][0], ah[mf2][1], ah[mf2][2], ah[mf2][3], addr + 0 * TILE_B);
                ldm_x4(al[mf2][0], al[mf2][1], al[mf2][2], al[mf2][3], addr + 1 * TILE_B);
            }
            #pragma unroll
            for (int np = 0; np < 2; np++) {
                uint32_t addr = stage + ((b_row + np * 16) * PITCH + k16 + b_colsel) * 2;
                ldm_x4(bh[np][0], bh[np][1], bh[np][2], bh[np][3], addr + 2 * TILE_B);
                ldm_x4(bl[np][0], bl[np][1], bl[np][2], bl[np][3], addr + 3 * TILE_B);
            }
            #pragma unroll
            for (int mf = 0; mf < 2; mf++)
                #pragma unroll
                for (int np = 0; np < 2; np++)
                    #pragma unroll
                    for (int sub = 0; sub < 2; sub++) {
                        float* cp = acc[mf][np * 2 + sub];
                        mma_bf16(cp, ah[mf][0], ah[mf][1], ah[mf][2], ah[mf][3],
                                 bh[np][sub * 2], bh[np][sub * 2 + 1]);
                        mma_bf16(cp, ah[mf][0], ah[mf][1], ah[mf][2], ah[mf][3],
                                 bl[np][sub * 2], bl[np][sub * 2 + 1]);
                        mma_bf16(cp, al[mf][0], al[mf][1], al[mf][2], al[mf][3],
                                 bh[np][sub * 2], bh[np][sub * 2 + 1]);
                    }
        }
        __syncthreads();
        if (c + 2 < nc) {
            uint32_t b = sbase + (c & 1) * STAGE_B + ldst;
            int k0 = (c + 2) * BK;
            cp16(b + 0 * TILE_B, srcA_h + k0);
            cp16(b + 1 * TILE_B, srcA_l + k0);
            cp16(b + 2 * TILE_B, srcB_h + k0);
            cp16(b + 3 * TILE_B, srcB_l + k0);
        }
        CP_COMMIT();
    }

    #pragma unroll
    for (int mf = 0; mf < 2; mf++) {
        #pragma unroll
        for (int nf = 0; nf < 4; nf++) {
            #pragma unroll
            for (int i = 0; i < 4; i++) {
                int r = m0 + warp_m * 32 + mf * 16 + (lane >> 2) + ((i >> 1) << 3);
                int n = n0 + warp_n * 32 + nf * 8 + ((lane & 3) << 1) + (i & 1);
                float v = acc[mf][nf][i];
                if (TYPE == 0) {
                    int bb = r >> 8, t = r & (NT - 1);
                    int which = n / NE, rem = n - which * NE;
                    int hh = rem >> 6, s = rem & 63;
                    size_t o = (size_t)which * ((size_t)MTOT * NE) +
                               ((((size_t)bb * NH + hh) * NT + t) * HS + s);
                    split_bf16(v, obh[o], obl[o]);
                } else if (TYPE == 1) {
                    size_t o = (size_t)r * NE + n;
                    out0[o] = res[o] + v + bias[n];
                } else {
                    float y = fmaxf(v + bias[n], 0.f);
                    size_t o = (size_t)r * FF + n;
                    split_bf16(y, obh[o], obl[o]);
                }
            }
        }
    }
}

// ================= flash attention (mma.sync, hi/lo 3-term) =================
#define AQT 128
#define AKT 64
#define APITCH 72
#define ATILE_B (AKT*APITCH*2)      /* 9216 */
#define ASTAGE_B (4*ATILE_B)        /* 36864 */
#define AT_SMEM (2*ASTAGE_B)        /* 73728 */

__device__ __forceinline__ void flash_issue(uint32_t bs, int kt, int tid,
    const __nv_bfloat16* Kh, const __nv_bfloat16* Kl,
    const __nv_bfloat16* Vh, const __nv_bfloat16* Vl) {
    #pragma unroll
    for (int i2 = 0; i2 < 2; i2++) {
        int i = tid + i2 * 256;
        int r = i >> 3, ch = i & 7;
        uint32_t off = (uint32_t)(r * (APITCH * 2) + ch * 16);
        size_t g = (size_t)(kt * AKT + r) * HS + ch * 8;
        cp16(bs + 0 * ATILE_B + off, Kh + g);
        cp16(bs + 1 * ATILE_B + off, Kl + g);
        cp16(bs + 2 * ATILE_B + off, Vh + g);
        cp16(bs + 3 * ATILE_B + off, Vl + g);
    }
}

__global__ void __launch_bounds__(256, 1)
flash_kernel(const __nv_bfloat16* __restrict__ qkvh, const __nv_bfloat16* __restrict__ qkvl,
             __nv_bfloat16* __restrict__ ooh, __nv_bfloat16* __restrict__ ool) {
    extern __shared__ __align__(128) char smem[];
    const uint32_t sbase = smem_u32(smem);
    const int tid = threadIdx.x, lane = tid & 31, wid = tid >> 5;
    const int bh = blockIdx.x, qt = blockIdx.y;
    const int b = bh / NH, h = bh - b * NH;
    const size_t TS = (size_t)MTOT * NE;
    const size_t base_bh = (size_t)bh * NT * HS;
    const __nv_bfloat16* Qh = qkvh + base_bh;
    const __nv_bfloat16* Ql = qkvl + base_bh;
    const __nv_bfloat16* Kh = qkvh + TS + base_bh;
    const __nv_bfloat16* Kl = qkvl + TS + base_bh;
    const __nv_bfloat16* Vh = qkvh + 2 * TS + base_bh;
    const __nv_bfloat16* Vl = qkvl + 2 * TS + base_bh;

    // stage Q through smem then ldmatrix to regs
    for (int i = tid; i < 1024; i += 256) {
        int r = i >> 3, ch = i & 7;
        uint32_t off = (uint32_t)(r * (APITCH * 2) + ch * 16);
        const __nv_bfloat16* s0 = Qh + (size_t)(qt * AQT + r) * HS + ch * 8;
        const __nv_bfloat16* s1 = Ql + (size_t)(qt * AQT + r) * HS + ch * 8;
        cp16(sbase + off, s0);
        cp16(sbase + 2 * ATILE_B + off, s1);
    }
    CP_COMMIT();
    CP_WAIT0();
    __syncthreads();
    uint32_t qfh[4][4], qfl[4][4];
    {
        int a_row = wid * 16 + (lane & 15);
        int a_col = (lane >> 4) * 8;
        #pragma unroll
        for (int ks = 0; ks < 4; ks++) {
            uint32_t ad = sbase + (uint32_t)((a_row * APITCH + ks * 16 + a_col) * 2);
            ldm_x4(qfh[ks][0], qfh[ks][1], qfh[ks][2], qfh[ks][3], ad);
            ldm_x4(qfl[ks][0], qfl[ks][1], qfl[ks][2], qfl[ks][3], ad + 2 * ATILE_B);
        }
    }
    __syncthreads();

    const int nkt = 2 * (qt + 1);
    flash_issue(sbase, 0, tid, Kh, Kl, Vh, Vl);
    CP_COMMIT();

    float of[8][4];
    #pragma unroll
    for (int i = 0; i < 8; i++)
        #pragma unroll
        for (int j = 0; j < 4; j++) of[i][j] = 0.f;
    float m0 = -1e30f, m1 = -1e30f, l0 = 0.f, l1 = 0.f;
    const float scale = rsqrtf((float)NE);
    const int qrow0 = qt * AQT + wid * 16 + (lane >> 2);
    const int warp_qmax = qt * AQT + wid * 16 + 15;

    for (int kt = 0; kt < nkt; kt++) {
        if (kt + 1 < nkt) flash_issue(sbase + ((kt + 1) & 1) * ASTAGE_B, kt + 1, tid, Kh, Kl, Vh, Vl);
        CP_COMMIT();
        CP_WAIT1();
        __syncthreads();
        if (kt * AKT <= warp_qmax) {   // warp has at least one unmasked row
            uint32_t kb = sbase + (kt & 1) * ASTAGE_B;
            float sc[8][4];
            #pragma unroll
            for (int i = 0; i < 8; i++)
                #pragma unroll
                for (int j = 0; j < 4; j++) sc[i][j] = 0.f;
            #pragma unroll
            for (int ks = 0; ks < 4; ks++) {
                uint32_t bfh[4][4], bfl[4][4];
                #pragma unroll
                for (int np = 0; np < 4; np++) {
                    int brow = np * 16 + (lane & 7) + ((lane >> 4) << 3);
                    int bcol = ks * 16 + ((lane >> 3) & 1) * 8;
                    uint32_t ad = kb + (uint32_t)((brow * APITCH + bcol) * 2);
                    ldm_x4(bfh[np][0], bfh[np][1], bfh[np][2], bfh[np][3], ad);
                    ldm_x4(bfl[np][0], bfl[np][1], bfl[np][2], bfl[np][3], ad + ATILE_B);
                }
                #pragma unroll
                for (int np = 0; np < 4; np++)
                    #pragma unroll
                    for (int sub = 0; sub < 2; sub++) {
                        float* cc = sc[np * 2 + sub];
                        mma_bf16(cc, qfh[ks][0], qfh[ks][1], qfh[ks][2], qfh[ks][3],
                                 bfh[np][sub * 2], bfh[np][sub * 2 + 1]);
                        mma_bf16(cc, qfh[ks][0], qfh[ks][1], qfh[ks][2], qfh[ks][3],
                                 bfl[np][sub * 2], bfl[np][sub * 2 + 1]);
                        mma_bf16(cc, qfl[ks][0], qfl[ks][1], qfl[ks][2], qfl[ks][3],
                                 bfh[np][sub * 2], bfh[np][sub * 2 + 1]);
                    }
            }
            // scale + causal mask
            #pragma unroll
            for (int nf = 0; nf < 8; nf++)
                #pragma unroll
                for (int j = 0; j < 4; j++) {
                    int kcol = kt * AKT + nf * 8 + ((lane & 3) << 1) + (j & 1);
                    int qr = (j < 2) ? qrow0 : (qrow0 + 8);
                    sc[nf][j] = (kcol <= qr) ? sc[nf][j] * scale : -1e30f;
                }
            // online softmax
            float ml0 = -1e30f, ml1 = -1e30f;
            #pragma unroll
            for (int nf = 0; nf < 8; nf++) {
                ml0 = fmaxf(ml0, fmaxf(sc[nf][0], sc[nf][1]));
                ml1 = fmaxf(ml1, fmaxf(sc[nf][2], sc[nf][3]));
            }
            ml0 = fmaxf(ml0, __shfl_xor_sync(0xffffffffu, ml0, 1));
            ml0 = fmaxf(ml0, __shfl_xor_sync(0xffffffffu, ml0, 2));
            ml1 = fmaxf(ml1, __shfl_xor_sync(0xffffffffu, ml1, 1));
            ml1 = fmaxf(ml1, __shfl_xor_sync(0xffffffffu, ml1, 2));
            float mn0 = fmaxf(m0, ml0), mn1 = fmaxf(m1, ml1);
            float a0 = __expf(m0 - mn0), a1 = __expf(m1 - mn1);
            float rs0 = 0.f, rs1 = 0.f;
            #pragma unroll
            for (int nf = 0; nf < 8; nf++) {
                sc[nf][0] = __expf(sc[nf][0] - mn0); rs0 += sc[nf][0];
                sc[nf][1] = __expf(sc[nf][1] - mn0); rs0 += sc[nf][1];
                sc[nf][2] = __expf(sc[nf][2] - mn1); rs1 += sc[nf][2];
                sc[nf][3] = __expf(sc[nf][3] - mn1); rs1 += sc[nf][3];
            }
            rs0 += __shfl_xor_sync(0xffffffffu, rs0, 1);
            rs0 += __shfl_xor_sync(0xffffffffu, rs0, 2);
            rs1 += __shfl_xor_sync(0xffffffffu, rs1, 1);
            rs1 += __shfl_xor_sync(0xffffffffu, rs1, 2);
            #pragma unroll
            for (int nf = 0; nf < 8; nf++) {
                of[nf][0] *= a0; of[nf][1] *= a0;
                of[nf][2] *= a1; of[nf][3] *= a1;
            }
            l0 = l0 * a0 + rs0; l1 = l1 * a1 + rs1;
            m0 = mn0; m1 = mn1;
            // P @ V
            #pragma unroll
            for (int ks = 0; ks < 4; ks++) {
                uint32_t ph[4], pl[4];
                packsplit(sc[2 * ks][0], sc[2 * ks][1], ph[0], pl[0]);
                packsplit(sc[2 * ks][2], sc[2 * ks][3], ph[1], pl[1]);
                packsplit(sc[2 * ks + 1][0], sc[2 * ks + 1][1], ph[2], pl[2]);
                packsplit(sc[2 * ks + 1][2], sc[2 * ks + 1][3], ph[3], pl[3]);
                uint32_t vfh[4][4], vfl[4][4];
                #pragma unroll
                for (int nd = 0; nd < 4; nd++) {
                    int vrow = ks * 16 + (lane & 7) + (((lane >> 3) & 1) << 3);
                    int vcol = nd * 16 + ((lane >> 4) << 3);
                    uint32_t ad = kb + (uint32_t)((vrow * APITCH + vcol) * 2);
                    ldm_x4_t(vfh[nd][0], vfh[nd][1], vfh[nd][2], vfh[nd][3], ad + 2 * ATILE_B);
                    ldm_x4_t(vfl[nd][0], vfl[nd][1], vfl[nd][2], vfl[nd][3], ad + 3 * ATILE_B);
                }
                #pragma unroll
                for (int nd = 0; nd < 4; nd++)
                    #pragma unroll
                    for (int sub = 0; sub < 2; sub++) {
                        float* cc = of[nd * 2 + sub];
                        mma_bf16(cc, ph[0], ph[1], ph[2], ph[3],
                                 vfh[nd][sub * 2], vfh[nd][sub * 2 + 1]);
                        mma_bf16(cc, ph[0], ph[1], ph[2], ph[3],
                                 vfl[nd][sub * 2], vfl[nd][sub * 2 + 1]);
                        mma_bf16(cc, pl[0], pl[1], pl[2], pl[3],
                                 vfh[nd][sub * 2], vfh[nd][sub * 2 + 1]);
                    }
            }
        }
        __syncthreads();
    }

    // normalize + write hi/lo to [b,t,E] concat layout
    float inv0 = 1.f / l0, inv1 = 1.f / l1;
    size_t row0 = ((size_t)b * NT + qrow0) * NE + h * HS;
    size_t row1 = row0 + (size_t)8 * NE;
    #pragma unroll
    for (int nf = 0; nf < 8; nf++) {
        int d = nf * 8 + ((lane & 3) << 1);
        uint32_t hi, lo;
        packsplit(of[nf][0] * inv0, of[nf][1] * inv0, hi, lo);
        *reinterpret_cast<uint32_t*>(&ooh[row0 + d]) = hi;
        *reinterpret_cast<uint32_t*>(&ool[row0 + d]) = lo;
        packsplit(of[nf][2] * inv1, of[nf][3] * inv1, hi, lo);
        *reinterpret_cast<uint32_t*>(&ooh[row1 + d]) = hi;
        *reinterpret_cast<uint32_t*>(&ool[row1 + d]) = lo;
    }
}

// ================= fp32 SIMT gemm for LM head (N=65) =================
__global__ void gemm_lm_kernel(const float* __restrict__ A, const float* __restrict__ Bm,
                               const float* __restrict__ bias, float* __restrict__ C,
                               int N, int K) {
    __shared__ float As[16][64];
    __shared__ float Bs[16][68];
    int tid = threadIdx.x;
    int tx = tid & 15, ty = tid >> 4;
    int rowBase = blockIdx.x * 64, colBase = blockIdx.y * 64;
    float acc[4][4] = {};
    int la_m = tid >> 2, la_k = (tid & 3) * 4;
    int lb_k = tid >> 4, lb_n = (tid & 15) * 4;
    for (int k0 = 0; k0 < K; k0 += 16) {
        float4 a4 = *(const float4*)(A + (size_t)(rowBase + la_m) * K + k0 + la_k);
        As[la_k + 0][la_m] = a4.x; As[la_k + 1][la_m] = a4.y;
        As[la_k + 2][la_m] = a4.z; As[la_k + 3][la_m] = a4.w;
        #pragma unroll
        for (int u = 0; u < 4; u++) {
            int n = colBase + lb_n + u;
            Bs[lb_k][lb_n + u] = (n < N) ? Bm[(size_t)(k0 + lb_k) * N + n] : 0.f;
        }
        __syncthreads();
        #pragma unroll
        for (int kk = 0; kk < 16; kk++) {
            float4 a = *(float4*)&As[kk][ty * 4];
            float4 b = *(float4*)&Bs[kk][tx * 4];
            float av[4] = {a.x, a.y, a.z, a.w};
            float bv[4] = {b.x, b.y, b.z, b.w};
            #pragma unroll
            for (int i = 0; i < 4; i++)
                #pragma unroll
                for (int j = 0; j < 4; j++)
                    acc[i][j] += av[i] * bv[j];
        }
        __syncthreads();
    }
    #pragma unroll
    for (int i = 0; i < 4; i++) {
        int r = rowBase + ty * 4 + i;
        #pragma unroll
        for (int j = 0; j < 4; j++) {
            int c = colBase + tx * 4 + j;
            if (c >= N) continue;
            C[(size_t)r * N + c] = acc[i][j] + bias[c];
        }
    }
}

// ================= loss =================
__global__ void zero_loss_kernel() { g_loss = 0.0; }

__global__ void loss_kernel(const float* __restrict__ logits, const int* __restrict__ tgt) {
    int row = blockIdx.x * 8 + (threadIdx.x >> 5);
    int lane = threadIdx.x & 31;
    const float* lp = logits + (size_t)row * NV;
    float v0 = lp[lane];
    float v1 = (lane + 32 < NV) ? lp[lane + 32] : -1e30f;
    float v2 = (lane + 64 < NV) ? lp[lane + 64] : -1e30f;
    float m = fmaxf(v0, fmaxf(v1, v2));
    #pragma unroll
    for (int off = 16; off; off >>= 1) m = fmaxf(m, __shfl_xor_sync(0xffffffffu, m, off));
    float su = expf(v0 - m);
    if (lane + 32 < NV) su += expf(v1 - m);
    if (lane + 64 < NV) su += expf(v2 - m);
    #pragma unroll
    for (int off = 16; off; off >>= 1) su += __shfl_xor_sync(0xffffffffu, su, off);
    if (lane == 0) {
        float lt = lp[tgt[row]];
        double nl = -((double)lt - (double)m - (double)logf(su));
        atomicAdd(&g_loss, nl);
    }
}

__global__ void finalize_loss_kernel(float* __restrict__ out) {
    out[0] = (float)(g_loss / (double)MTOT);
}

// ================= launch =================
extern "C" void kernel_launch(void* const* d_in, const int* in_sizes, int n_in,
                              void* d_out, int out_size) {
    const int*   idx  = (const int*)d_in[0];
    const int*   tgt  = (const int*)d_in[1];
    const float* tok  = (const float*)d_in[2];
    const float* pos  = (const float*)d_in[3];
    const float* Wq   = (const float*)d_in[4];
    const float* Wk   = (const float*)d_in[5];
    const float* Wv   = (const float*)d_in[6];
    const float* Wpr  = (const float*)d_in[7];
    const float* bpr  = (const float*)d_in[8];
    const float* ln1g = (const float*)d_in[9];
    const float* ln1b = (const float*)d_in[10];
    const float* ln2g = (const float*)d_in[11];
    const float* ln2b = (const float*)d_in[12];
    const float* W1   = (const float*)d_in[13];
    const float* b1   = (const float*)d_in[14];
    const float* W2   = (const float*)d_in[15];
    const float* b2   = (const float*)d_in[16];
    const float* lnfg = (const float*)d_in[17];
    const float* lnfb = (const float*)d_in[18];
    const float* Wlm  = (const float*)d_in[19];
    const float* blm  = (const float*)d_in[20];
    float* out = (float*)d_out;

    float *px, *phf, *plog;
    __nv_bfloat16 *phh, *phl, *pqkvh, *pqkvl, *poh, *pol, *pmh, *pml;
    __nv_bfloat16 *wqh, *wql, *wph, *wpl, *w1h, *w1l, *w2h, *w2l;
    cudaGetSymbolAddress((void**)&px, g_x);
    cudaGetSymbolAddress((void**)&phf, g_hf);
    cudaGetSymbolAddress((void**)&plog, g_logits);
    cudaGetSymbolAddress((void**)&phh, g_hh);
    cudaGetSymbolAddress((void**)&phl, g_hl);
    cudaGetSymbolAddress((void**)&pqkvh, g_qkvh);
    cudaGetSymbolAddress((void**)&pqkvl, g_qkvl);
    cudaGetSymbolAddress((void**)&poh, g_oh);
    cudaGetSymbolAddress((void**)&pol, g_ol);
    cudaGetSymbolAddress((void**)&pmh, g_mh);
    cudaGetSymbolAddress((void**)&pml, g_ml);
    cudaGetSymbolAddress((void**)&wqh, g_wqkv_h);
    cudaGetSymbolAddress((void**)&wql, g_wqkv_l);
    cudaGetSymbolAddress((void**)&wph, g_wpr_h);
    cudaGetSymbolAddress((void**)&wpl, g_wpr_l);
    cudaGetSymbolAddress((void**)&w1h, g_w1_h);
    cudaGetSymbolAddress((void**)&w1l, g_w1_l);
    cudaGetSymbolAddress((void**)&w2h, g_w2_h);
    cudaGetSymbolAddress((void**)&w2l, g_w2_l);

    cudaFuncSetAttribute(flash_kernel, cudaFuncAttributeMaxDynamicSharedMemorySize, AT_SMEM);
    cudaFuncSetAttribute(gemm_hmma<0>, cudaFuncAttributeMaxDynamicSharedMemorySize, HM_SMEM);
    cudaFuncSetAttribute(gemm_hmma<1>, cudaFuncAttributeMaxDynamicSharedMemorySize, HM_SMEM);
    cudaFuncSetAttribute(gemm_hmma<2>, cudaFuncAttributeMaxDynamicSharedMemorySize, HM_SMEM);

    prep_qkv_kernel<<<(NL * NQKV * NE + 255) / 256, 256>>>(Wq, Wk, Wv, wqh, wql);
    prep_t_kernel<<<(NL * NE * NE + 255) / 256, 256>>>(Wpr, wph, wpl, NE, NE);
    prep_t_kernel<<<(NL * NE * FF + 255) / 256, 256>>>(W1, w1h, w1l, NE, FF);
    prep_t_kernel<<<(NL * FF * NE + 255) / 256, 256>>>(W2, w2h, w2l, FF, NE);

    embed_kernel<<<(MTOT * NE + 255) / 256, 256>>>(idx, tok, pos);

    for (int l = 0; l < NL; l++) {
        ln_kernel<true><<<MTOT, 128>>>(px, nullptr, phh, phl, ln1g + l * NE, ln1b + l * NE);
        gemm_hmma<0><<<dim3(MTOT / TM, NQKV / TN), HM_THREADS, HM_SMEM>>>(
            phh, phl, wqh + (size_t)l * NQKV * NE, wql + (size_t)l * NQKV * NE,
            nullptr, nullptr, nullptr, pqkvh, pqkvl, NE);
        flash_kernel<<<dim3(NB * NH, 2), 256, AT_SMEM>>>(pqkvh, pqkvl, poh, pol);
        gemm_hmma<1><<<dim3(MTOT / TM, NE / TN), HM_THREADS, HM_SMEM>>>(
            poh, pol, wph + (size_t)l * NE * NE, wpl + (size_t)l * NE * NE,
            bpr + l * NE, px, px, nullptr, nullptr, NE);
        ln_kernel<true><<<MTOT, 128>>>(px, nullptr, phh, phl, ln2g + l * NE, ln2b + l * NE);
        gemm_hmma<2><<<dim3(MTOT / TM, FF / TN), HM_THREADS, HM_SMEM>>>(
            phh, phl, w1h + (size_t)l * FF * NE, w1l + (size_t)l * FF * NE,
            b1 + l * FF, nullptr, nullptr, pmh, pml, NE);
        gemm_hmma<1><<<dim3(MTOT / TM, NE / TN), HM_THREADS, HM_SMEM>>>(
            pmh, pml, w2h + (size_t)l * NE * FF, w2l + (size_t)l * NE * FF,
            b2 + l * NE, px, px, nullptr, nullptr, FF);
    }
    ln_kernel<false><<<MTOT, 128>>>(px, phf, nullptr, nullptr, lnfg, lnfb);

    const int NLOG = MTOT * NV;
    float* logits = (out_size >= NLOG) ? out : plog;
    gemm_lm_kernel<<<dim3(MTOT / 64, (NV + 63) / 64), 256>>>(phf, Wlm, blm, logits, NV, NE);

    zero_loss_kernel<<<1, 1>>>();
    loss_kernel<<<MTOT / 8, 256>>>(logits, tgt);
    if (out_size > NLOG)       finalize_loss_kernel<<<1, 1>>>(out + NLOG);
    else if (out_size >= 1 && out_size < NLOG) finalize_loss_kernel<<<1, 1>>>(out);
}

// round 6
// speedup vs baseline: 5.3725x; 2.2290x over previous
#include <cuda_runtime.h>
#include <cuda_fp16.h>
#include <cstdint>
#include <math.h>

#define NL 6
#define NH 6
#define NE 384
#define HS 64
#define NT 256
#define NB 64
#define NV 65
#define MTOT (NB*NT)      /* 16384 rows */
#define FF (4*NE)         /* 1536 */
#define NQKV (3*NE)       /* 1152 */
#define LNEPS 1e-5f

// ================= scratch =================
__device__ __align__(256) float g_x[MTOT*NE];
__device__ __align__(256) float g_hf[MTOT*NE];
__device__ __align__(256) __half g_h16[MTOT*NE];
__device__ __align__(256) __half g_qkv16[3*MTOT*NE];
__device__ __align__(256) __half g_o16[MTOT*NE];
__device__ __align__(256) __half g_m16[MTOT*FF];
__device__ __align__(256) float g_logits[MTOT*NV];
__device__ double g_loss;
__device__ __align__(256) __half g_wqkv_h[NL*NQKV*NE];
__device__ __align__(256) __half g_wqkv_l[NL*NQKV*NE];
__device__ __align__(256) __half g_wpr_h[NL*NE*NE];
__device__ __align__(256) __half g_wpr_l[NL*NE*NE];
__device__ __align__(256) __half g_w1_h[NL*FF*NE];
__device__ __align__(256) __half g_w1_l[NL*FF*NE];
__device__ __align__(256) __half g_w2_h[NL*NE*FF];
__device__ __align__(256) __half g_w2_l[NL*NE*FF];

__device__ __forceinline__ void split_fp16(float v, __half& hi, __half& lo) {
    hi = __float2half_rn(v);
    lo = __float2half_rn(v - __half2float(hi));
}

// ================= PTX helpers (base ISA: sm_80+) =================
__device__ __forceinline__ uint32_t smem_u32(const void* p) {
    uint32_t a;
    asm("{ .reg .u64 t; cvta.to.shared.u64 t, %1; cvt.u32.u64 %0, t; }" : "=r"(a) : "l"(p));
    return a;
}
__device__ __forceinline__ void cp16(uint32_t dst, const void* src) {
    asm volatile("cp.async.cg.shared.global [%0], [%1], 16;" :: "r"(dst), "l"(src));
}
#define CP_COMMIT() asm volatile("cp.async.commit_group;" ::: "memory")
#define CP_WAIT1()  asm volatile("cp.async.wait_group 1;" ::: "memory")
#define CP_WAIT0()  asm volatile("cp.async.wait_group 0;" ::: "memory")
__device__ __forceinline__ void ldm_x4(uint32_t& r0, uint32_t& r1, uint32_t& r2, uint32_t& r3, uint32_t addr) {
    asm volatile("ldmatrix.sync.aligned.m8n8.x4.shared.b16 {%0,%1,%2,%3}, [%4];"
        : "=r"(r0), "=r"(r1), "=r"(r2), "=r"(r3) : "r"(addr));
}
__device__ __forceinline__ void ldm_x4_t(uint32_t& r0, uint32_t& r1, uint32_t& r2, uint32_t& r3, uint32_t addr) {
    asm volatile("ldmatrix.sync.aligned.m8n8.x4.trans.shared.b16 {%0,%1,%2,%3}, [%4];"
        : "=r"(r0), "=r"(r1), "=r"(r2), "=r"(r3) : "r"(addr));
}
__device__ __forceinline__ void mma_f16(float* c, uint32_t a0, uint32_t a1, uint32_t a2, uint32_t a3,
                                        uint32_t b0, uint32_t b1) {
    asm volatile("mma.sync.aligned.m16n8k16.row.col.f32.f16.f16.f32 "
        "{%0,%1,%2,%3}, {%4,%5,%6,%7}, {%8,%9}, {%0,%1,%2,%3};"
        : "+f"(c[0]), "+f"(c[1]), "+f"(c[2]), "+f"(c[3])
        : "r"(a0), "r"(a1), "r"(a2), "r"(a3), "r"(b0), "r"(b1));
}
__device__ __forceinline__ uint32_t pack2(float x, float y) {
    __half2 h2 = __floats2half2_rn(x, y);
    return *reinterpret_cast<uint32_t*>(&h2);
}

// ================= weight prep =================
__global__ void prep_qkv_kernel(const float* __restrict__ Wq, const float* __restrict__ Wk,
                                const float* __restrict__ Wv,
                                __half* __restrict__ Th, __half* __restrict__ Tl) {
    int i = blockIdx.x * 256 + threadIdx.x;
    if (i >= NL * NQKV * NE) return;
    int e = i % NE; int n = (i / NE) % NQKV; int l = i / (NE * NQKV);
    int which = n / NE, rem = n % NE, h = rem >> 6, s = rem & 63;
    const float* W = (which == 0) ? Wq : (which == 1) ? Wk : Wv;
    float v = W[(((size_t)l * NH + h) * NE + e) * HS + s];
    split_fp16(v, Th[i], Tl[i]);
}
__global__ void prep_t_kernel(const float* __restrict__ W, __half* __restrict__ Th,
                              __half* __restrict__ Tl, int Kd, int Nd) {
    int i = blockIdx.x * 256 + threadIdx.x;
    if (i >= NL * Kd * Nd) return;
    int k = i % Kd; int n = (i / Kd) % Nd; int l = i / (Kd * Nd);
    float v = W[((size_t)l * Kd + k) * Nd + n];
    split_fp16(v, Th[i], Tl[i]);
}

// ================= embedding =================
__global__ void embed_kernel(const int* __restrict__ idx, const float* __restrict__ tok,
                             const float* __restrict__ pos) {
    int i = blockIdx.x * blockDim.x + threadIdx.x;
    if (i >= MTOT * NE) return;
    int r = i / NE, e = i - r * NE;
    int t = r & (NT - 1);
    g_x[i] = tok[idx[r] * NE + e] + pos[t * NE + e];
}

// ================= layernorm =================
template<bool F16OUT>
__global__ void ln_kernel(const float* __restrict__ in, float* __restrict__ outf,
                          __half* __restrict__ oh,
                          const float* __restrict__ gw, const float* __restrict__ bw) {
    int r = blockIdx.x;
    const float* row = in + (size_t)r * NE;
    int tid = threadIdx.x;
    float v0 = row[tid], v1 = row[tid + 128], v2 = row[tid + 256];
    float s = v0 + v1 + v2;
    float sq = v0 * v0 + v1 * v1 + v2 * v2;
    __shared__ float sm[8];
    #pragma unroll
    for (int o = 16; o; o >>= 1) {
        s  += __shfl_xor_sync(0xffffffffu, s, o);
        sq += __shfl_xor_sync(0xffffffffu, sq, o);
    }
    if ((tid & 31) == 0) { sm[tid >> 5] = s; sm[4 + (tid >> 5)] = sq; }
    __syncthreads();
    s  = sm[0] + sm[1] + sm[2] + sm[3];
    sq = sm[4] + sm[5] + sm[6] + sm[7];
    float mean = s * (1.0f / NE);
    float var  = sq * (1.0f / NE) - mean * mean;
    float inv  = rsqrtf(var + LNEPS);
    #pragma unroll
    for (int u = 0; u < 3; u++) {
        int c = tid + u * 128;
        float vv = (u == 0) ? v0 : (u == 1) ? v1 : v2;
        float y = (vv - mean) * inv * gw[c] + bw[c];
        if (F16OUT) oh[(size_t)r * NE + c] = __float2half_rn(y);
        else outf[(size_t)r * NE + c] = y;
    }
}

// ================= HMMA GEMM: C[M,N] = A[M,K] @ Bt[N,K]^T =================
// A single fp16, B hi/lo fp16 pre-split: C = A*Bh + A*Bl
// TYPE 0: QKV -> fp16 scatter into g_qkv16[3][b,h,t,s]
// TYPE 1: res+acc+bias fp32; TYPE 2: relu -> fp16
#define TM 128
#define TN 128
#define BK 32
#define HM_THREADS 512
#define PITCH 40
#define TILE_H (128*PITCH)
#define TILE_B (TILE_H*2)           /* 10240 */
#define STAGE_B (3*TILE_B)          /* A Bh Bl = 30720 */
#define HM_SMEM (2*STAGE_B)         /* 61440 */

template<int TYPE>
__global__ void __launch_bounds__(HM_THREADS, 1)
gemm_hmma(const __half* __restrict__ A,
          const __half* __restrict__ Bh, const __half* __restrict__ Bl,
          const float* __restrict__ bias, const float* __restrict__ res,
          float* __restrict__ out0, __half* __restrict__ oh,
          int K) {
    extern __shared__ __align__(128) char smem[];
    const uint32_t sbase = smem_u32(smem);
    const int tid = threadIdx.x;
    const int lane = tid & 31, wid = tid >> 5;
    const int warp_m = wid >> 2, warp_n = wid & 3;
    const int m0 = blockIdx.x * TM, n0 = blockIdx.y * TN;

    const int lrow = tid >> 2, lc = tid & 3;
    const uint32_t ldst = (uint32_t)(lrow * 80 + lc * 16);
    const __half* srcA  = A  + (size_t)(m0 + lrow) * K + lc * 8;
    const __half* srcBh = Bh + (size_t)(n0 + lrow) * K + lc * 8;
    const __half* srcBl = Bl + (size_t)(n0 + lrow) * K + lc * 8;

    const int nc = K / BK;
    #pragma unroll
    for (int st = 0; st < 2; st++) {
        uint32_t b = sbase + st * STAGE_B + ldst;
        int k0 = st * BK;
        cp16(b + 0 * TILE_B, srcA + k0);
        cp16(b + 1 * TILE_B, srcBh + k0);
        cp16(b + 2 * TILE_B, srcBl + k0);
        CP_COMMIT();
    }

    float acc[2][4][4];
    #pragma unroll
    for (int i = 0; i < 2; i++)
        #pragma unroll
        for (int j = 0; j < 4; j++)
            #pragma unroll
            for (int q = 0; q < 4; q++) acc[i][j][q] = 0.f;

    const int a_row = warp_m * 32 + (lane & 15);
    const int a_colsel = (lane >> 4) * 8;
    const int b_row = warp_n * 32 + (lane & 7) + ((lane >> 4) << 3);
    const int b_colsel = ((lane >> 3) & 1) * 8;

    for (int c = 0; c < nc; c++) {
        CP_WAIT1();
        __syncthreads();
        uint32_t stage = sbase + (c & 1) * STAGE_B;
        #pragma unroll
        for (int k16 = 0; k16 < BK; k16 += 16) {
            uint32_t af[2][4], bh4[2][4], bl4[2][4];
            #pragma unroll
            for (int mf2 = 0; mf2 < 2; mf2++) {
                uint32_t addr = stage + ((a_row + mf2 * 16) * PITCH + k16 + a_colsel) * 2;
                ldm_x4(af[mf2][0], af[mf2][1], af[mf2][2], af[mf2][3], addr);
            }
            #pragma unroll
            for (int np = 0; np < 2; np++) {
                uint32_t addr = stage + ((b_row + np * 16) * PITCH + k16 + b_colsel) * 2;
                ldm_x4(bh4[np][0], bh4[np][1], bh4[np][2], bh4[np][3], addr + 1 * TILE_B);
                ldm_x4(bl4[np][0], bl4[np][1], bl4[np][2], bl4[np][3], addr + 2 * TILE_B);
            }
            #pragma unroll
            for (int mf = 0; mf < 2; mf++)
                #pragma unroll
                for (int np = 0; np < 2; np++)
                    #pragma unroll
                    for (int sub = 0; sub < 2; sub++) {
                        float* cp = acc[mf][np * 2 + sub];
                        mma_f16(cp, af[mf][0], af[mf][1], af[mf][2], af[mf][3],
                                bh4[np][sub * 2], bh4[np][sub * 2 + 1]);
                        mma_f16(cp, af[mf][0], af[mf][1], af[mf][2], af[mf][3],
                                bl4[np][sub * 2], bl4[np][sub * 2 + 1]);
                    }
        }
        __syncthreads();
        if (c + 2 < nc) {
            uint32_t b = sbase + (c & 1) * STAGE_B + ldst;
            int k0 = (c + 2) * BK;
            cp16(b + 0 * TILE_B, srcA + k0);
            cp16(b + 1 * TILE_B, srcBh + k0);
            cp16(b + 2 * TILE_B, srcBl + k0);
        }
        CP_COMMIT();
    }

    #pragma unroll
    for (int mf = 0; mf < 2; mf++) {
        #pragma unroll
        for (int nf = 0; nf < 4; nf++) {
            #pragma unroll
            for (int i = 0; i < 4; i++) {
                int r = m0 + warp_m * 32 + mf * 16 + (lane >> 2) + ((i >> 1) << 3);
                int n = n0 + warp_n * 32 + nf * 8 + ((lane & 3) << 1) + (i & 1);
                float v = acc[mf][nf][i];
                if (TYPE == 0) {
                    int bb = r >> 8, t = r & (NT - 1);
                    int which = n / NE, rem = n - which * NE;
                    int hh = rem >> 6, s = rem & 63;
                    size_t o = (size_t)which * ((size_t)MTOT * NE) +
                               ((((size_t)bb * NH + hh) * NT + t) * HS + s);
                    oh[o] = __float2half_rn(v);
                } else if (TYPE == 1) {
                    size_t o = (size_t)r * NE + n;
                    out0[o] = res[o] + v + bias[n];
                } else {
                    float y = fmaxf(v + bias[n], 0.f);
                    oh[(size_t)r * FF + n] = __float2half_rn(y);
                }
            }
        }
    }
}

// ================= flash attention (single fp16) =================
#define AQT 128
#define AKT 64
#define APITCH 72
#define ATILE_B (AKT*APITCH*2)      /* 9216 */
#define ASTAGE_B (2*ATILE_B)        /* K,V = 18432 */
#define AQ_OFF (2*ASTAGE_B)         /* 36864 */
#define AT_SMEM (AQ_OFF + 128*APITCH*2)  /* 55296 */

__device__ __forceinline__ void flash_issue(uint32_t bs, int kt, int tid,
    const __half* Kp, const __half* Vp) {
    #pragma unroll
    for (int i2 = 0; i2 < 2; i2++) {
        int i = tid + i2 * 256;
        int r = i >> 3, ch = i & 7;
        uint32_t off = (uint32_t)(r * (APITCH * 2) + ch * 16);
        size_t g = (size_t)(kt * AKT + r) * HS + ch * 8;
        cp16(bs + 0 * ATILE_B + off, Kp + g);
        cp16(bs + 1 * ATILE_B + off, Vp + g);
    }
}

__global__ void __launch_bounds__(256, 1)
flash_kernel(const __half* __restrict__ qkv, __half* __restrict__ oo) {
    extern __shared__ __align__(128) char smem[];
    const uint32_t sbase = smem_u32(smem);
    const int tid = threadIdx.x, lane = tid & 31, wid = tid >> 5;
    const int bh = blockIdx.x, qt = blockIdx.y;
    const int b = bh / NH, h = bh - b * NH;
    const size_t TS = (size_t)MTOT * NE;
    const size_t base_bh = (size_t)bh * NT * HS;
    const __half* Qp = qkv + base_bh;
    const __half* Kp = qkv + TS + base_bh;
    const __half* Vp = qkv + 2 * TS + base_bh;

    // stage Q into its own region, plus first K/V stage
    for (int i = tid; i < 1024; i += 256) {
        int r = i >> 3, ch = i & 7;
        uint32_t off = (uint32_t)(r * (APITCH * 2) + ch * 16);
        cp16(sbase + AQ_OFF + off, Qp + (size_t)(qt * AQT + r) * HS + ch * 8);
    }
    flash_issue(sbase, 0, tid, Kp, Vp);
    CP_COMMIT();
    CP_WAIT0();
    __syncthreads();
    uint32_t qf[4][4];
    {
        int a_row = wid * 16 + (lane & 15);
        int a_col = (lane >> 4) * 8;
        #pragma unroll
        for (int ks = 0; ks < 4; ks++) {
            uint32_t ad = sbase + AQ_OFF + (uint32_t)((a_row * APITCH + ks * 16 + a_col) * 2);
            ldm_x4(qf[ks][0], qf[ks][1], qf[ks][2], qf[ks][3], ad);
        }
    }

    const int nkt = 2 * (qt + 1);
    float of[8][4];
    #pragma unroll
    for (int i = 0; i < 8; i++)
        #pragma unroll
        for (int j = 0; j < 4; j++) of[i][j] = 0.f;
    float m0 = -1e30f, m1 = -1e30f, l0 = 0.f, l1 = 0.f;
    const float scale = rsqrtf((float)NE);
    const int qrow0 = qt * AQT + wid * 16 + (lane >> 2);
    const int warp_qmax = qt * AQT + wid * 16 + 15;

    for (int kt = 0; kt < nkt; kt++) {
        if (kt + 1 < nkt) flash_issue(sbase + ((kt + 1) & 1) * ASTAGE_B, kt + 1, tid, Kp, Vp);
        CP_COMMIT();
        CP_WAIT1();
        __syncthreads();
        if (kt * AKT <= warp_qmax) {
            uint32_t kb = sbase + (kt & 1) * ASTAGE_B;
            float sc[8][4];
            #pragma unroll
            for (int i = 0; i < 8; i++)
                #pragma unroll
                for (int j = 0; j < 4; j++) sc[i][j] = 0.f;
            #pragma unroll
            for (int ks = 0; ks < 4; ks++) {
                uint32_t bf[4][4];
                #pragma unroll
                for (int np = 0; np < 4; np++) {
                    int brow = np * 16 + (lane & 7) + ((lane >> 4) << 3);
                    int bcol = ks * 16 + ((lane >> 3) & 1) * 8;
                    uint32_t ad = kb + (uint32_t)((brow * APITCH + bcol) * 2);
                    ldm_x4(bf[np][0], bf[np][1], bf[np][2], bf[np][3], ad);
                }
                #pragma unroll
                for (int np = 0; np < 4; np++)
                    #pragma unroll
                    for (int sub = 0; sub < 2; sub++)
                        mma_f16(sc[np * 2 + sub], qf[ks][0], qf[ks][1], qf[ks][2], qf[ks][3],
                                bf[np][sub * 2], bf[np][sub * 2 + 1]);
            }
            // scale + causal mask
            #pragma unroll
            for (int nf = 0; nf < 8; nf++)
                #pragma unroll
                for (int j = 0; j < 4; j++) {
                    int kcol = kt * AKT + nf * 8 + ((lane & 3) << 1) + (j & 1);
                    int qr = (j < 2) ? qrow0 : (qrow0 + 8);
                    sc[nf][j] = (kcol <= qr) ? sc[nf][j] * scale : -1e30f;
                }
            // online softmax
            float ml0 = -1e30f, ml1 = -1e30f;
            #pragma unroll
            for (int nf = 0; nf < 8; nf++) {
                ml0 = fmaxf(ml0, fmaxf(sc[nf][0], sc[nf][1]));
                ml1 = fmaxf(ml1, fmaxf(sc[nf][2], sc[nf][3]));
            }
            ml0 = fmaxf(ml0, __shfl_xor_sync(0xffffffffu, ml0, 1));
            ml0 = fmaxf(ml0, __shfl_xor_sync(0xffffffffu, ml0, 2));
            ml1 = fmaxf(ml1, __shfl_xor_sync(0xffffffffu, ml1, 1));
            ml1 = fmaxf(ml1, __shfl_xor_sync(0xffffffffu, ml1, 2));
            float mn0 = fmaxf(m0, ml0), mn1 = fmaxf(m1, ml1);
            float a0 = __expf(m0 - mn0), a1 = __expf(m1 - mn1);
            float rs0 = 0.f, rs1 = 0.f;
            #pragma unroll
            for (int nf = 0; nf < 8; nf++) {
                sc[nf][0] = __expf(sc[nf][0] - mn0); rs0 += sc[nf][0];
                sc[nf][1] = __expf(sc[nf][1] - mn0); rs0 += sc[nf][1];
                sc[nf][2] = __expf(sc[nf][2] - mn1); rs1 += sc[nf][2];
                sc[nf][3] = __expf(sc[nf][3] - mn1); rs1 += sc[nf][3];
            }
            rs0 += __shfl_xor_sync(0xffffffffu, rs0, 1);
            rs0 += __shfl_xor_sync(0xffffffffu, rs0, 2);
            rs1 += __shfl_xor_sync(0xffffffffu, rs1, 1);
            rs1 += __shfl_xor_sync(0xffffffffu, rs1, 2);
            #pragma unroll
            for (int nf = 0; nf < 8; nf++) {
                of[nf][0] *= a0; of[nf][1] *= a0;
                of[nf][2] *= a1; of[nf][3] *= a1;
            }
            l0 = l0 * a0 + rs0; l1 = l1 * a1 + rs1;
            m0 = mn0; m1 = mn1;
            // P @ V
            #pragma unroll
            for (int ks = 0; ks < 4; ks++) {
                uint32_t pf[4];
                pf[0] = pack2(sc[2 * ks][0], sc[2 * ks][1]);
                pf[1] = pack2(sc[2 * ks][2], sc[2 * ks][3]);
                pf[2] = pack2(sc[2 * ks + 1][0], sc[2 * ks + 1][1]);
                pf[3] = pack2(sc[2 * ks + 1][2], sc[2 * ks + 1][3]);
                uint32_t vf[4][4];
                #pragma unroll
                for (int nd = 0; nd < 4; nd++) {
                    int vrow = ks * 16 + (lane & 7) + (((lane >> 3) & 1) << 3);
                    int vcol = nd * 16 + ((lane >> 4) << 3);
                    uint32_t ad = kb + (uint32_t)((vrow * APITCH + vcol) * 2);
                    ldm_x4_t(vf[nd][0], vf[nd][1], vf[nd][2], vf[nd][3], ad + ATILE_B);
                }
                #pragma unroll
                for (int nd = 0; nd < 4; nd++)
                    #pragma unroll
                    for (int sub = 0; sub < 2; sub++)
                        mma_f16(of[nd * 2 + sub], pf[0], pf[1], pf[2], pf[3],
                                vf[nd][sub * 2], vf[nd][sub * 2 + 1]);
            }
        }
        __syncthreads();
    }

    float inv0 = 1.f / l0, inv1 = 1.f / l1;
    size_t row0 = ((size_t)b * NT + qrow0) * NE + h * HS;
    size_t row1 = row0 + (size_t)8 * NE;
    #pragma unroll
    for (int nf = 0; nf < 8; nf++) {
        int d = nf * 8 + ((lane & 3) << 1);
        *reinterpret_cast<uint32_t*>(&oo[row0 + d]) = pack2(of[nf][0] * inv0, of[nf][1] * inv0);
        *reinterpret_cast<uint32_t*>(&oo[row1 + d]) = pack2(of[nf][2] * inv1, of[nf][3] * inv1);
    }
}

// ================= fp32 SIMT gemm for LM head (N=65) =================
__global__ void gemm_lm_kernel(const float* __restrict__ A, const float* __restrict__ Bm,
                               const float* __restrict__ bias, float* __restrict__ C,
                               int N, int K) {
    __shared__ float As[16][64];
    __shared__ float Bs[16][68];
    int tid = threadIdx.x;
    int tx = tid & 15, ty = tid >> 4;
    int rowBase = blockIdx.x * 64, colBase = blockIdx.y * 64;
    float acc[4][4] = {};
    int la_m = tid >> 2, la_k = (tid & 3) * 4;
    int lb_k = tid >> 4, lb_n = (tid & 15) * 4;
    for (int k0 = 0; k0 < K; k0 += 16) {
        float4 a4 = *(const float4*)(A + (size_t)(rowBase + la_m) * K + k0 + la_k);
        As[la_k + 0][la_m] = a4.x; As[la_k + 1][la_m] = a4.y;
        As[la_k + 2][la_m] = a4.z; As[la_k + 3][la_m] = a4.w;
        #pragma unroll
        for (int u = 0; u < 4; u++) {
            int n = colBase + lb_n + u;
            Bs[lb_k][lb_n + u] = (n < N) ? Bm[(size_t)(k0 + lb_k) * N + n] : 0.f;
        }
        __syncthreads();
        #pragma unroll
        for (int kk = 0; kk < 16; kk++) {
            float4 a = *(float4*)&As[kk][ty * 4];
            float4 b = *(float4*)&Bs[kk][tx * 4];
            float av[4] = {a.x, a.y, a.z, a.w};
            float bv[4] = {b.x, b.y, b.z, b.w};
            #pragma unroll
            for (int i = 0; i < 4; i++)
                #pragma unroll
                for (int j = 0; j < 4; j++)
                    acc[i][j] += av[i] * bv[j];
        }
        __syncthreads();
    }
    #pragma unroll
    for (int i = 0; i < 4; i++) {
        int r = rowBase + ty * 4 + i;
        #pragma unroll
        for (int j = 0; j < 4; j++) {
            int c = colBase + tx * 4 + j;
            if (c >= N) continue;
            C[(size_t)r * N + c] = acc[i][j] + bias[c];
        }
    }
}

// ================= loss =================
__global__ void zero_loss_kernel() { g_loss = 0.0; }

__global__ void loss_kernel(const float* __restrict__ logits, const int* __restrict__ tgt) {
    int row = blockIdx.x * 8 + (threadIdx.x >> 5);
    int lane = threadIdx.x & 31;
    const float* lp = logits + (size_t)row * NV;
    float v0 = lp[lane];
    float v1 = (lane + 32 < NV) ? lp[lane + 32] : -1e30f;
    float v2 = (lane + 64 < NV) ? lp[lane + 64] : -1e30f;
    float m = fmaxf(v0, fmaxf(v1, v2));
    #pragma unroll
    for (int off = 16; off; off >>= 1) m = fmaxf(m, __shfl_xor_sync(0xffffffffu, m, off));
    float su = expf(v0 - m);
    if (lane + 32 < NV) su += expf(v1 - m);
    if (lane + 64 < NV) su += expf(v2 - m);
    #pragma unroll
    for (int off = 16; off; off >>= 1) su += __shfl_xor_sync(0xffffffffu, su, off);
    if (lane == 0) {
        float lt = lp[tgt[row]];
        double nl = -((double)lt - (double)m - (double)logf(su));
        atomicAdd(&g_loss, nl);
    }
}

__global__ void finalize_loss_kernel(float* __restrict__ out) {
    out[0] = (float)(g_loss / (double)MTOT);
}

// ================= launch =================
extern "C" void kernel_launch(void* const* d_in, const int* in_sizes, int n_in,
                              void* d_out, int out_size) {
    const int*   idx  = (const int*)d_in[0];
    const int*   tgt  = (const int*)d_in[1];
    const float* tok  = (const float*)d_in[2];
    const float* pos  = (const float*)d_in[3];
    const float* Wq   = (const float*)d_in[4];
    const float* Wk   = (const float*)d_in[5];
    const float* Wv   = (const float*)d_in[6];
    const float* Wpr  = (const float*)d_in[7];
    const float* bpr  = (const float*)d_in[8];
    const float* ln1g = (const float*)d_in[9];
    const float* ln1b = (const float*)d_in[10];
    const float* ln2g = (const float*)d_in[11];
    const float* ln2b = (const float*)d_in[12];
    const float* W1   = (const float*)d_in[13];
    const float* b1   = (const float*)d_in[14];
    const float* W2   = (const float*)d_in[15];
    const float* b2   = (const float*)d_in[16];
    const float* lnfg = (const float*)d_in[17];
    const float* lnfb = (const float*)d_in[18];
    const float* Wlm  = (const float*)d_in[19];
    const float* blm  = (const float*)d_in[20];
    float* out = (float*)d_out;

    float *px, *phf, *plog;
    __half *ph16, *pqkv, *po16, *pm16;
    __half *wqh, *wql, *wph, *wpl, *w1h, *w1l, *w2h, *w2l;
    cudaGetSymbolAddress((void**)&px, g_x);
    cudaGetSymbolAddress((void**)&phf, g_hf);
    cudaGetSymbolAddress((void**)&plog, g_logits);
    cudaGetSymbolAddress((void**)&ph16, g_h16);
    cudaGetSymbolAddress((void**)&pqkv, g_qkv16);
    cudaGetSymbolAddress((void**)&po16, g_o16);
    cudaGetSymbolAddress((void**)&pm16, g_m16);
    cudaGetSymbolAddress((void**)&wqh, g_wqkv_h);
    cudaGetSymbolAddress((void**)&wql, g_wqkv_l);
    cudaGetSymbolAddress((void**)&wph, g_wpr_h);
    cudaGetSymbolAddress((void**)&wpl, g_wpr_l);
    cudaGetSymbolAddress((void**)&w1h, g_w1_h);
    cudaGetSymbolAddress((void**)&w1l, g_w1_l);
    cudaGetSymbolAddress((void**)&w2h, g_w2_h);
    cudaGetSymbolAddress((void**)&w2l, g_w2_l);

    cudaFuncSetAttribute(flash_kernel, cudaFuncAttributeMaxDynamicSharedMemorySize, AT_SMEM);
    cudaFuncSetAttribute(gemm_hmma<0>, cudaFuncAttributeMaxDynamicSharedMemorySize, HM_SMEM);
    cudaFuncSetAttribute(gemm_hmma<1>, cudaFuncAttributeMaxDynamicSharedMemorySize, HM_SMEM);
    cudaFuncSetAttribute(gemm_hmma<2>, cudaFuncAttributeMaxDynamicSharedMemorySize, HM_SMEM);

    prep_qkv_kernel<<<(NL * NQKV * NE + 255) / 256, 256>>>(Wq, Wk, Wv, wqh, wql);
    prep_t_kernel<<<(NL * NE * NE + 255) / 256, 256>>>(Wpr, wph, wpl, NE, NE);
    prep_t_kernel<<<(NL * NE * FF + 255) / 256, 256>>>(W1, w1h, w1l, NE, FF);
    prep_t_kernel<<<(NL * FF * NE + 255) / 256, 256>>>(W2, w2h, w2l, FF, NE);

    embed_kernel<<<(MTOT * NE + 255) / 256, 256>>>(idx, tok, pos);

    for (int l = 0; l < NL; l++) {
        ln_kernel<true><<<MTOT, 128>>>(px, nullptr, ph16, ln1g + l * NE, ln1b + l * NE);
        gemm_hmma<0><<<dim3(MTOT / TM, NQKV / TN), HM_THREADS, HM_SMEM>>>(
            ph16, wqh + (size_t)l * NQKV * NE, wql + (size_t)l * NQKV * NE,
            nullptr, nullptr, nullptr, pqkv, NE);
        flash_kernel<<<dim3(NB * NH, 2), 256, AT_SMEM>>>(pqkv, po16);
        gemm_hmma<1><<<dim3(MTOT / TM, NE / TN), HM_THREADS, HM_SMEM>>>(
            po16, wph + (size_t)l * NE * NE, wpl + (size_t)l * NE * NE,
            bpr + l * NE, px, px, nullptr, NE);
        ln_kernel<true><<<MTOT, 128>>>(px, nullptr, ph16, ln2g + l * NE, ln2b + l * NE);
        gemm_hmma<2><<<dim3(MTOT / TM, FF / TN), HM_THREADS, HM_SMEM>>>(
            ph16, w1h + (size_t)l * FF * NE, w1l + (size_t)l * FF * NE,
            b1 + l * FF, nullptr, nullptr, pm16, NE);
        gemm_hmma<1><<<dim3(MTOT / TM, NE / TN), HM_THREADS, HM_SMEM>>>(
            pm16, w2h + (size_t)l * NE * FF, w2l + (size_t)l * NE * FF,
            b2 + l * NE, px, px, nullptr, FF);
    }
    ln_kernel<false><<<MTOT, 128>>>(px, phf, nullptr, lnfg, lnfb);

    const int NLOG = MTOT * NV;
    float* logits = (out_size >= NLOG) ? out : plog;
    gemm_lm_kernel<<<dim3(MTOT / 64, (NV + 63) / 64), 256>>>(phf, Wlm, blm, logits, NV, NE);

    zero_loss_kernel<<<1, 1>>>();
    loss_kernel<<<MTOT / 8, 256>>>(logits, tgt);
    if (out_size > NLOG)       finalize_loss_kernel<<<1, 1>>>(out + NLOG);
    else if (out_size >= 1 && out_size < NLOG) finalize_loss_kernel<<<1, 1>>>(out);
}

// round 7
// speedup vs baseline: 5.5051x; 1.0247x over previous
#include <cuda_runtime.h>
#include <cuda_fp16.h>
#include <cstdint>
#include <math.h>

#define NL 6
#define NH 6
#define NE 384
#define HS 64
#define NT 256
#define NB 64
#define NV 65
#define MTOT (NB*NT)      /* 16384 rows */
#define FF (4*NE)         /* 1536 */
#define NQKV (3*NE)       /* 1152 */
#define LNEPS 1e-5f
#define LOSCALE 1024.0f
#define LOINV (1.0f/1024.0f)

// ================= scratch =================
__device__ __align__(256) float g_x[MTOT*NE];
__device__ __align__(256) float g_hf[MTOT*NE];
__device__ __align__(256) __half g_qkv16[3*MTOT*NE];
__device__ __align__(256) __half g_o16[MTOT*NE];
__device__ __align__(256) __half g_m16[MTOT*FF];
__device__ __align__(256) float g_logits[MTOT*NV];
__device__ double g_loss;
__device__ __align__(256) __half g_wqkv_h[NL*NQKV*NE];
__device__ __align__(256) __half g_wqkv_l[NL*NQKV*NE];
__device__ __align__(256) __half g_wpr_h[NL*NE*NE];
__device__ __align__(256) __half g_wpr_l[NL*NE*NE];
__device__ __align__(256) __half g_w1_h[NL*FF*NE];
__device__ __align__(256) __half g_w1_l[NL*FF*NE];
__device__ __align__(256) __half g_w2_h[NL*NE*FF];
__device__ __align__(256) __half g_w2_l[NL*NE*FF];

// hi = rn(v); lo = rn((v-hi)*1024) so lo products stay in fp16 normal range
__device__ __forceinline__ void split_fp16s(float v, __half& hi, __half& lo) {
    hi = __float2half_rn(v);
    lo = __float2half_rn((v - __half2float(hi)) * LOSCALE);
}

// ================= PTX helpers (base ISA: sm_80+) =================
__device__ __forceinline__ uint32_t smem_u32(const void* p) {
    uint32_t a;
    asm("{ .reg .u64 t; cvta.to.shared.u64 t, %1; cvt.u32.u64 %0, t; }" : "=r"(a) : "l"(p));
    return a;
}
__device__ __forceinline__ void cp16(uint32_t dst, const void* src) {
    asm volatile("cp.async.cg.shared.global [%0], [%1], 16;" :: "r"(dst), "l"(src));
}
#define CP_COMMIT() asm volatile("cp.async.commit_group;" ::: "memory")
#define CP_WAIT1()  asm volatile("cp.async.wait_group 1;" ::: "memory")
#define CP_WAIT0()  asm volatile("cp.async.wait_group 0;" ::: "memory")
__device__ __forceinline__ void ldm_x4(uint32_t& r0, uint32_t& r1, uint32_t& r2, uint32_t& r3, uint32_t addr) {
    asm volatile("ldmatrix.sync.aligned.m8n8.x4.shared.b16 {%0,%1,%2,%3}, [%4];"
        : "=r"(r0), "=r"(r1), "=r"(r2), "=r"(r3) : "r"(addr));
}
__device__ __forceinline__ void ldm_x4_t(uint32_t& r0, uint32_t& r1, uint32_t& r2, uint32_t& r3, uint32_t addr) {
    asm volatile("ldmatrix.sync.aligned.m8n8.x4.trans.shared.b16 {%0,%1,%2,%3}, [%4];"
        : "=r"(r0), "=r"(r1), "=r"(r2), "=r"(r3) : "r"(addr));
}
__device__ __forceinline__ void mma_f16(float* c, uint32_t a0, uint32_t a1, uint32_t a2, uint32_t a3,
                                        uint32_t b0, uint32_t b1) {
    asm volatile("mma.sync.aligned.m16n8k16.row.col.f32.f16.f16.f32 "
        "{%0,%1,%2,%3}, {%4,%5,%6,%7}, {%8,%9}, {%0,%1,%2,%3};"
        : "+f"(c[0]), "+f"(c[1]), "+f"(c[2]), "+f"(c[3])
        : "r"(a0), "r"(a1), "r"(a2), "r"(a3), "r"(b0), "r"(b1));
}
__device__ __forceinline__ void mma_f16acc(uint32_t& c0, uint32_t& c1,
                                           uint32_t a0, uint32_t a1, uint32_t a2, uint32_t a3,
                                           uint32_t b0, uint32_t b1) {
    asm volatile("mma.sync.aligned.m16n8k16.row.col.f16.f16.f16.f16 "
        "{%0,%1}, {%2,%3,%4,%5}, {%6,%7}, {%0,%1};"
        : "+r"(c0), "+r"(c1)
        : "r"(a0), "r"(a1), "r"(a2), "r"(a3), "r"(b0), "r"(b1));
}
__device__ __forceinline__ float lo2f(uint32_t u) { __half2 h = *reinterpret_cast<__half2*>(&u); return __low2float(h); }
__device__ __forceinline__ float hi2f(uint32_t u) { __half2 h = *reinterpret_cast<__half2*>(&u); return __high2float(h); }
__device__ __forceinline__ uint32_t pack2(float x, float y) {
    __half2 h2 = __floats2half2_rn(x, y);
    return *reinterpret_cast<uint32_t*>(&h2);
}

// ================= weight prep =================
__global__ void prep_qkv_kernel(const float* __restrict__ Wq, const float* __restrict__ Wk,
                                const float* __restrict__ Wv,
                                __half* __restrict__ Th, __half* __restrict__ Tl) {
    int i = blockIdx.x * 256 + threadIdx.x;
    if (i >= NL * NQKV * NE) return;
    int e = i % NE; int n = (i / NE) % NQKV; int l = i / (NE * NQKV);
    int which = n / NE, rem = n % NE, h = rem >> 6, s = rem & 63;
    const float* W = (which == 0) ? Wq : (which == 1) ? Wk : Wv;
    float v = W[(((size_t)l * NH + h) * NE + e) * HS + s];
    split_fp16s(v, Th[i], Tl[i]);
}
__global__ void prep_t_kernel(const float* __restrict__ W, __half* __restrict__ Th,
                              __half* __restrict__ Tl, int Kd, int Nd) {
    int i = blockIdx.x * 256 + threadIdx.x;
    if (i >= NL * Kd * Nd) return;
    int k = i % Kd; int n = (i / Kd) % Nd; int l = i / (Kd * Nd);
    float v = W[((size_t)l * Kd + k) * Nd + n];
    split_fp16s(v, Th[i], Tl[i]);
}

// ================= embedding =================
__global__ void embed_kernel(const int* __restrict__ idx, const float* __restrict__ tok,
                             const float* __restrict__ pos) {
    int i = blockIdx.x * blockDim.x + threadIdx.x;
    if (i >= MTOT * NE) return;
    int r = i / NE, e = i - r * NE;
    int t = r & (NT - 1);
    g_x[i] = tok[idx[r] * NE + e] + pos[t * NE + e];
}

// ================= final layernorm (fp32 out) =================
__global__ void ln_kernel(const float* __restrict__ in, float* __restrict__ outf,
                          const float* __restrict__ gw, const float* __restrict__ bw) {
    int r = blockIdx.x;
    const float* row = in + (size_t)r * NE;
    int tid = threadIdx.x;
    float v0 = row[tid], v1 = row[tid + 128], v2 = row[tid + 256];
    float s = v0 + v1 + v2;
    float sq = v0 * v0 + v1 * v1 + v2 * v2;
    __shared__ float sm[8];
    #pragma unroll
    for (int o = 16; o; o >>= 1) {
        s  += __shfl_xor_sync(0xffffffffu, s, o);
        sq += __shfl_xor_sync(0xffffffffu, sq, o);
    }
    if ((tid & 31) == 0) { sm[tid >> 5] = s; sm[4 + (tid >> 5)] = sq; }
    __syncthreads();
    s  = sm[0] + sm[1] + sm[2] + sm[3];
    sq = sm[4] + sm[5] + sm[6] + sm[7];
    float mean = s * (1.0f / NE);
    float var  = sq * (1.0f / NE) - mean * mean;
    float inv  = rsqrtf(var + LNEPS);
    #pragma unroll
    for (int u = 0; u < 3; u++) {
        int c = tid + u * 128;
        float vv = (u == 0) ? v0 : (u == 1) ? v1 : v2;
        outf[(size_t)r * NE + c] = (vv - mean) * inv * gw[c] + bw[c];
    }
}

// ============ LN-fused GEMM (K=384): C = LN(x)[M,K] @ Bt[N,K]^T ============
// A computed in-kernel into resident smem. TYPE 0: QKV scatter fp16; TYPE 2: relu fp16.
#define ALN_PITCH 392                      /* halves per resident-A row */
#define ALN_B (128*ALN_PITCH*2)            /* 100352 */
#define LNT_B (128*40*2)                   /* 10240 per B tile */
#define LNS_B (2*LNT_B)                    /* Bh + Bl per stage */
#define GLN_SMEM (ALN_B + 2*LNS_B)         /* 141312 */

template<int TYPE>
__global__ void __launch_bounds__(512, 1)
gemm_ln(const float* __restrict__ x, const float* __restrict__ gw, const float* __restrict__ bw,
        const __half* __restrict__ Bh, const __half* __restrict__ Bl,
        const float* __restrict__ bias, __half* __restrict__ oh) {
    extern __shared__ __align__(128) char smem[];
    const uint32_t sbase = smem_u32(smem);
    const int tid = threadIdx.x;
    const int lane = tid & 31, wid = tid >> 5;
    const int warp_m = wid >> 2, warp_n = wid & 3;
    const int m0 = blockIdx.x * 128, n0 = blockIdx.y * 128;

    // kick off B stages 0,1 (overlaps with LN compute)
    const int lrow = tid >> 2, lc = tid & 3;
    const uint32_t ldst = (uint32_t)(lrow * 80 + lc * 16);
    const __half* srcBh = Bh + (size_t)(n0 + lrow) * NE + lc * 8;
    const __half* srcBl = Bl + (size_t)(n0 + lrow) * NE + lc * 8;
    #pragma unroll
    for (int st = 0; st < 2; st++) {
        uint32_t b = sbase + ALN_B + st * LNS_B + ldst;
        cp16(b, srcBh + st * 32);
        cp16(b + LNT_B, srcBl + st * 32);
        CP_COMMIT();
    }

    // LN of 128 rows directly into resident A smem (one warp per row, 8 rows/warp)
    #pragma unroll
    for (int it = 0; it < 8; it++) {
        int r = wid * 8 + it;
        const float* xr = x + (size_t)(m0 + r) * NE;
        float vals[12];
        float s = 0.f, sq = 0.f;
        #pragma unroll
        for (int j = 0; j < 12; j++) {
            float v = xr[lane + 32 * j];
            vals[j] = v; s += v; sq += v * v;
        }
        #pragma unroll
        for (int o = 16; o; o >>= 1) {
            s  += __shfl_xor_sync(0xffffffffu, s, o);
            sq += __shfl_xor_sync(0xffffffffu, sq, o);
        }
        float mean = s * (1.0f / NE);
        float var  = sq * (1.0f / NE) - mean * mean;
        float inv  = rsqrtf(var + LNEPS);
        #pragma unroll
        for (int j = 0; j < 12; j++) {
            int c = lane + 32 * j;
            float y = (vals[j] - mean) * inv * gw[c] + bw[c];
            *reinterpret_cast<__half*>(smem + ((size_t)r * ALN_PITCH + c) * 2) = __float2half_rn(y);
        }
    }

    float acc[2][4][4];
    uint32_t acc16[2][4][2];
    #pragma unroll
    for (int i = 0; i < 2; i++)
        #pragma unroll
        for (int j = 0; j < 4; j++) {
            acc[i][j][0] = acc[i][j][1] = acc[i][j][2] = acc[i][j][3] = 0.f;
            acc16[i][j][0] = acc16[i][j][1] = 0u;
        }

    const int a_row = warp_m * 32 + (lane & 15);
    const int a_colsel = (lane >> 4) * 8;
    const int b_row = warp_n * 32 + (lane & 7) + ((lane >> 4) << 3);
    const int b_colsel = ((lane >> 3) & 1) * 8;

    const int nc = NE / 32;   // 12
    for (int c = 0; c < nc; c++) {
        CP_WAIT1();
        __syncthreads();   // also orders LN stores before first A reads
        uint32_t bst = sbase + ALN_B + (c & 1) * LNS_B;
        #pragma unroll
        for (int k16 = 0; k16 < 32; k16 += 16) {
            uint32_t af[2][4], bh4[2][4], bl4[2][4];
            #pragma unroll
            for (int mf2 = 0; mf2 < 2; mf2++) {
                uint32_t addr = sbase + ((uint32_t)(a_row + mf2 * 16) * ALN_PITCH + c * 32 + k16 + a_colsel) * 2;
                ldm_x4(af[mf2][0], af[mf2][1], af[mf2][2], af[mf2][3], addr);
            }
            #pragma unroll
            for (int np = 0; np < 2; np++) {
                uint32_t addr = bst + ((uint32_t)(b_row + np * 16) * 40 + k16 + b_colsel) * 2;
                ldm_x4(bh4[np][0], bh4[np][1], bh4[np][2], bh4[np][3], addr);
                ldm_x4(bl4[np][0], bl4[np][1], bl4[np][2], bl4[np][3], addr + LNT_B);
            }
            #pragma unroll
            for (int mf = 0; mf < 2; mf++)
                #pragma unroll
                for (int np = 0; np < 2; np++)
                    #pragma unroll
                    for (int sub = 0; sub < 2; sub++) {
                        int nf = np * 2 + sub;
                        mma_f16(acc[mf][nf], af[mf][0], af[mf][1], af[mf][2], af[mf][3],
                                bh4[np][sub * 2], bh4[np][sub * 2 + 1]);
                        mma_f16acc(acc16[mf][nf][0], acc16[mf][nf][1],
                                   af[mf][0], af[mf][1], af[mf][2], af[mf][3],
                                   bl4[np][sub * 2], bl4[np][sub * 2 + 1]);
                    }
        }
        __syncthreads();
        if (c + 2 < nc) {
            uint32_t b = sbase + ALN_B + (c & 1) * LNS_B + ldst;
            cp16(b, srcBh + (c + 2) * 32);
            cp16(b + LNT_B, srcBl + (c + 2) * 32);
        }
        CP_COMMIT();
    }

    #pragma unroll
    for (int mf = 0; mf < 2; mf++) {
        #pragma unroll
        for (int nf = 0; nf < 4; nf++) {
            #pragma unroll
            for (int i = 0; i < 4; i++) {
                int r = m0 + warp_m * 32 + mf * 16 + (lane >> 2) + ((i >> 1) << 3);
                int n = n0 + warp_n * 32 + nf * 8 + ((lane & 3) << 1) + (i & 1);
                float lo = (i & 1) ? hi2f(acc16[mf][nf][i >> 1]) : lo2f(acc16[mf][nf][i >> 1]);
                float v = acc[mf][nf][i] + lo * LOINV;
                if (TYPE == 0) {
                    int bb = r >> 8, t = r & (NT - 1);
                    int which = n / NE, rem = n - which * NE;
                    int hh = rem >> 6, s = rem & 63;
                    size_t o = (size_t)which * ((size_t)MTOT * NE) +
                               ((((size_t)bb * NH + hh) * NT + t) * HS + s);
                    oh[o] = __float2half_rn(v);
                } else {
                    float y = fmaxf(v + bias[n], 0.f);
                    oh[(size_t)r * FF + n] = __float2half_rn(y);
                }
            }
        }
    }
}

// ======= HMMA GEMM (residual): out = res + A@Bt^T + bias, fp16 A staged =======
#define PITCH 40
#define TILE_B (128*PITCH*2)        /* 10240 */
#define STAGE_B (3*TILE_B)          /* A Bh Bl = 30720 */
#define HM_SMEM (2*STAGE_B)         /* 61440 */

__global__ void __launch_bounds__(512, 1)
gemm_res(const __half* __restrict__ A,
         const __half* __restrict__ Bh, const __half* __restrict__ Bl,
         const float* __restrict__ bias, const float* __restrict__ res,
         float* __restrict__ out0, int K) {
    extern __shared__ __align__(128) char smem[];
    const uint32_t sbase = smem_u32(smem);
    const int tid = threadIdx.x;
    const int lane = tid & 31, wid = tid >> 5;
    const int warp_m = wid >> 2, warp_n = wid & 3;
    const int m0 = blockIdx.x * 128, n0 = blockIdx.y * 128;

    const int lrow = tid >> 2, lc = tid & 3;
    const uint32_t ldst = (uint32_t)(lrow * 80 + lc * 16);
    const __half* srcA  = A  + (size_t)(m0 + lrow) * K + lc * 8;
    const __half* srcBh = Bh + (size_t)(n0 + lrow) * K + lc * 8;
    const __half* srcBl = Bl + (size_t)(n0 + lrow) * K + lc * 8;

    const int nc = K / 32;
    #pragma unroll
    for (int st = 0; st < 2; st++) {
        uint32_t b = sbase + st * STAGE_B + ldst;
        int k0 = st * 32;
        cp16(b + 0 * TILE_B, srcA + k0);
        cp16(b + 1 * TILE_B, srcBh + k0);
        cp16(b + 2 * TILE_B, srcBl + k0);
        CP_COMMIT();
    }

    float acc[2][4][4];
    uint32_t acc16[2][4][2];
    #pragma unroll
    for (int i = 0; i < 2; i++)
        #pragma unroll
        for (int j = 0; j < 4; j++) {
            acc[i][j][0] = acc[i][j][1] = acc[i][j][2] = acc[i][j][3] = 0.f;
            acc16[i][j][0] = acc16[i][j][1] = 0u;
        }

    const int a_row = warp_m * 32 + (lane & 15);
    const int a_colsel = (lane >> 4) * 8;
    const int b_row = warp_n * 32 + (lane & 7) + ((lane >> 4) << 3);
    const int b_colsel = ((lane >> 3) & 1) * 8;

    for (int c = 0; c < nc; c++) {
        CP_WAIT1();
        __syncthreads();
        uint32_t stage = sbase + (c & 1) * STAGE_B;
        #pragma unroll
        for (int k16 = 0; k16 < 32; k16 += 16) {
            uint32_t af[2][4], bh4[2][4], bl4[2][4];
            #pragma unroll
            for (int mf2 = 0; mf2 < 2; mf2++) {
                uint32_t addr = stage + ((uint32_t)(a_row + mf2 * 16) * PITCH + k16 + a_colsel) * 2;
                ldm_x4(af[mf2][0], af[mf2][1], af[mf2][2], af[mf2][3], addr);
            }
            #pragma unroll
            for (int np = 0; np < 2; np++) {
                uint32_t addr = stage + ((uint32_t)(b_row + np * 16) * PITCH + k16 + b_colsel) * 2;
                ldm_x4(bh4[np][0], bh4[np][1], bh4[np][2], bh4[np][3], addr + 1 * TILE_B);
                ldm_x4(bl4[np][0], bl4[np][1], bl4[np][2], bl4[np][3], addr + 2 * TILE_B);
            }
            #pragma unroll
            for (int mf = 0; mf < 2; mf++)
                #pragma unroll
                for (int np = 0; np < 2; np++)
                    #pragma unroll
                    for (int sub = 0; sub < 2; sub++) {
                        int nf = np * 2 + sub;
                        mma_f16(acc[mf][nf], af[mf][0], af[mf][1], af[mf][2], af[mf][3],
                                bh4[np][sub * 2], bh4[np][sub * 2 + 1]);
                        mma_f16acc(acc16[mf][nf][0], acc16[mf][nf][1],
                                   af[mf][0], af[mf][1], af[mf][2], af[mf][3],
                                   bl4[np][sub * 2], bl4[np][sub * 2 + 1]);
                    }
        }
        __syncthreads();
        if (c + 2 < nc) {
            uint32_t b = sbase + (c & 1) * STAGE_B + ldst;
            int k0 = (c + 2) * 32;
            cp16(b + 0 * TILE_B, srcA + k0);
            cp16(b + 1 * TILE_B, srcBh + k0);
            cp16(b + 2 * TILE_B, srcBl + k0);
        }
        CP_COMMIT();
    }

    #pragma unroll
    for (int mf = 0; mf < 2; mf++) {
        #pragma unroll
        for (int nf = 0; nf < 4; nf++) {
            #pragma unroll
            for (int i = 0; i < 4; i++) {
                int r = m0 + warp_m * 32 + mf * 16 + (lane >> 2) + ((i >> 1) << 3);
                int n = n0 + warp_n * 32 + nf * 8 + ((lane & 3) << 1) + (i & 1);
                float lo = (i & 1) ? hi2f(acc16[mf][nf][i >> 1]) : lo2f(acc16[mf][nf][i >> 1]);
                float v = acc[mf][nf][i] + lo * LOINV;
                size_t o = (size_t)r * NE + n;
                out0[o] = res[o] + v + bias[n];
            }
        }
    }
}

// ================= flash attention (fp16; QK fp16-acc, PV fp32-acc) =========
#define AQT 128
#define AKT 64
#define APITCH 72
#define ATILE_B (AKT*APITCH*2)      /* 9216 */
#define ASTAGE_B (2*ATILE_B)        /* K,V = 18432 */
#define AQ_OFF (2*ASTAGE_B)         /* 36864 */
#define AT_SMEM (AQ_OFF + 128*APITCH*2)  /* 55296 */

__device__ __forceinline__ void flash_issue(uint32_t bs, int kt, int tid,
    const __half* Kp, const __half* Vp) {
    #pragma unroll
    for (int i2 = 0; i2 < 2; i2++) {
        int i = tid + i2 * 256;
        int r = i >> 3, ch = i & 7;
        uint32_t off = (uint32_t)(r * (APITCH * 2) + ch * 16);
        size_t g = (size_t)(kt * AKT + r) * HS + ch * 8;
        cp16(bs + 0 * ATILE_B + off, Kp + g);
        cp16(bs + 1 * ATILE_B + off, Vp + g);
    }
}

__global__ void __launch_bounds__(256, 1)
flash_kernel(const __half* __restrict__ qkv, __half* __restrict__ oo) {
    extern __shared__ __align__(128) char smem[];
    const uint32_t sbase = smem_u32(smem);
    const int tid = threadIdx.x, lane = tid & 31, wid = tid >> 5;
    const int bh = blockIdx.x, qt = blockIdx.y;
    const int b = bh / NH, h = bh - b * NH;
    const size_t TS = (size_t)MTOT * NE;
    const size_t base_bh = (size_t)bh * NT * HS;
    const __half* Qp = qkv + base_bh;
    const __half* Kp = qkv + TS + base_bh;
    const __half* Vp = qkv + 2 * TS + base_bh;

    for (int i = tid; i < 1024; i += 256) {
        int r = i >> 3, ch = i & 7;
        uint32_t off = (uint32_t)(r * (APITCH * 2) + ch * 16);
        cp16(sbase + AQ_OFF + off, Qp + (size_t)(qt * AQT + r) * HS + ch * 8);
    }
    flash_issue(sbase, 0, tid, Kp, Vp);
    CP_COMMIT();
    CP_WAIT0();
    __syncthreads();
    uint32_t qf[4][4];
    {
        int a_row = wid * 16 + (lane & 15);
        int a_col = (lane >> 4) * 8;
        #pragma unroll
        for (int ks = 0; ks < 4; ks++) {
            uint32_t ad = sbase + AQ_OFF + (uint32_t)((a_row * APITCH + ks * 16 + a_col) * 2);
            ldm_x4(qf[ks][0], qf[ks][1], qf[ks][2], qf[ks][3], ad);
        }
    }

    const int nkt = 2 * (qt + 1);
    float of[8][4];
    #pragma unroll
    for (int i = 0; i < 8; i++)
        #pragma unroll
        for (int j = 0; j < 4; j++) of[i][j] = 0.f;
    float m0 = -1e30f, m1 = -1e30f, l0 = 0.f, l1 = 0.f;
    const float scale = rsqrtf((float)NE);
    const int qrow0 = qt * AQT + wid * 16 + (lane >> 2);
    const int warp_qmax = qt * AQT + wid * 16 + 15;

    for (int kt = 0; kt < nkt; kt++) {
        if (kt + 1 < nkt) flash_issue(sbase + ((kt + 1) & 1) * ASTAGE_B, kt + 1, tid, Kp, Vp);
        CP_COMMIT();
        CP_WAIT1();
        __syncthreads();
        if (kt * AKT <= warp_qmax) {
            uint32_t kb = sbase + (kt & 1) * ASTAGE_B;
            uint32_t sc16[8][2];
            #pragma unroll
            for (int i = 0; i < 8; i++) { sc16[i][0] = 0u; sc16[i][1] = 0u; }
            #pragma unroll
            for (int ks = 0; ks < 4; ks++) {
                uint32_t bf[4][4];
                #pragma unroll
                for (int np = 0; np < 4; np++) {
                    int brow = np * 16 + (lane & 7) + ((lane >> 4) << 3);
                    int bcol = ks * 16 + ((lane >> 3) & 1) * 8;
                    uint32_t ad = kb + (uint32_t)((brow * APITCH + bcol) * 2);
                    ldm_x4(bf[np][0], bf[np][1], bf[np][2], bf[np][3], ad);
                }
                #pragma unroll
                for (int np = 0; np < 4; np++)
                    #pragma unroll
                    for (int sub = 0; sub < 2; sub++)
                        mma_f16acc(sc16[np * 2 + sub][0], sc16[np * 2 + sub][1],
                                   qf[ks][0], qf[ks][1], qf[ks][2], qf[ks][3],
                                   bf[np][sub * 2], bf[np][sub * 2 + 1]);
            }
            float sc[8][4];
            #pragma unroll
            for (int nf = 0; nf < 8; nf++) {
                sc[nf][0] = lo2f(sc16[nf][0]); sc[nf][1] = hi2f(sc16[nf][0]);
                sc[nf][2] = lo2f(sc16[nf][1]); sc[nf][3] = hi2f(sc16[nf][1]);
            }
            // scale + causal mask
            #pragma unroll
            for (int nf = 0; nf < 8; nf++)
                #pragma unroll
                for (int j = 0; j < 4; j++) {
                    int kcol = kt * AKT + nf * 8 + ((lane & 3) << 1) + (j & 1);
                    int qr = (j < 2) ? qrow0 : (qrow0 + 8);
                    sc[nf][j] = (kcol <= qr) ? sc[nf][j] * scale : -1e30f;
                }
            // online softmax
            float ml0 = -1e30f, ml1 = -1e30f;
            #pragma unroll
            for (int nf = 0; nf < 8; nf++) {
                ml0 = fmaxf(ml0, fmaxf(sc[nf][0], sc[nf][1]));
                ml1 = fmaxf(ml1, fmaxf(sc[nf][2], sc[nf][3]));
            }
            ml0 = fmaxf(ml0, __shfl_xor_sync(0xffffffffu, ml0, 1));
            ml0 = fmaxf(ml0, __shfl_xor_sync(0xffffffffu, ml0, 2));
            ml1 = fmaxf(ml1, __shfl_xor_sync(0xffffffffu, ml1, 1));
            ml1 = fmaxf(ml1, __shfl_xor_sync(0xffffffffu, ml1, 2));
            float mn0 = fmaxf(m0, ml0), mn1 = fmaxf(m1, ml1);
            float a0 = __expf(m0 - mn0), a1 = __expf(m1 - mn1);
            float rs0 = 0.f, rs1 = 0.f;
            #pragma unroll
            for (int nf = 0; nf < 8; nf++) {
                sc[nf][0] = __expf(sc[nf][0] - mn0); rs0 += sc[nf][0];
                sc[nf][1] = __expf(sc[nf][1] - mn0); rs0 += sc[nf][1];
                sc[nf][2] = __expf(sc[nf][2] - mn1); rs1 += sc[nf][2];
                sc[nf][3] = __expf(sc[nf][3] - mn1); rs1 += sc[nf][3];
            }
            rs0 += __shfl_xor_sync(0xffffffffu, rs0, 1);
            rs0 += __shfl_xor_sync(0xffffffffu, rs0, 2);
            rs1 += __shfl_xor_sync(0xffffffffu, rs1, 1);
            rs1 += __shfl_xor_sync(0xffffffffu, rs1, 2);
            #pragma unroll
            for (int nf = 0; nf < 8; nf++) {
                of[nf][0] *= a0; of[nf][1] *= a0;
                of[nf][2] *= a1; of[nf][3] *= a1;
            }
            l0 = l0 * a0 + rs0; l1 = l1 * a1 + rs1;
            m0 = mn0; m1 = mn1;
            // P @ V (fp32 acc)
            #pragma unroll
            for (int ks = 0; ks < 4; ks++) {
                uint32_t pf[4];
                pf[0] = pack2(sc[2 * ks][0], sc[2 * ks][1]);
                pf[1] = pack2(sc[2 * ks][2], sc[2 * ks][3]);
                pf[2] = pack2(sc[2 * ks + 1][0], sc[2 * ks + 1][1]);
                pf[3] = pack2(sc[2 * ks + 1][2], sc[2 * ks + 1][3]);
                uint32_t vf[4][4];
                #pragma unroll
                for (int nd = 0; nd < 4; nd++) {
                    int vrow = ks * 16 + (lane & 7) + (((lane >> 3) & 1) << 3);
                    int vcol = nd * 16 + ((lane >> 4) << 3);
                    uint32_t ad = kb + (uint32_t)((vrow * APITCH + vcol) * 2);
                    ldm_x4_t(vf[nd][0], vf[nd][1], vf[nd][2], vf[nd][3], ad + ATILE_B);
                }
                #pragma unroll
                for (int nd = 0; nd < 4; nd++)
                    #pragma unroll
                    for (int sub = 0; sub < 2; sub++)
                        mma_f16(of[nd * 2 + sub], pf[0], pf[1], pf[2], pf[3],
                                vf[nd][sub * 2], vf[nd][sub * 2 + 1]);
            }
        }
        __syncthreads();
    }

    float inv0 = 1.f / l0, inv1 = 1.f / l1;
    size_t row0 = ((size_t)b * NT + qrow0) * NE + h * HS;
    size_t row1 = row0 + (size_t)8 * NE;
    #pragma unroll
    for (int nf = 0; nf < 8; nf++) {
        int d = nf * 8 + ((lane & 3) << 1);
        *reinterpret_cast<uint32_t*>(&oo[row0 + d]) = pack2(of[nf][0] * inv0, of[nf][1] * inv0);
        *reinterpret_cast<uint32_t*>(&oo[row1 + d]) = pack2(of[nf][2] * inv1, of[nf][3] * inv1);
    }
}

// ================= fp32 SIMT gemm for LM head (N=65) =================
__global__ void gemm_lm_kernel(const float* __restrict__ A, const float* __restrict__ Bm,
                               const float* __restrict__ bias, float* __restrict__ C,
                               int N, int K) {
    __shared__ float As[16][64];
    __shared__ float Bs[16][68];
    int tid = threadIdx.x;
    int tx = tid & 15, ty = tid >> 4;
    int rowBase = blockIdx.x * 64, colBase = blockIdx.y * 64;
    float acc[4][4] = {};
    int la_m = tid >> 2, la_k = (tid & 3) * 4;
    int lb_k = tid >> 4, lb_n = (tid & 15) * 4;
    for (int k0 = 0; k0 < K; k0 += 16) {
        float4 a4 = *(const float4*)(A + (size_t)(rowBase + la_m) * K + k0 + la_k);
        As[la_k + 0][la_m] = a4.x; As[la_k + 1][la_m] = a4.y;
        As[la_k + 2][la_m] = a4.z; As[la_k + 3][la_m] = a4.w;
        #pragma unroll
        for (int u = 0; u < 4; u++) {
            int n = colBase + lb_n + u;
            Bs[lb_k][lb_n + u] = (n < N) ? Bm[(size_t)(k0 + lb_k) * N + n] : 0.f;
        }
        __syncthreads();
        #pragma unroll
        for (int kk = 0; kk < 16; kk++) {
            float4 a = *(float4*)&As[kk][ty * 4];
            float4 b = *(float4*)&Bs[kk][tx * 4];
            float av[4] = {a.x, a.y, a.z, a.w};
            float bv[4] = {b.x, b.y, b.z, b.w};
            #pragma unroll
            for (int i = 0; i < 4; i++)
                #pragma unroll
                for (int j = 0; j < 4; j++)
                    acc[i][j] += av[i] * bv[j];
        }
        __syncthreads();
    }
    #pragma unroll
    for (int i = 0; i < 4; i++) {
        int r = rowBase + ty * 4 + i;
        #pragma unroll
        for (int j = 0; j < 4; j++) {
            int c = colBase + tx * 4 + j;
            if (c >= N) continue;
            C[(size_t)r * N + c] = acc[i][j] + bias[c];
        }
    }
}

// ================= loss =================
__global__ void zero_loss_kernel() { g_loss = 0.0; }

__global__ void loss_kernel(const float* __restrict__ logits, const int* __restrict__ tgt) {
    int row = blockIdx.x * 8 + (threadIdx.x >> 5);
    int lane = threadIdx.x & 31;
    const float* lp = logits + (size_t)row * NV;
    float v0 = lp[lane];
    float v1 = (lane + 32 < NV) ? lp[lane + 32] : -1e30f;
    float v2 = (lane + 64 < NV) ? lp[lane + 64] : -1e30f;
    float m = fmaxf(v0, fmaxf(v1, v2));
    #pragma unroll
    for (int off = 16; off; off >>= 1) m = fmaxf(m, __shfl_xor_sync(0xffffffffu, m, off));
    float su = expf(v0 - m);
    if (lane + 32 < NV) su += expf(v1 - m);
    if (lane + 64 < NV) su += expf(v2 - m);
    #pragma unroll
    for (int off = 16; off; off >>= 1) su += __shfl_xor_sync(0xffffffffu, su, off);
    if (lane == 0) {
        float lt = lp[tgt[row]];
        double nl = -((double)lt - (double)m - (double)logf(su));
        atomicAdd(&g_loss, nl);
    }
}

__global__ void finalize_loss_kernel(float* __restrict__ out) {
    out[0] = (float)(g_loss / (double)MTOT);
}

// ================= launch =================
extern "C" void kernel_launch(void* const* d_in, const int* in_sizes, int n_in,
                              void* d_out, int out_size) {
    const int*   idx  = (const int*)d_in[0];
    const int*   tgt  = (const int*)d_in[1];
    const float* tok  = (const float*)d_in[2];
    const float* pos  = (const float*)d_in[3];
    const float* Wq   = (const float*)d_in[4];
    const float* Wk   = (const float*)d_in[5];
    const float* Wv   = (const float*)d_in[6];
    const float* Wpr  = (const float*)d_in[7];
    const float* bpr  = (const float*)d_in[8];
    const float* ln1g = (const float*)d_in[9];
    const float* ln1b = (const float*)d_in[10];
    const float* ln2g = (const float*)d_in[11];
    const float* ln2b = (const float*)d_in[12];
    const float* W1   = (const float*)d_in[13];
    const float* b1   = (const float*)d_in[14];
    const float* W2   = (const float*)d_in[15];
    const float* b2   = (const float*)d_in[16];
    const float* lnfg = (const float*)d_in[17];
    const float* lnfb = (const float*)d_in[18];
    const float* Wlm  = (const float*)d_in[19];
    const float* blm  = (const float*)d_in[20];
    float* out = (float*)d_out;

    float *px, *phf, *plog;
    __half *pqkv, *po16, *pm16;
    __half *wqh, *wql, *wph, *wpl, *w1h, *w1l, *w2h, *w2l;
    cudaGetSymbolAddress((void**)&px, g_x);
    cudaGetSymbolAddress((void**)&phf, g_hf);
    cudaGetSymbolAddress((void**)&plog, g_logits);
    cudaGetSymbolAddress((void**)&pqkv, g_qkv16);
    cudaGetSymbolAddress((void**)&po16, g_o16);
    cudaGetSymbolAddress((void**)&pm16, g_m16);
    cudaGetSymbolAddress((void**)&wqh, g_wqkv_h);
    cudaGetSymbolAddress((void**)&wql, g_wqkv_l);
    cudaGetSymbolAddress((void**)&wph, g_wpr_h);
    cudaGetSymbolAddress((void**)&wpl, g_wpr_l);
    cudaGetSymbolAddress((void**)&w1h, g_w1_h);
    cudaGetSymbolAddress((void**)&w1l, g_w1_l);
    cudaGetSymbolAddress((void**)&w2h, g_w2_h);
    cudaGetSymbolAddress((void**)&w2l, g_w2_l);

    cudaFuncSetAttribute(flash_kernel, cudaFuncAttributeMaxDynamicSharedMemorySize, AT_SMEM);
    cudaFuncSetAttribute(gemm_res, cudaFuncAttributeMaxDynamicSharedMemorySize, HM_SMEM);
    cudaFuncSetAttribute(gemm_ln<0>, cudaFuncAttributeMaxDynamicSharedMemorySize, GLN_SMEM);
    cudaFuncSetAttribute(gemm_ln<2>, cudaFuncAttributeMaxDynamicSharedMemorySize, GLN_SMEM);

    prep_qkv_kernel<<<(NL * NQKV * NE + 255) / 256, 256>>>(Wq, Wk, Wv, wqh, wql);
    prep_t_kernel<<<(NL * NE * NE + 255) / 256, 256>>>(Wpr, wph, wpl, NE, NE);
    prep_t_kernel<<<(NL * NE * FF + 255) / 256, 256>>>(W1, w1h, w1l, NE, FF);
    prep_t_kernel<<<(NL * FF * NE + 255) / 256, 256>>>(W2, w2h, w2l, FF, NE);

    embed_kernel<<<(MTOT * NE + 255) / 256, 256>>>(idx, tok, pos);

    for (int l = 0; l < NL; l++) {
        gemm_ln<0><<<dim3(MTOT / 128, NQKV / 128), 512, GLN_SMEM>>>(
            px, ln1g + l * NE, ln1b + l * NE,
            wqh + (size_t)l * NQKV * NE, wql + (size_t)l * NQKV * NE,
            nullptr, pqkv);
        flash_kernel<<<dim3(NB * NH, 2), 256, AT_SMEM>>>(pqkv, po16);
        gemm_res<<<dim3(MTOT / 128, NE / 128), 512, HM_SMEM>>>(
            po16, wph + (size_t)l * NE * NE, wpl + (size_t)l * NE * NE,
            bpr + l * NE, px, px, NE);
        gemm_ln<2><<<dim3(MTOT / 128, FF / 128), 512, GLN_SMEM>>>(
            px, ln2g + l * NE, ln2b + l * NE,
            w1h + (size_t)l * FF * NE, w1l + (size_t)l * FF * NE,
            b1 + l * FF, pm16);
        gemm_res<<<dim3(MTOT / 128, NE / 128), 512, HM_SMEM>>>(
            pm16, w2h + (size_t)l * NE * FF, w2l + (size_t)l * NE * FF,
            b2 + l * NE, px, px, FF);
    }
    ln_kernel<<<MTOT, 128>>>(px, phf, lnfg, lnfb);

    const int NLOG = MTOT * NV;
    float* logits = (out_size >= NLOG) ? out : plog;
    gemm_lm_kernel<<<dim3(MTOT / 64, (NV + 63) / 64), 256>>>(phf, Wlm, blm, logits, NV, NE);

    zero_loss_kernel<<<1, 1>>>();
    loss_kernel<<<MTOT / 8, 256>>>(logits, tgt);
    if (out_size > NLOG)       finalize_loss_kernel<<<1, 1>>>(out + NLOG);
    else if (out_size >= 1 && out_size < NLOG) finalize_loss_kernel<<<1, 1>>>(out);
}

// round 9
// speedup vs baseline: 6.9942x; 1.2705x over previous
#include <cuda_runtime.h>
#include <cuda_fp16.h>
#include <cstdint>
#include <math.h>

#define NL 6
#define NH 6
#define NE 384
#define HS 64
#define NT 256
#define NB 64
#define NV 65
#define MTOT (NB*NT)      /* 16384 rows */
#define FF (4*NE)         /* 1536 */
#define NQKV (3*NE)       /* 1152 */
#define LNEPS 1e-5f

// ================= scratch =================
__device__ __align__(256) float g_x[MTOT*NE];
__device__ __align__(256) float g_hf[MTOT*NE];
__device__ __align__(256) __half g_qkv16[3*MTOT*NE];
__device__ __align__(256) __half g_o16[MTOT*NE];
__device__ __align__(256) __half g_m16[MTOT*FF];
__device__ __align__(256) float g_logits[MTOT*NV];
__device__ double g_loss;
__device__ __align__(256) __half g_wqkv[NL*NQKV*NE];
__device__ __align__(256) __half g_wpr[NL*NE*NE];
__device__ __align__(256) __half g_w1[NL*FF*NE];
__device__ __align__(256) __half g_w2[NL*NE*FF];

// ================= PTX helpers (base ISA: sm_80+) =================
__device__ __forceinline__ uint32_t smem_u32(const void* p) {
    uint32_t a;
    asm("{ .reg .u64 t; cvta.to.shared.u64 t, %1; cvt.u32.u64 %0, t; }" : "=r"(a) : "l"(p));
    return a;
}
__device__ __forceinline__ void cp16(uint32_t dst, const void* src) {
    asm volatile("cp.async.cg.shared.global [%0], [%1], 16;" :: "r"(dst), "l"(src));
}
#define CP_COMMIT() asm volatile("cp.async.commit_group;" ::: "memory")
#define CP_WAIT1()  asm volatile("cp.async.wait_group 1;" ::: "memory")
#define CP_WAIT0()  asm volatile("cp.async.wait_group 0;" ::: "memory")
__device__ __forceinline__ void ldm_x4(uint32_t& r0, uint32_t& r1, uint32_t& r2, uint32_t& r3, uint32_t addr) {
    asm volatile("ldmatrix.sync.aligned.m8n8.x4.shared.b16 {%0,%1,%2,%3}, [%4];"
        : "=r"(r0), "=r"(r1), "=r"(r2), "=r"(r3) : "r"(addr));
}
__device__ __forceinline__ void ldm_x4_t(uint32_t& r0, uint32_t& r1, uint32_t& r2, uint32_t& r3, uint32_t addr) {
    asm volatile("ldmatrix.sync.aligned.m8n8.x4.trans.shared.b16 {%0,%1,%2,%3}, [%4];"
        : "=r"(r0), "=r"(r1), "=r"(r2), "=r"(r3) : "r"(addr));
}
__device__ __forceinline__ void mma_f16(float* c, uint32_t a0, uint32_t a1, uint32_t a2, uint32_t a3,
                                        uint32_t b0, uint32_t b1) {
    asm volatile("mma.sync.aligned.m16n8k16.row.col.f32.f16.f16.f32 "
        "{%0,%1,%2,%3}, {%4,%5,%6,%7}, {%8,%9}, {%0,%1,%2,%3};"
        : "+f"(c[0]), "+f"(c[1]), "+f"(c[2]), "+f"(c[3])
        : "r"(a0), "r"(a1), "r"(a2), "r"(a3), "r"(b0), "r"(b1));
}
__device__ __forceinline__ void mma_f16acc(uint32_t& c0, uint32_t& c1,
                                           uint32_t a0, uint32_t a1, uint32_t a2, uint32_t a3,
                                           uint32_t b0, uint32_t b1) {
    asm volatile("mma.sync.aligned.m16n8k16.row.col.f16.f16.f16.f16 "
        "{%0,%1}, {%2,%3,%4,%5}, {%6,%7}, {%0,%1};"
        : "+r"(c0), "+r"(c1)
        : "r"(a0), "r"(a1), "r"(a2), "r"(a3), "r"(b0), "r"(b1));
}
__device__ __forceinline__ float lo2f(uint32_t u) { __half2 h = *reinterpret_cast<__half2*>(&u); return __low2float(h); }
__device__ __forceinline__ float hi2f(uint32_t u) { __half2 h = *reinterpret_cast<__half2*>(&u); return __high2float(h); }
__device__ __forceinline__ uint32_t pack2(float x, float y) {
    __half2 h2 = __floats2half2_rn(x, y);
    return *reinterpret_cast<uint32_t*>(&h2);
}

// ================= weight prep (single fp16, transposed [N,K]) =================
__global__ void prep_qkv_kernel(const float* __restrict__ Wq, const float* __restrict__ Wk,
                                const float* __restrict__ Wv, __half* __restrict__ Th) {
    int i = blockIdx.x * 256 + threadIdx.x;
    if (i >= NL * NQKV * NE) return;
    int e = i % NE; int n = (i / NE) % NQKV; int l = i / (NE * NQKV);
    int which = n / NE, rem = n % NE, h = rem >> 6, s = rem & 63;
    const float* W = (which == 0) ? Wq : (which == 1) ? Wk : Wv;
    Th[i] = __float2half_rn(W[(((size_t)l * NH + h) * NE + e) * HS + s]);
}
__global__ void prep_t_kernel(const float* __restrict__ W, __half* __restrict__ Th,
                              int Kd, int Nd) {
    int i = blockIdx.x * 256 + threadIdx.x;
    if (i >= NL * Kd * Nd) return;
    int k = i % Kd; int n = (i / Kd) % Nd; int l = i / (Kd * Nd);
    Th[i] = __float2half_rn(W[((size_t)l * Kd + k) * Nd + n]);
}

// ================= embedding =================
__global__ void embed_kernel(const int* __restrict__ idx, const float* __restrict__ tok,
                             const float* __restrict__ pos) {
    int i = blockIdx.x * blockDim.x + threadIdx.x;
    if (i >= MTOT * NE) return;
    int r = i / NE, e = i - r * NE;
    int t = r & (NT - 1);
    g_x[i] = tok[idx[r] * NE + e] + pos[t * NE + e];
}

// ================= final layernorm (fp32 out) =================
__global__ void ln_kernel(const float* __restrict__ in, float* __restrict__ outf,
                          const float* __restrict__ gw, const float* __restrict__ bw) {
    int r = blockIdx.x;
    const float* row = in + (size_t)r * NE;
    int tid = threadIdx.x;
    float v0 = row[tid], v1 = row[tid + 128], v2 = row[tid + 256];
    float s = v0 + v1 + v2;
    float sq = v0 * v0 + v1 * v1 + v2 * v2;
    __shared__ float sm[8];
    #pragma unroll
    for (int o = 16; o; o >>= 1) {
        s  += __shfl_xor_sync(0xffffffffu, s, o);
        sq += __shfl_xor_sync(0xffffffffu, sq, o);
    }
    if ((tid & 31) == 0) { sm[tid >> 5] = s; sm[4 + (tid >> 5)] = sq; }
    __syncthreads();
    s  = sm[0] + sm[1] + sm[2] + sm[3];
    sq = sm[4] + sm[5] + sm[6] + sm[7];
    float mean = s * (1.0f / NE);
    float var  = sq * (1.0f / NE) - mean * mean;
    float inv  = rsqrtf(var + LNEPS);
    #pragma unroll
    for (int u = 0; u < 3; u++) {
        int c = tid + u * 128;
        float vv = (u == 0) ? v0 : (u == 1) ? v1 : v2;
        outf[(size_t)r * NE + c] = (vv - mean) * inv * gw[c] + bw[c];
    }
}

// ============ LN-fused GEMM (K=384): C = LN(x)[M,K] @ Bt[N,K]^T ============
// TYPE 0: QKV scatter fp16; TYPE 2: relu fp16.
#define ALN_PITCH 392                      /* halves per resident-A row */
#define ALN_B (128*ALN_PITCH*2)            /* 100352 */
#define LNT_B (128*40*2)                   /* 10240 per B tile (one stage) */
#define GLN_SMEM (ALN_B + 2*LNT_B)         /* 120832 */

template<int TYPE>
__global__ void __launch_bounds__(512, 1)
gemm_ln(const float* __restrict__ x, const float* __restrict__ gw, const float* __restrict__ bw,
        const __half* __restrict__ Bh,
        const float* __restrict__ bias, __half* __restrict__ oh) {
    extern __shared__ __align__(128) char smem[];
    const uint32_t sbase = smem_u32(smem);
    const int tid = threadIdx.x;
    const int lane = tid & 31, wid = tid >> 5;
    const int warp_m = wid >> 2, warp_n = wid & 3;
    const int m0 = blockIdx.x * 128, n0 = blockIdx.y * 128;

    // kick off B stages 0,1 (overlaps with LN compute)
    const int lrow = tid >> 2, lc = tid & 3;
    const uint32_t ldst = (uint32_t)(lrow * 80 + lc * 16);
    const __half* srcBh = Bh + (size_t)(n0 + lrow) * NE + lc * 8;
    #pragma unroll
    for (int st = 0; st < 2; st++) {
        cp16(sbase + ALN_B + st * LNT_B + ldst, srcBh + st * 32);
        CP_COMMIT();
    }

    // LN of 128 rows directly into resident A smem (one warp per row, 8 rows/warp)
    #pragma unroll
    for (int it = 0; it < 8; it++) {
        int r = wid * 8 + it;
        const float* xr = x + (size_t)(m0 + r) * NE;
        float vals[12];
        float s = 0.f, sq = 0.f;
        #pragma unroll
        for (int j = 0; j < 12; j++) {
            float v = xr[lane + 32 * j];
            vals[j] = v; s += v; sq += v * v;
        }
        #pragma unroll
        for (int o = 16; o; o >>= 1) {
            s  += __shfl_xor_sync(0xffffffffu, s, o);
            sq += __shfl_xor_sync(0xffffffffu, sq, o);
        }
        float mean = s * (1.0f / NE);
        float var  = sq * (1.0f / NE) - mean * mean;
        float inv  = rsqrtf(var + LNEPS);
        #pragma unroll
        for (int j = 0; j < 12; j++) {
            int c = lane + 32 * j;
            float y = (vals[j] - mean) * inv * gw[c] + bw[c];
            *reinterpret_cast<__half*>(smem + ((size_t)r * ALN_PITCH + c) * 2) = __float2half_rn(y);
        }
    }

    float acc[2][4][4];
    #pragma unroll
    for (int i = 0; i < 2; i++)
        #pragma unroll
        for (int j = 0; j < 4; j++)
            acc[i][j][0] = acc[i][j][1] = acc[i][j][2] = acc[i][j][3] = 0.f;

    const int a_row = warp_m * 32 + (lane & 15);
    const int a_colsel = (lane >> 4) * 8;
    const int b_row = warp_n * 32 + (lane & 7) + ((lane >> 4) << 3);
    const int b_colsel = ((lane >> 3) & 1) * 8;

    const int nc = NE / 32;   // 12
    for (int c = 0; c < nc; c++) {
        CP_WAIT1();
        __syncthreads();   // also orders LN stores before first A reads
        uint32_t bst = sbase + ALN_B + (c & 1) * LNT_B;
        #pragma unroll
        for (int k16 = 0; k16 < 32; k16 += 16) {
            uint32_t af[2][4], bh4[2][4];
            #pragma unroll
            for (int mf2 = 0; mf2 < 2; mf2++) {
                uint32_t addr = sbase + ((uint32_t)(a_row + mf2 * 16) * ALN_PITCH + c * 32 + k16 + a_colsel) * 2;
                ldm_x4(af[mf2][0], af[mf2][1], af[mf2][2], af[mf2][3], addr);
            }
            #pragma unroll
            for (int np = 0; np < 2; np++) {
                uint32_t addr = bst + ((uint32_t)(b_row + np * 16) * 40 + k16 + b_colsel) * 2;
                ldm_x4(bh4[np][0], bh4[np][1], bh4[np][2], bh4[np][3], addr);
            }
            #pragma unroll
            for (int mf = 0; mf < 2; mf++)
                #pragma unroll
                for (int np = 0; np < 2; np++)
                    #pragma unroll
                    for (int sub = 0; sub < 2; sub++)
                        mma_f16(acc[mf][np * 2 + sub], af[mf][0], af[mf][1], af[mf][2], af[mf][3],
                                bh4[np][sub * 2], bh4[np][sub * 2 + 1]);
        }
        __syncthreads();
        if (c + 2 < nc)
            cp16(sbase + ALN_B + (c & 1) * LNT_B + ldst, srcBh + (c + 2) * 32);
        CP_COMMIT();
    }

    #pragma unroll
    for (int mf = 0; mf < 2; mf++) {
        #pragma unroll
        for (int nf = 0; nf < 4; nf++) {
            #pragma unroll
            for (int i = 0; i < 4; i++) {
                int r = m0 + warp_m * 32 + mf * 16 + (lane >> 2) + ((i >> 1) << 3);
                int n = n0 + warp_n * 32 + nf * 8 + ((lane & 3) << 1) + (i & 1);
                float v = acc[mf][nf][i];
                if (TYPE == 0) {
                    int bb = r >> 8, t = r & (NT - 1);
                    int which = n / NE, rem = n - which * NE;
                    int hh = rem >> 6, s = rem & 63;
                    size_t o = (size_t)which * ((size_t)MTOT * NE) +
                               ((((size_t)bb * NH + hh) * NT + t) * HS + s);
                    oh[o] = __float2half_rn(v);
                } else {
                    float y = fmaxf(v + bias[n], 0.f);
                    oh[(size_t)r * FF + n] = __float2half_rn(y);
                }
            }
        }
    }
}

// ======= HMMA GEMM (residual): out = res + A@Bt^T + bias =======
#define PITCH 40
#define TILE_B (128*PITCH*2)        /* 10240 */
#define STAGE_B (2*TILE_B)          /* A B = 20480 */
#define HM_SMEM (2*STAGE_B)         /* 40960 -> occupancy 2 */

__global__ void __launch_bounds__(512, 2)
gemm_res(const __half* __restrict__ A, const __half* __restrict__ Bh,
         const float* __restrict__ bias, const float* __restrict__ res,
         float* __restrict__ out0, int K) {
    extern __shared__ __align__(128) char smem[];
    const uint32_t sbase = smem_u32(smem);
    const int tid = threadIdx.x;
    const int lane = tid & 31, wid = tid >> 5;
    const int warp_m = wid >> 2, warp_n = wid & 3;
    const int m0 = blockIdx.x * 128, n0 = blockIdx.y * 128;

    const int lrow = tid >> 2, lc = tid & 3;
    const uint32_t ldst = (uint32_t)(lrow * 80 + lc * 16);
    const __half* srcA  = A  + (size_t)(m0 + lrow) * K + lc * 8;
    const __half* srcBh = Bh + (size_t)(n0 + lrow) * K + lc * 8;

    const int nc = K / 32;
    #pragma unroll
    for (int st = 0; st < 2; st++) {
        uint32_t b = sbase + st * STAGE_B + ldst;
        int k0 = st * 32;
        cp16(b + 0 * TILE_B, srcA + k0);
        cp16(b + 1 * TILE_B, srcBh + k0);
        CP_COMMIT();
    }

    float acc[2][4][4];
    #pragma unroll
    for (int i = 0; i < 2; i++)
        #pragma unroll
        for (int j = 0; j < 4; j++)
            acc[i][j][0] = acc[i][j][1] = acc[i][j][2] = acc[i][j][3] = 0.f;

    const int a_row = warp_m * 32 + (lane & 15);
    const int a_colsel = (lane >> 4) * 8;
    const int b_row = warp_n * 32 + (lane & 7) + ((lane >> 4) << 3);
    const int b_colsel = ((lane >> 3) & 1) * 8;

    for (int c = 0; c < nc; c++) {
        CP_WAIT1();
        __syncthreads();
        uint32_t stage = sbase + (c & 1) * STAGE_B;
        #pragma unroll
        for (int k16 = 0; k16 < 32; k16 += 16) {
            uint32_t af[2][4], bh4[2][4];
            #pragma unroll
            for (int mf2 = 0; mf2 < 2; mf2++) {
                uint32_t addr = stage + ((uint32_t)(a_row + mf2 * 16) * PITCH + k16 + a_colsel) * 2;
                ldm_x4(af[mf2][0], af[mf2][1], af[mf2][2], af[mf2][3], addr);
            }
            #pragma unroll
            for (int np = 0; np < 2; np++) {
                uint32_t addr = stage + ((uint32_t)(b_row + np * 16) * PITCH + k16 + b_colsel) * 2;
                ldm_x4(bh4[np][0], bh4[np][1], bh4[np][2], bh4[np][3], addr + 1 * TILE_B);
            }
            #pragma unroll
            for (int mf = 0; mf < 2; mf++)
                #pragma unroll
                for (int np = 0; np < 2; np++)
                    #pragma unroll
                    for (int sub = 0; sub < 2; sub++)
                        mma_f16(acc[mf][np * 2 + sub], af[mf][0], af[mf][1], af[mf][2], af[mf][3],
                                bh4[np][sub * 2], bh4[np][sub * 2 + 1]);
        }
        __syncthreads();
        if (c + 2 < nc) {
            uint32_t b = sbase + (c & 1) * STAGE_B + ldst;
            int k0 = (c + 2) * 32;
            cp16(b + 0 * TILE_B, srcA + k0);
            cp16(b + 1 * TILE_B, srcBh + k0);
        }
        CP_COMMIT();
    }

    #pragma unroll
    for (int mf = 0; mf < 2; mf++) {
        #pragma unroll
        for (int nf = 0; nf < 4; nf++) {
            #pragma unroll
            for (int i = 0; i < 4; i++) {
                int r = m0 + warp_m * 32 + mf * 16 + (lane >> 2) + ((i >> 1) << 3);
                int n = n0 + warp_n * 32 + nf * 8 + ((lane & 3) << 1) + (i & 1);
                size_t o = (size_t)r * NE + n;
                out0[o] = res[o] + acc[mf][nf][i] + bias[n];
            }
        }
    }
}

// ================= flash attention (fp16; QK fp16-acc, PV fp32-acc) =========
#define AQT 128
#define AKT 64
#define APITCH 72
#define ATILE_B (AKT*APITCH*2)      /* 9216 */
#define ASTAGE_B (2*ATILE_B)        /* K,V = 18432 */
#define AQ_OFF (2*ASTAGE_B)         /* 36864 */
#define AT_SMEM (AQ_OFF + 128*APITCH*2)  /* 55296 */

__device__ __forceinline__ void flash_issue(uint32_t bs, int kt, int tid,
    const __half* Kp, const __half* Vp) {
    #pragma unroll
    for (int i2 = 0; i2 < 2; i2++) {
        int i = tid + i2 * 256;
        int r = i >> 3, ch = i & 7;
        uint32_t off = (uint32_t)(r * (APITCH * 2) + ch * 16);
        size_t g = (size_t)(kt * AKT + r) * HS + ch * 8;
        cp16(bs + 0 * ATILE_B + off, Kp + g);
        cp16(bs + 1 * ATILE_B + off, Vp + g);
    }
}

__global__ void __launch_bounds__(256, 1)
flash_kernel(const __half* __restrict__ qkv, __half* __restrict__ oo) {
    extern __shared__ __align__(128) char smem[];
    const uint32_t sbase = smem_u32(smem);
    const int tid = threadIdx.x, lane = tid & 31, wid = tid >> 5;
    const int bh = blockIdx.x, qt = blockIdx.y;
    const int b = bh / NH, h = bh - b * NH;
    const size_t TS = (size_t)MTOT * NE;
    const size_t base_bh = (size_t)bh * NT * HS;
    const __half* Qp = qkv + base_bh;
    const __half* Kp = qkv + TS + base_bh;
    const __half* Vp = qkv + 2 * TS + base_bh;

    for (int i = tid; i < 1024; i += 256) {
        int r = i >> 3, ch = i & 7;
        uint32_t off = (uint32_t)(r * (APITCH * 2) + ch * 16);
        cp16(sbase + AQ_OFF + off, Qp + (size_t)(qt * AQT + r) * HS + ch * 8);
    }
    flash_issue(sbase, 0, tid, Kp, Vp);
    CP_COMMIT();
    CP_WAIT0();
    __syncthreads();
    uint32_t qf[4][4];
    {
        int a_row = wid * 16 + (lane & 15);
        int a_col = (lane >> 4) * 8;
        #pragma unroll
        for (int ks = 0; ks < 4; ks++) {
            uint32_t ad = sbase + AQ_OFF + (uint32_t)((a_row * APITCH + ks * 16 + a_col) * 2);
            ldm_x4(qf[ks][0], qf[ks][1], qf[ks][2], qf[ks][3], ad);
        }
    }

    const int nkt = 2 * (qt + 1);
    float of[8][4];
    #pragma unroll
    for (int i = 0; i < 8; i++)
        #pragma unroll
        for (int j = 0; j < 4; j++) of[i][j] = 0.f;
    float m0 = -1e30f, m1 = -1e30f, l0 = 0.f, l1 = 0.f;
    const float scale = rsqrtf((float)NE);
    const int qrow0 = qt * AQT + wid * 16 + (lane >> 2);
    const int warp_qmax = qt * AQT + wid * 16 + 15;

    for (int kt = 0; kt < nkt; kt++) {
        if (kt + 1 < nkt) flash_issue(sbase + ((kt + 1) & 1) * ASTAGE_B, kt + 1, tid, Kp, Vp);
        CP_COMMIT();
        CP_WAIT1();
        __syncthreads();
        if (kt * AKT <= warp_qmax) {
            uint32_t kb = sbase + (kt & 1) * ASTAGE_B;
            uint32_t sc16[8][2];
            #pragma unroll
            for (int i = 0; i < 8; i++) { sc16[i][0] = 0u; sc16[i][1] = 0u; }
            #pragma unroll
            for (int ks = 0; ks < 4; ks++) {
                uint32_t bf[4][4];
                #pragma unroll
                for (int np = 0; np < 4; np++) {
                    int brow = np * 16 + (lane & 7) + ((lane >> 4) << 3);
                    int bcol = ks * 16 + ((lane >> 3) & 1) * 8;
                    uint32_t ad = kb + (uint32_t)((brow * APITCH + bcol) * 2);
                    ldm_x4(bf[np][0], bf[np][1], bf[np][2], bf[np][3], ad);
                }
                #pragma unroll
                for (int np = 0; np < 4; np++)
                    #pragma unroll
                    for (int sub = 0; sub < 2; sub++)
                        mma_f16acc(sc16[np * 2 + sub][0], sc16[np * 2 + sub][1],
                                   qf[ks][0], qf[ks][1], qf[ks][2], qf[ks][3],
                                   bf[np][sub * 2], bf[np][sub * 2 + 1]);
            }
            float sc[8][4];
            #pragma unroll
            for (int nf = 0; nf < 8; nf++) {
                sc[nf][0] = lo2f(sc16[nf][0]); sc[nf][1] = hi2f(sc16[nf][0]);
                sc[nf][2] = lo2f(sc16[nf][1]); sc[nf][3] = hi2f(sc16[nf][1]);
            }
            // scale + causal mask
            #pragma unroll
            for (int nf = 0; nf < 8; nf++)
                #pragma unroll
                for (int j = 0; j < 4; j++) {
                    int kcol = kt * AKT + nf * 8 + ((lane & 3) << 1) + (j & 1);
                    int qr = (j < 2) ? qrow0 : (qrow0 + 8);
                    sc[nf][j] = (kcol <= qr) ? sc[nf][j] * scale : -1e30f;
                }
            // online softmax
            float ml0 = -1e30f, ml1 = -1e30f;
            #pragma unroll
            for (int nf = 0; nf < 8; nf++) {
                ml0 = fmaxf(ml0, fmaxf(sc[nf][0], sc[nf][1]));
                ml1 = fmaxf(ml1, fmaxf(sc[nf][2], sc[nf][3]));
            }
            ml0 = fmaxf(ml0, __shfl_xor_sync(0xffffffffu, ml0, 1));
            ml0 = fmaxf(ml0, __shfl_xor_sync(0xffffffffu, ml0, 2));
            ml1 = fmaxf(ml1, __shfl_xor_sync(0xffffffffu, ml1, 1));
            ml1 = fmaxf(ml1, __shfl_xor_sync(0xffffffffu, ml1, 2));
            float mn0 = fmaxf(m0, ml0), mn1 = fmaxf(m1, ml1);
            float a0 = __expf(m0 - mn0), a1 = __expf(m1 - mn1);
            float rs0 = 0.f, rs1 = 0.f;
            #pragma unroll
            for (int nf = 0; nf < 8; nf++) {
                sc[nf][0] = __expf(sc[nf][0] - mn0); rs0 += sc[nf][0];
                sc[nf][1] = __expf(sc[nf][1] - mn0); rs0 += sc[nf][1];
                sc[nf][2] = __expf(sc[nf][2] - mn1); rs1 += sc[nf][2];
                sc[nf][3] = __expf(sc[nf][3] - mn1); rs1 += sc[nf][3];
            }
            rs0 += __shfl_xor_sync(0xffffffffu, rs0, 1);
            rs0 += __shfl_xor_sync(0xffffffffu, rs0, 2);
            rs1 += __shfl_xor_sync(0xffffffffu, rs1, 1);
            rs1 += __shfl_xor_sync(0xffffffffu, rs1, 2);
            #pragma unroll
            for (int nf = 0; nf < 8; nf++) {
                of[nf][0] *= a0; of[nf][1] *= a0;
                of[nf][2] *= a1; of[nf][3] *= a1;
            }
            l0 = l0 * a0 + rs0; l1 = l1 * a1 + rs1;
            m0 = mn0; m1 = mn1;
            // P @ V (fp32 acc)
            #pragma unroll
            for (int ks = 0; ks < 4; ks++) {
                uint32_t pf[4];
                pf[0] = pack2(sc[2 * ks][0], sc[2 * ks][1]);
                pf[1] = pack2(sc[2 * ks][2], sc[2 * ks][3]);
                pf[2] = pack2(sc[2 * ks + 1][0], sc[2 * ks + 1][1]);
                pf[3] = pack2(sc[2 * ks + 1][2], sc[2 * ks + 1][3]);
                uint32_t vf[4][4];
                #pragma unroll
                for (int nd = 0; nd < 4; nd++) {
                    int vrow = ks * 16 + (lane & 7) + (((lane >> 3) & 1) << 3);
                    int vcol = nd * 16 + ((lane >> 4) << 3);
                    uint32_t ad = kb + (uint32_t)((vrow * APITCH + vcol) * 2);
                    ldm_x4_t(vf[nd][0], vf[nd][1], vf[nd][2], vf[nd][3], ad + ATILE_B);
                }
                #pragma unroll
                for (int nd = 0; nd < 4; nd++)
                    #pragma unroll
                    for (int sub = 0; sub < 2; sub++)
                        mma_f16(of[nd * 2 + sub], pf[0], pf[1], pf[2], pf[3],
                                vf[nd][sub * 2], vf[nd][sub * 2 + 1]);
            }
        }
        __syncthreads();
    }

    float inv0 = 1.f / l0, inv1 = 1.f / l1;
    size_t row0 = ((size_t)b * NT + qrow0) * NE + h * HS;
    size_t row1 = row0 + (size_t)8 * NE;
    #pragma unroll
    for (int nf = 0; nf < 8; nf++) {
        int d = nf * 8 + ((lane & 3) << 1);
        *reinterpret_cast<uint32_t*>(&oo[row0 + d]) = pack2(of[nf][0] * inv0, of[nf][1] * inv0);
        *reinterpret_cast<uint32_t*>(&oo[row1 + d]) = pack2(of[nf][2] * inv1, of[nf][3] * inv1);
    }
}

// ================= fp32 SIMT gemm for LM head (N=65) =================
__global__ void gemm_lm_kernel(const float* __restrict__ A, const float* __restrict__ Bm,
                               const float* __restrict__ bias, float* __restrict__ C,
                               int N, int K) {
    __shared__ float As[16][64];
    __shared__ float Bs[16][68];
    int tid = threadIdx.x;
    int tx = tid & 15, ty = tid >> 4;
    int rowBase = blockIdx.x * 64, colBase = blockIdx.y * 64;
    float acc[4][4] = {};
    int la_m = tid >> 2, la_k = (tid & 3) * 4;
    int lb_k = tid >> 4, lb_n = (tid & 15) * 4;
    for (int k0 = 0; k0 < K; k0 += 16) {
        float4 a4 = *(const float4*)(A + (size_t)(rowBase + la_m) * K + k0 + la_k);
        As[la_k + 0][la_m] = a4.x; As[la_k + 1][la_m] = a4.y;
        As[la_k + 2][la_m] = a4.z; As[la_k + 3][la_m] = a4.w;
        #pragma unroll
        for (int u = 0; u < 4; u++) {
            int n = colBase + lb_n + u;
            Bs[lb_k][lb_n + u] = (n < N) ? Bm[(size_t)(k0 + lb_k) * N + n] : 0.f;
        }
        __syncthreads();
        #pragma unroll
        for (int kk = 0; kk < 16; kk++) {
            float4 a = *(float4*)&As[kk][ty * 4];
            float4 b = *(float4*)&Bs[kk][tx * 4];
            float av[4] = {a.x, a.y, a.z, a.w};
            float bv[4] = {b.x, b.y, b.z, b.w};
            #pragma unroll
            for (int i = 0; i < 4; i++)
                #pragma unroll
                for (int j = 0; j < 4; j++)
                    acc[i][j] += av[i] * bv[j];
        }
        __syncthreads();
    }
    #pragma unroll
    for (int i = 0; i < 4; i++) {
        int r = rowBase + ty * 4 + i;
        #pragma unroll
        for (int j = 0; j < 4; j++) {
            int c = colBase + tx * 4 + j;
            if (c >= N) continue;
            C[(size_t)r * N + c] = acc[i][j] + bias[c];
        }
    }
}

// ================= loss =================
__global__ void zero_loss_kernel() { g_loss = 0.0; }

__global__ void loss_kernel(const float* __restrict__ logits, const int* __restrict__ tgt) {
    int row = blockIdx.x * 8 + (threadIdx.x >> 5);
    int lane = threadIdx.x & 31;
    const float* lp = logits + (size_t)row * NV;
    float v0 = lp[lane];
    float v1 = (lane + 32 < NV) ? lp[lane + 32] : -1e30f;
    float v2 = (lane + 64 < NV) ? lp[lane + 64] : -1e30f;
    float m = fmaxf(v0, fmaxf(v1, v2));
    #pragma unroll
    for (int off = 16; off; off >>= 1) m = fmaxf(m, __shfl_xor_sync(0xffffffffu, m, off));
    float su = expf(v0 - m);
    if (lane + 32 < NV) su += expf(v1 - m);
    if (lane + 64 < NV) su += expf(v2 - m);
    #pragma unroll
    for (int off = 16; off; off >>= 1) su += __shfl_xor_sync(0xffffffffu, su, off);
    if (lane == 0) {
        float lt = lp[tgt[row]];
        double nl = -((double)lt - (double)m - (double)logf(su));
        atomicAdd(&g_loss, nl);
    }
}

__global__ void finalize_loss_kernel(float* __restrict__ out) {
    out[0] = (float)(g_loss / (double)MTOT);
}

// ================= launch =================
extern "C" void kernel_launch(void* const* d_in, const int* in_sizes, int n_in,
                              void* d_out, int out_size) {
    const int*   idx  = (const int*)d_in[0];
    const int*   tgt  = (const int*)d_in[1];
    const float* tok  = (const float*)d_in[2];
    const float* pos  = (const float*)d_in[3];
    const float* Wq   = (const float*)d_in[4];
    const float* Wk   = (const float*)d_in[5];
    const float* Wv   = (const float*)d_in[6];
    const float* Wpr  = (const float*)d_in[7];
    const float* bpr  = (const float*)d_in[8];
    const float* ln1g = (const float*)d_in[9];
    const float* ln1b = (const float*)d_in[10];
    const float* ln2g = (const float*)d_in[11];
    const float* ln2b = (const float*)d_in[12];
    const float* W1   = (const float*)d_in[13];
    const float* b1   = (const float*)d_in[14];
    const float* W2   = (const float*)d_in[15];
    const float* b2   = (const float*)d_in[16];
    const float* lnfg = (const float*)d_in[17];
    const float* lnfb = (const float*)d_in[18];
    const float* Wlm  = (const float*)d_in[19];
    const float* blm  = (const float*)d_in[20];
    float* out = (float*)d_out;

    float *px, *phf, *plog;
    __half *pqkv, *po16, *pm16;
    __half *wq, *wp, *w1, *w2;
    cudaGetSymbolAddress((void**)&px, g_x);
    cudaGetSymbolAddress((void**)&phf, g_hf);
    cudaGetSymbolAddress((void**)&plog, g_logits);
    cudaGetSymbolAddress((void**)&pqkv, g_qkv16);
    cudaGetSymbolAddress((void**)&po16, g_o16);
    cudaGetSymbolAddress((void**)&pm16, g_m16);
    cudaGetSymbolAddress((void**)&wq, g_wqkv);
    cudaGetSymbolAddress((void**)&wp, g_wpr);
    cudaGetSymbolAddress((void**)&w1, g_w1);
    cudaGetSymbolAddress((void**)&w2, g_w2);

    cudaFuncSetAttribute(flash_kernel, cudaFuncAttributeMaxDynamicSharedMemorySize, AT_SMEM);
    cudaFuncSetAttribute(gemm_res, cudaFuncAttributeMaxDynamicSharedMemorySize, HM_SMEM);
    cudaFuncSetAttribute(gemm_ln<0>, cudaFuncAttributeMaxDynamicSharedMemorySize, GLN_SMEM);
    cudaFuncSetAttribute(gemm_ln<2>, cudaFuncAttributeMaxDynamicSharedMemorySize, GLN_SMEM);

    prep_qkv_kernel<<<(NL * NQKV * NE + 255) / 256, 256>>>(Wq, Wk, Wv, wq);
    prep_t_kernel<<<(NL * NE * NE + 255) / 256, 256>>>(Wpr, wp, NE, NE);
    prep_t_kernel<<<(NL * NE * FF + 255) / 256, 256>>>(W1, w1, NE, FF);
    prep_t_kernel<<<(NL * FF * NE + 255) / 256, 256>>>(W2, w2, FF, NE);

    embed_kernel<<<(MTOT * NE + 255) / 256, 256>>>(idx, tok, pos);

    for (int l = 0; l < NL; l++) {
        gemm_ln<0><<<dim3(MTOT / 128, NQKV / 128), 512, GLN_SMEM>>>(
            px, ln1g + l * NE, ln1b + l * NE,
            wq + (size_t)l * NQKV * NE, nullptr, pqkv);
        flash_kernel<<<dim3(NB * NH, 2), 256, AT_SMEM>>>(pqkv, po16);
        gemm_res<<<dim3(MTOT / 128, NE / 128), 512, HM_SMEM>>>(
            po16, wp + (size_t)l * NE * NE, bpr + l * NE, px, px, NE);
        gemm_ln<2><<<dim3(MTOT / 128, FF / 128), 512, GLN_SMEM>>>(
            px, ln2g + l * NE, ln2b + l * NE,
            w1 + (size_t)l * FF * NE, b1 + l * FF, pm16);
        gemm_res<<<dim3(MTOT / 128, NE / 128), 512, HM_SMEM>>>(
            pm16, w2 + (size_t)l * NE * FF, b2 + l * NE, px, px, FF);
    }
    ln_kernel<<<MTOT, 128>>>(px, phf, lnfg, lnfb);

    const int NLOG = MTOT * NV;
    float* logits = (out_size >= NLOG) ? out : plog;
    gemm_lm_kernel<<<dim3(MTOT / 64, (NV + 63) / 64), 256>>>(phf, Wlm, blm, logits, NV, NE);

    zero_loss_kernel<<<1, 1>>>();
    loss_kernel<<<MTOT / 8, 256>>>(logits, tgt);
    if (out_size > NLOG)       finalize_loss_kernel<<<1, 1>>>(out + NLOG);
    else if (out_size >= 1 && out_size < NLOG) finalize_loss_kernel<<<1, 1>>>(out);
}

// round 10
// speedup vs baseline: 9.1163x; 1.3034x over previous
#include <cuda_runtime.h>
#include <cuda_fp16.h>
#include <cstdint>
#include <math.h>

#define NL 6
#define NH 6
#define NE 384
#define HS 64
#define NT 256
#define NB 64
#define NV 65
#define MTOT (NB*NT)      /* 16384 rows */
#define FF (4*NE)         /* 1536 */
#define NQKV (3*NE)       /* 1152 */
#define LNEPS 1e-5f

// ================= scratch =================
__device__ __align__(256) float g_x[MTOT*NE];
__device__ __align__(256) float g_hf[MTOT*NE];
__device__ __align__(256) __half g_qkv16[3*MTOT*NE];
__device__ __align__(256) __half g_o16[MTOT*NE];
__device__ __align__(256) __half g_m16[MTOT*FF];
__device__ __align__(256) float g_logits[MTOT*NV];
__device__ double g_loss;
__device__ __align__(256) __half g_wqkv[NL*NQKV*NE];
__device__ __align__(256) __half g_wpr[NL*NE*NE];
__device__ __align__(256) __half g_w1[NL*FF*NE];
__device__ __align__(256) __half g_w2[NL*NE*FF];

// ================= PTX helpers (base ISA: sm_80+) =================
__device__ __forceinline__ uint32_t smem_u32(const void* p) {
    uint32_t a;
    asm("{ .reg .u64 t; cvta.to.shared.u64 t, %1; cvt.u32.u64 %0, t; }" : "=r"(a) : "l"(p));
    return a;
}
__device__ __forceinline__ void cp16(uint32_t dst, const void* src) {
    asm volatile("cp.async.cg.shared.global [%0], [%1], 16;" :: "r"(dst), "l"(src));
}
#define CP_COMMIT() asm volatile("cp.async.commit_group;" ::: "memory")
#define CP_WAIT2()  asm volatile("cp.async.wait_group 2;" ::: "memory")
#define CP_WAIT1()  asm volatile("cp.async.wait_group 1;" ::: "memory")
#define CP_WAIT0()  asm volatile("cp.async.wait_group 0;" ::: "memory")
__device__ __forceinline__ void ldm_x4(uint32_t& r0, uint32_t& r1, uint32_t& r2, uint32_t& r3, uint32_t addr) {
    asm volatile("ldmatrix.sync.aligned.m8n8.x4.shared.b16 {%0,%1,%2,%3}, [%4];"
        : "=r"(r0), "=r"(r1), "=r"(r2), "=r"(r3) : "r"(addr));
}
__device__ __forceinline__ void ldm_x4_t(uint32_t& r0, uint32_t& r1, uint32_t& r2, uint32_t& r3, uint32_t addr) {
    asm volatile("ldmatrix.sync.aligned.m8n8.x4.trans.shared.b16 {%0,%1,%2,%3}, [%4];"
        : "=r"(r0), "=r"(r1), "=r"(r2), "=r"(r3) : "r"(addr));
}
__device__ __forceinline__ void mma_f16(float* c, uint32_t a0, uint32_t a1, uint32_t a2, uint32_t a3,
                                        uint32_t b0, uint32_t b1) {
    asm volatile("mma.sync.aligned.m16n8k16.row.col.f32.f16.f16.f32 "
        "{%0,%1,%2,%3}, {%4,%5,%6,%7}, {%8,%9}, {%0,%1,%2,%3};"
        : "+f"(c[0]), "+f"(c[1]), "+f"(c[2]), "+f"(c[3])
        : "r"(a0), "r"(a1), "r"(a2), "r"(a3), "r"(b0), "r"(b1));
}
__device__ __forceinline__ void mma_f16acc(uint32_t& c0, uint32_t& c1,
                                           uint32_t a0, uint32_t a1, uint32_t a2, uint32_t a3,
                                           uint32_t b0, uint32_t b1) {
    asm volatile("mma.sync.aligned.m16n8k16.row.col.f16.f16.f16.f16 "
        "{%0,%1}, {%2,%3,%4,%5}, {%6,%7}, {%0,%1};"
        : "+r"(c0), "+r"(c1)
        : "r"(a0), "r"(a1), "r"(a2), "r"(a3), "r"(b0), "r"(b1));
}
__device__ __forceinline__ float lo2f(uint32_t u) { __half2 h = *reinterpret_cast<__half2*>(&u); return __low2float(h); }
__device__ __forceinline__ float hi2f(uint32_t u) { __half2 h = *reinterpret_cast<__half2*>(&u); return __high2float(h); }
__device__ __forceinline__ uint32_t pack2(float x, float y) {
    __half2 h2 = __floats2half2_rn(x, y);
    return *reinterpret_cast<uint32_t*>(&h2);
}

// ================= weight prep (single fp16, transposed [N,K]) =================
__global__ void prep_qkv_kernel(const float* __restrict__ Wq, const float* __restrict__ Wk,
                                const float* __restrict__ Wv, __half* __restrict__ Th) {
    int i = blockIdx.x * 256 + threadIdx.x;
    if (i >= NL * NQKV * NE) return;
    int e = i % NE; int n = (i / NE) % NQKV; int l = i / (NE * NQKV);
    int which = n / NE, rem = n % NE, h = rem >> 6, s = rem & 63;
    const float* W = (which == 0) ? Wq : (which == 1) ? Wk : Wv;
    Th[i] = __float2half_rn(W[(((size_t)l * NH + h) * NE + e) * HS + s]);
}
__global__ void prep_t_kernel(const float* __restrict__ W, __half* __restrict__ Th,
                              int Kd, int Nd) {
    int i = blockIdx.x * 256 + threadIdx.x;
    if (i >= NL * Kd * Nd) return;
    int k = i % Kd; int n = (i / Kd) % Nd; int l = i / (Kd * Nd);
    Th[i] = __float2half_rn(W[((size_t)l * Kd + k) * Nd + n]);
}

// ================= embedding =================
__global__ void embed_kernel(const int* __restrict__ idx, const float* __restrict__ tok,
                             const float* __restrict__ pos) {
    int i = blockIdx.x * blockDim.x + threadIdx.x;
    if (i >= MTOT * NE) return;
    int r = i / NE, e = i - r * NE;
    int t = r & (NT - 1);
    g_x[i] = tok[idx[r] * NE + e] + pos[t * NE + e];
}

// ================= final layernorm (fp32 out) =================
__global__ void ln_kernel(const float* __restrict__ in, float* __restrict__ outf,
                          const float* __restrict__ gw, const float* __restrict__ bw) {
    int r = blockIdx.x;
    const float* row = in + (size_t)r * NE;
    int tid = threadIdx.x;
    float v0 = row[tid], v1 = row[tid + 128], v2 = row[tid + 256];
    float s = v0 + v1 + v2;
    float sq = v0 * v0 + v1 * v1 + v2 * v2;
    __shared__ float sm[8];
    #pragma unroll
    for (int o = 16; o; o >>= 1) {
        s  += __shfl_xor_sync(0xffffffffu, s, o);
        sq += __shfl_xor_sync(0xffffffffu, sq, o);
    }
    if ((tid & 31) == 0) { sm[tid >> 5] = s; sm[4 + (tid >> 5)] = sq; }
    __syncthreads();
    s  = sm[0] + sm[1] + sm[2] + sm[3];
    sq = sm[4] + sm[5] + sm[6] + sm[7];
    float mean = s * (1.0f / NE);
    float var  = sq * (1.0f / NE) - mean * mean;
    float inv  = rsqrtf(var + LNEPS);
    #pragma unroll
    for (int u = 0; u < 3; u++) {
        int c = tid + u * 128;
        float vv = (u == 0) ? v0 : (u == 1) ? v1 : v2;
        outf[(size_t)r * NE + c] = (vv - mean) * inv * gw[c] + bw[c];
    }
}

// ============ LN-fused GEMM (K=384): C = LN(x)[M,K] @ Bt[N,K]^T ============
// 4-stage B ring, batched LN preamble, paired fp16 stores.
// TYPE 0: QKV scatter fp16; TYPE 2: relu fp16.
#define ALN_PITCH 392                      /* halves per resident-A row */
#define ALN_B (128*ALN_PITCH*2)            /* 100352 */
#define LNT_B (128*40*2)                   /* 10240 per B tile */
#define GLN_SMEM (ALN_B + 4*LNT_B)         /* 141312 */

template<int TYPE>
__global__ void __launch_bounds__(512, 1)
gemm_ln(const float* __restrict__ x, const float* __restrict__ gw, const float* __restrict__ bw,
        const __half* __restrict__ Bh,
        const float* __restrict__ bias, __half* __restrict__ oh) {
    extern __shared__ __align__(128) char smem[];
    const uint32_t sbase = smem_u32(smem);
    const int tid = threadIdx.x;
    const int lane = tid & 31, wid = tid >> 5;
    const int warp_m = wid >> 2, warp_n = wid & 3;
    const int m0 = blockIdx.x * 128, n0 = blockIdx.y * 128;
    const int nc = NE / 32;   // 12

    // kick off B stages for chunks 0,1,2 (overlaps with LN compute)
    const int lrow = tid >> 2, lc = tid & 3;
    const uint32_t ldst = (uint32_t)(lrow * 80 + lc * 16);
    const __half* srcBh = Bh + (size_t)(n0 + lrow) * NE + lc * 8;
    #pragma unroll
    for (int st = 0; st < 3; st++) {
        cp16(sbase + ALN_B + st * LNT_B + ldst, srcBh + st * 32);
        CP_COMMIT();
    }

    // LN of 128 rows into resident A smem. One warp per 8 rows, 2 rows/iteration.
    {
        const float4* gw4 = (const float4*)gw;
        const float4* bw4 = (const float4*)bw;
        float4 gg[3], bb[3];
        #pragma unroll
        for (int j = 0; j < 3; j++) { gg[j] = gw4[lane + 32 * j]; bb[j] = bw4[lane + 32 * j]; }
        #pragma unroll
        for (int it = 0; it < 4; it++) {
            int r0 = wid * 8 + it * 2;
            const float4* p0 = (const float4*)(x + (size_t)(m0 + r0) * NE);
            const float4* p1 = (const float4*)(x + (size_t)(m0 + r0 + 1) * NE);
            float4 a[3], b[3];
            #pragma unroll
            for (int j = 0; j < 3; j++) { a[j] = p0[lane + 32 * j]; b[j] = p1[lane + 32 * j]; }
            float s0 = 0.f, q0 = 0.f, s1 = 0.f, q1 = 0.f;
            #pragma unroll
            for (int j = 0; j < 3; j++) {
                s0 += a[j].x + a[j].y + a[j].z + a[j].w;
                q0 += a[j].x * a[j].x + a[j].y * a[j].y + a[j].z * a[j].z + a[j].w * a[j].w;
                s1 += b[j].x + b[j].y + b[j].z + b[j].w;
                q1 += b[j].x * b[j].x + b[j].y * b[j].y + b[j].z * b[j].z + b[j].w * b[j].w;
            }
            #pragma unroll
            for (int o = 16; o; o >>= 1) {
                s0 += __shfl_xor_sync(0xffffffffu, s0, o);
                q0 += __shfl_xor_sync(0xffffffffu, q0, o);
                s1 += __shfl_xor_sync(0xffffffffu, s1, o);
                q1 += __shfl_xor_sync(0xffffffffu, q1, o);
            }
            float mean0 = s0 * (1.0f / NE), mean1 = s1 * (1.0f / NE);
            float inv0 = rsqrtf(q0 * (1.0f / NE) - mean0 * mean0 + LNEPS);
            float inv1 = rsqrtf(q1 * (1.0f / NE) - mean1 * mean1 + LNEPS);
            #pragma unroll
            for (int j = 0; j < 3; j++) {
                uint32_t coff = (uint32_t)((lane + 32 * j) * 4) * 2;
                uint2 w0, w1;
                w0.x = pack2((a[j].x - mean0) * inv0 * gg[j].x + bb[j].x,
                             (a[j].y - mean0) * inv0 * gg[j].y + bb[j].y);
                w0.y = pack2((a[j].z - mean0) * inv0 * gg[j].z + bb[j].z,
                             (a[j].w - mean0) * inv0 * gg[j].w + bb[j].w);
                w1.x = pack2((b[j].x - mean1) * inv1 * gg[j].x + bb[j].x,
                             (b[j].y - mean1) * inv1 * gg[j].y + bb[j].y);
                w1.y = pack2((b[j].z - mean1) * inv1 * gg[j].z + bb[j].z,
                             (b[j].w - mean1) * inv1 * gg[j].w + bb[j].w);
                *(uint2*)(smem + (size_t)r0 * (ALN_PITCH * 2) + coff) = w0;
                *(uint2*)(smem + (size_t)(r0 + 1) * (ALN_PITCH * 2) + coff) = w1;
            }
        }
    }

    float acc[2][4][4];
    #pragma unroll
    for (int i = 0; i < 2; i++)
        #pragma unroll
        for (int j = 0; j < 4; j++)
            acc[i][j][0] = acc[i][j][1] = acc[i][j][2] = acc[i][j][3] = 0.f;

    const int a_row = warp_m * 32 + (lane & 15);
    const int a_colsel = (lane >> 4) * 8;
    const int b_row = warp_n * 32 + (lane & 7) + ((lane >> 4) << 3);
    const int b_colsel = ((lane >> 3) & 1) * 8;

    for (int c = 0; c < nc; c++) {
        CP_WAIT2();
        __syncthreads();   // also orders LN stores before first A reads
        uint32_t bst = sbase + ALN_B + (c & 3) * LNT_B;
        #pragma unroll
        for (int k16 = 0; k16 < 32; k16 += 16) {
            uint32_t af[2][4], bh4[2][4];
            #pragma unroll
            for (int mf2 = 0; mf2 < 2; mf2++) {
                uint32_t addr = sbase + ((uint32_t)(a_row + mf2 * 16) * ALN_PITCH + c * 32 + k16 + a_colsel) * 2;
                ldm_x4(af[mf2][0], af[mf2][1], af[mf2][2], af[mf2][3], addr);
            }
            #pragma unroll
            for (int np = 0; np < 2; np++) {
                uint32_t addr = bst + ((uint32_t)(b_row + np * 16) * 40 + k16 + b_colsel) * 2;
                ldm_x4(bh4[np][0], bh4[np][1], bh4[np][2], bh4[np][3], addr);
            }
            #pragma unroll
            for (int mf = 0; mf < 2; mf++)
                #pragma unroll
                for (int np = 0; np < 2; np++)
                    #pragma unroll
                    for (int sub = 0; sub < 2; sub++)
                        mma_f16(acc[mf][np * 2 + sub], af[mf][0], af[mf][1], af[mf][2], af[mf][3],
                                bh4[np][sub * 2], bh4[np][sub * 2 + 1]);
        }
        __syncthreads();
        if (c + 3 < nc)
            cp16(sbase + ALN_B + ((c + 3) & 3) * LNT_B + ldst, srcBh + (c + 3) * 32);
        CP_COMMIT();
    }

    #pragma unroll
    for (int mf = 0; mf < 2; mf++) {
        #pragma unroll
        for (int nf = 0; nf < 4; nf++) {
            #pragma unroll
            for (int hp = 0; hp < 2; hp++) {
                int r = m0 + warp_m * 32 + mf * 16 + (lane >> 2) + hp * 8;
                int n = n0 + warp_n * 32 + nf * 8 + ((lane & 3) << 1);
                float v0 = acc[mf][nf][hp * 2 + 0];
                float v1 = acc[mf][nf][hp * 2 + 1];
                if (TYPE == 0) {
                    int bb = r >> 8, t = r & (NT - 1);
                    int which = n / NE, rem = n - which * NE;
                    int hh = rem >> 6, s = rem & 63;
                    size_t o = (size_t)which * ((size_t)MTOT * NE) +
                               ((((size_t)bb * NH + hh) * NT + t) * HS + s);
                    *(uint32_t*)&oh[o] = pack2(v0, v1);
                } else {
                    float y0 = fmaxf(v0 + bias[n], 0.f);
                    float y1 = fmaxf(v1 + bias[n + 1], 0.f);
                    *(uint32_t*)&oh[(size_t)r * FF + n] = pack2(y0, y1);
                }
            }
        }
    }
}

// ======= HMMA GEMM (residual): out = res + A@Bt^T + bias, 3-stage ring =======
#define PITCH 40
#define TILE_B (128*PITCH*2)        /* 10240 */
#define STAGE_B (2*TILE_B)          /* A B = 20480 */
#define HM_SMEM (3*STAGE_B)         /* 61440 */

__global__ void __launch_bounds__(512, 2)
gemm_res(const __half* __restrict__ A, const __half* __restrict__ Bh,
         const float* __restrict__ bias, const float* __restrict__ res,
         float* __restrict__ out0, int K) {
    extern __shared__ __align__(128) char smem[];
    const uint32_t sbase = smem_u32(smem);
    const int tid = threadIdx.x;
    const int lane = tid & 31, wid = tid >> 5;
    const int warp_m = wid >> 2, warp_n = wid & 3;
    const int m0 = blockIdx.x * 128, n0 = blockIdx.y * 128;

    const int lrow = tid >> 2, lc = tid & 3;
    const uint32_t ldst = (uint32_t)(lrow * 80 + lc * 16);
    const __half* srcA  = A  + (size_t)(m0 + lrow) * K + lc * 8;
    const __half* srcBh = Bh + (size_t)(n0 + lrow) * K + lc * 8;

    const int nc = K / 32;
    #pragma unroll
    for (int st = 0; st < 3; st++) {
        uint32_t b = sbase + st * STAGE_B + ldst;
        int k0 = st * 32;
        cp16(b + 0 * TILE_B, srcA + k0);
        cp16(b + 1 * TILE_B, srcBh + k0);
        CP_COMMIT();
    }

    float acc[2][4][4];
    #pragma unroll
    for (int i = 0; i < 2; i++)
        #pragma unroll
        for (int j = 0; j < 4; j++)
            acc[i][j][0] = acc[i][j][1] = acc[i][j][2] = acc[i][j][3] = 0.f;

    const int a_row = warp_m * 32 + (lane & 15);
    const int a_colsel = (lane >> 4) * 8;
    const int b_row = warp_n * 32 + (lane & 7) + ((lane >> 4) << 3);
    const int b_colsel = ((lane >> 3) & 1) * 8;

    int stg = 0;
    for (int c = 0; c < nc; c++) {
        CP_WAIT2();
        __syncthreads();
        uint32_t stage = sbase + stg * STAGE_B;
        #pragma unroll
        for (int k16 = 0; k16 < 32; k16 += 16) {
            uint32_t af[2][4], bh4[2][4];
            #pragma unroll
            for (int mf2 = 0; mf2 < 2; mf2++) {
                uint32_t addr = stage + ((uint32_t)(a_row + mf2 * 16) * PITCH + k16 + a_colsel) * 2;
                ldm_x4(af[mf2][0], af[mf2][1], af[mf2][2], af[mf2][3], addr);
            }
            #pragma unroll
            for (int np = 0; np < 2; np++) {
                uint32_t addr = stage + ((uint32_t)(b_row + np * 16) * PITCH + k16 + b_colsel) * 2;
                ldm_x4(bh4[np][0], bh4[np][1], bh4[np][2], bh4[np][3], addr + 1 * TILE_B);
            }
            #pragma unroll
            for (int mf = 0; mf < 2; mf++)
                #pragma unroll
                for (int np = 0; np < 2; np++)
                    #pragma unroll
                    for (int sub = 0; sub < 2; sub++)
                        mma_f16(acc[mf][np * 2 + sub], af[mf][0], af[mf][1], af[mf][2], af[mf][3],
                                bh4[np][sub * 2], bh4[np][sub * 2 + 1]);
        }
        __syncthreads();
        if (c + 3 < nc) {
            uint32_t b = sbase + stg * STAGE_B + ldst;   // stage just consumed == (c+3)%3
            int k0 = (c + 3) * 32;
            cp16(b + 0 * TILE_B, srcA + k0);
            cp16(b + 1 * TILE_B, srcBh + k0);
        }
        CP_COMMIT();
        stg = (stg == 2) ? 0 : stg + 1;
    }

    #pragma unroll
    for (int mf = 0; mf < 2; mf++) {
        #pragma unroll
        for (int nf = 0; nf < 4; nf++) {
            #pragma unroll
            for (int hp = 0; hp < 2; hp++) {
                int r = m0 + warp_m * 32 + mf * 16 + (lane >> 2) + hp * 8;
                int n = n0 + warp_n * 32 + nf * 8 + ((lane & 3) << 1);
                size_t o = (size_t)r * NE + n;
                float2 rv = *(const float2*)&res[o];
                float2 ov;
                ov.x = rv.x + acc[mf][nf][hp * 2 + 0] + bias[n];
                ov.y = rv.y + acc[mf][nf][hp * 2 + 1] + bias[n + 1];
                *(float2*)&out0[o] = ov;
            }
        }
    }
}

// ================= flash attention (fp16; QK fp16-acc, PV fp32-acc) =========
#define AQT 128
#define AKT 64
#define APITCH 72
#define ATILE_B (AKT*APITCH*2)      /* 9216 */
#define ASTAGE_B (2*ATILE_B)        /* K,V = 18432 */
#define AQ_OFF (2*ASTAGE_B)         /* 36864 */
#define AT_SMEM (AQ_OFF + 128*APITCH*2)  /* 55296 */

__device__ __forceinline__ void flash_issue(uint32_t bs, int kt, int tid,
    const __half* Kp, const __half* Vp) {
    #pragma unroll
    for (int i2 = 0; i2 < 2; i2++) {
        int i = tid + i2 * 256;
        int r = i >> 3, ch = i & 7;
        uint32_t off = (uint32_t)(r * (APITCH * 2) + ch * 16);
        size_t g = (size_t)(kt * AKT + r) * HS + ch * 8;
        cp16(bs + 0 * ATILE_B + off, Kp + g);
        cp16(bs + 1 * ATILE_B + off, Vp + g);
    }
}

__global__ void __launch_bounds__(256, 1)
flash_kernel(const __half* __restrict__ qkv, __half* __restrict__ oo) {
    extern __shared__ __align__(128) char smem[];
    const uint32_t sbase = smem_u32(smem);
    const int tid = threadIdx.x, lane = tid & 31, wid = tid >> 5;
    const int bh = blockIdx.x, qt = blockIdx.y;
    const int b = bh / NH, h = bh - b * NH;
    const size_t TS = (size_t)MTOT * NE;
    const size_t base_bh = (size_t)bh * NT * HS;
    const __half* Qp = qkv + base_bh;
    const __half* Kp = qkv + TS + base_bh;
    const __half* Vp = qkv + 2 * TS + base_bh;

    for (int i = tid; i < 1024; i += 256) {
        int r = i >> 3, ch = i & 7;
        uint32_t off = (uint32_t)(r * (APITCH * 2) + ch * 16);
        cp16(sbase + AQ_OFF + off, Qp + (size_t)(qt * AQT + r) * HS + ch * 8);
    }
    flash_issue(sbase, 0, tid, Kp, Vp);
    CP_COMMIT();
    CP_WAIT0();
    __syncthreads();
    uint32_t qf[4][4];
    {
        int a_row = wid * 16 + (lane & 15);
        int a_col = (lane >> 4) * 8;
        #pragma unroll
        for (int ks = 0; ks < 4; ks++) {
            uint32_t ad = sbase + AQ_OFF + (uint32_t)((a_row * APITCH + ks * 16 + a_col) * 2);
            ldm_x4(qf[ks][0], qf[ks][1], qf[ks][2], qf[ks][3], ad);
        }
    }

    const int nkt = 2 * (qt + 1);
    float of[8][4];
    #pragma unroll
    for (int i = 0; i < 8; i++)
        #pragma unroll
        for (int j = 0; j < 4; j++) of[i][j] = 0.f;
    float m0 = -1e30f, m1 = -1e30f, l0 = 0.f, l1 = 0.f;
    const float scale = rsqrtf((float)NE);
    const int qrow0 = qt * AQT + wid * 16 + (lane >> 2);
    const int warp_qmax = qt * AQT + wid * 16 + 15;

    for (int kt = 0; kt < nkt; kt++) {
        if (kt + 1 < nkt) flash_issue(sbase + ((kt + 1) & 1) * ASTAGE_B, kt + 1, tid, Kp, Vp);
        CP_COMMIT();
        CP_WAIT1();
        __syncthreads();
        if (kt * AKT <= warp_qmax) {
            uint32_t kb = sbase + (kt & 1) * ASTAGE_B;
            uint32_t sc16[8][2];
            #pragma unroll
            for (int i = 0; i < 8; i++) { sc16[i][0] = 0u; sc16[i][1] = 0u; }
            #pragma unroll
            for (int ks = 0; ks < 4; ks++) {
                uint32_t bf[4][4];
                #pragma unroll
                for (int np = 0; np < 4; np++) {
                    int brow = np * 16 + (lane & 7) + ((lane >> 4) << 3);
                    int bcol = ks * 16 + ((lane >> 3) & 1) * 8;
                    uint32_t ad = kb + (uint32_t)((brow * APITCH + bcol) * 2);
                    ldm_x4(bf[np][0], bf[np][1], bf[np][2], bf[np][3], ad);
                }
                #pragma unroll
                for (int np = 0; np < 4; np++)
                    #pragma unroll
                    for (int sub = 0; sub < 2; sub++)
                        mma_f16acc(sc16[np * 2 + sub][0], sc16[np * 2 + sub][1],
                                   qf[ks][0], qf[ks][1], qf[ks][2], qf[ks][3],
                                   bf[np][sub * 2], bf[np][sub * 2 + 1]);
            }
            float sc[8][4];
            #pragma unroll
            for (int nf = 0; nf < 8; nf++) {
                sc[nf][0] = lo2f(sc16[nf][0]); sc[nf][1] = hi2f(sc16[nf][0]);
                sc[nf][2] = lo2f(sc16[nf][1]); sc[nf][3] = hi2f(sc16[nf][1]);
            }
            // scale + causal mask
            #pragma unroll
            for (int nf = 0; nf < 8; nf++)
                #pragma unroll
                for (int j = 0; j < 4; j++) {
                    int kcol = kt * AKT + nf * 8 + ((lane & 3) << 1) + (j & 1);
                    int qr = (j < 2) ? qrow0 : (qrow0 + 8);
                    sc[nf][j] = (kcol <= qr) ? sc[nf][j] * scale : -1e30f;
                }
            // online softmax
            float ml0 = -1e30f, ml1 = -1e30f;
            #pragma unroll
            for (int nf = 0; nf < 8; nf++) {
                ml0 = fmaxf(ml0, fmaxf(sc[nf][0], sc[nf][1]));
                ml1 = fmaxf(ml1, fmaxf(sc[nf][2], sc[nf][3]));
            }
            ml0 = fmaxf(ml0, __shfl_xor_sync(0xffffffffu, ml0, 1));
            ml0 = fmaxf(ml0, __shfl_xor_sync(0xffffffffu, ml0, 2));
            ml1 = fmaxf(ml1, __shfl_xor_sync(0xffffffffu, ml1, 1));
            ml1 = fmaxf(ml1, __shfl_xor_sync(0xffffffffu, ml1, 2));
            float mn0 = fmaxf(m0, ml0), mn1 = fmaxf(m1, ml1);
            float a0 = __expf(m0 - mn0), a1 = __expf(m1 - mn1);
            float rs0 = 0.f, rs1 = 0.f;
            #pragma unroll
            for (int nf = 0; nf < 8; nf++) {
                sc[nf][0] = __expf(sc[nf][0] - mn0); rs0 += sc[nf][0];
                sc[nf][1] = __expf(sc[nf][1] - mn0); rs0 += sc[nf][1];
                sc[nf][2] = __expf(sc[nf][2] - mn1); rs1 += sc[nf][2];
                sc[nf][3] = __expf(sc[nf][3] - mn1); rs1 += sc[nf][3];
            }
            rs0 += __shfl_xor_sync(0xffffffffu, rs0, 1);
            rs0 += __shfl_xor_sync(0xffffffffu, rs0, 2);
            rs1 += __shfl_xor_sync(0xffffffffu, rs1, 1);
            rs1 += __shfl_xor_sync(0xffffffffu, rs1, 2);
            #pragma unroll
            for (int nf = 0; nf < 8; nf++) {
                of[nf][0] *= a0; of[nf][1] *= a0;
                of[nf][2] *= a1; of[nf][3] *= a1;
            }
            l0 = l0 * a0 + rs0; l1 = l1 * a1 + rs1;
            m0 = mn0; m1 = mn1;
            // P @ V (fp32 acc)
            #pragma unroll
            for (int ks = 0; ks < 4; ks++) {
                uint32_t pf[4];
                pf[0] = pack2(sc[2 * ks][0], sc[2 * ks][1]);
                pf[1] = pack2(sc[2 * ks][2], sc[2 * ks][3]);
                pf[2] = pack2(sc[2 * ks + 1][0], sc[2 * ks + 1][1]);
                pf[3] = pack2(sc[2 * ks + 1][2], sc[2 * ks + 1][3]);
                uint32_t vf[4][4];
                #pragma unroll
                for (int nd = 0; nd < 4; nd++) {
                    int vrow = ks * 16 + (lane & 7) + (((lane >> 3) & 1) << 3);
                    int vcol = nd * 16 + ((lane >> 4) << 3);
                    uint32_t ad = kb + (uint32_t)((vrow * APITCH + vcol) * 2);
                    ldm_x4_t(vf[nd][0], vf[nd][1], vf[nd][2], vf[nd][3], ad + ATILE_B);
                }
                #pragma unroll
                for (int nd = 0; nd < 4; nd++)
                    #pragma unroll
                    for (int sub = 0; sub < 2; sub++)
                        mma_f16(of[nd * 2 + sub], pf[0], pf[1], pf[2], pf[3],
                                vf[nd][sub * 2], vf[nd][sub * 2 + 1]);
            }
        }
        __syncthreads();
    }

    float inv0 = 1.f / l0, inv1 = 1.f / l1;
    size_t row0 = ((size_t)b * NT + qrow0) * NE + h * HS;
    size_t row1 = row0 + (size_t)8 * NE;
    #pragma unroll
    for (int nf = 0; nf < 8; nf++) {
        int d = nf * 8 + ((lane & 3) << 1);
        *reinterpret_cast<uint32_t*>(&oo[row0 + d]) = pack2(of[nf][0] * inv0, of[nf][1] * inv0);
        *reinterpret_cast<uint32_t*>(&oo[row1 + d]) = pack2(of[nf][2] * inv1, of[nf][3] * inv1);
    }
}

// ================= fp32 SIMT gemm for LM head (N=65) =================
__global__ void gemm_lm_kernel(const float* __restrict__ A, const float* __restrict__ Bm,
                               const float* __restrict__ bias, float* __restrict__ C,
                               int N, int K) {
    __shared__ float As[16][64];
    __shared__ float Bs[16][68];
    int tid = threadIdx.x;
    int tx = tid & 15, ty = tid >> 4;
    int rowBase = blockIdx.x * 64, colBase = blockIdx.y * 64;
    float acc[4][4] = {};
    int la_m = tid >> 2, la_k = (tid & 3) * 4;
    int lb_k = tid >> 4, lb_n = (tid & 15) * 4;
    for (int k0 = 0; k0 < K; k0 += 16) {
        float4 a4 = *(const float4*)(A + (size_t)(rowBase + la_m) * K + k0 + la_k);
        As[la_k + 0][la_m] = a4.x; As[la_k + 1][la_m] = a4.y;
        As[la_k + 2][la_m] = a4.z; As[la_k + 3][la_m] = a4.w;
        #pragma unroll
        for (int u = 0; u < 4; u++) {
            int n = colBase + lb_n + u;
            Bs[lb_k][lb_n + u] = (n < N) ? Bm[(size_t)(k0 + lb_k) * N + n] : 0.f;
        }
        __syncthreads();
        #pragma unroll
        for (int kk = 0; kk < 16; kk++) {
            float4 a = *(float4*)&As[kk][ty * 4];
            float4 b = *(float4*)&Bs[kk][tx * 4];
            float av[4] = {a.x, a.y, a.z, a.w};
            float bv[4] = {b.x, b.y, b.z, b.w};
            #pragma unroll
            for (int i = 0; i < 4; i++)
                #pragma unroll
                for (int j = 0; j < 4; j++)
                    acc[i][j] += av[i] * bv[j];
        }
        __syncthreads();
    }
    #pragma unroll
    for (int i = 0; i < 4; i++) {
        int r = rowBase + ty * 4 + i;
        #pragma unroll
        for (int j = 0; j < 4; j++) {
            int c = colBase + tx * 4 + j;
            if (c >= N) continue;
            C[(size_t)r * N + c] = acc[i][j] + bias[c];
        }
    }
}

// ================= loss =================
__global__ void zero_loss_kernel() { g_loss = 0.0; }

__global__ void loss_kernel(const float* __restrict__ logits, const int* __restrict__ tgt) {
    int row = blockIdx.x * 8 + (threadIdx.x >> 5);
    int lane = threadIdx.x & 31;
    const float* lp = logits + (size_t)row * NV;
    float v0 = lp[lane];
    float v1 = (lane + 32 < NV) ? lp[lane + 32] : -1e30f;
    float v2 = (lane + 64 < NV) ? lp[lane + 64] : -1e30f;
    float m = fmaxf(v0, fmaxf(v1, v2));
    #pragma unroll
    for (int off = 16; off; off >>= 1) m = fmaxf(m, __shfl_xor_sync(0xffffffffu, m, off));
    float su = expf(v0 - m);
    if (lane + 32 < NV) su += expf(v1 - m);
    if (lane + 64 < NV) su += expf(v2 - m);
    #pragma unroll
    for (int off = 16; off; off >>= 1) su += __shfl_xor_sync(0xffffffffu, su, off);
    if (lane == 0) {
        float lt = lp[tgt[row]];
        double nl = -((double)lt - (double)m - (double)logf(su));
        atomicAdd(&g_loss, nl);
    }
}

__global__ void finalize_loss_kernel(float* __restrict__ out) {
    out[0] = (float)(g_loss / (double)MTOT);
}

// ================= launch =================
extern "C" void kernel_launch(void* const* d_in, const int* in_sizes, int n_in,
                              void* d_out, int out_size) {
    const int*   idx  = (const int*)d_in[0];
    const int*   tgt  = (const int*)d_in[1];
    const float* tok  = (const float*)d_in[2];
    const float* pos  = (const float*)d_in[3];
    const float* Wq   = (const float*)d_in[4];
    const float* Wk   = (const float*)d_in[5];
    const float* Wv   = (const float*)d_in[6];
    const float* Wpr  = (const float*)d_in[7];
    const float* bpr  = (const float*)d_in[8];
    const float* ln1g = (const float*)d_in[9];
    const float* ln1b = (const float*)d_in[10];
    const float* ln2g = (const float*)d_in[11];
    const float* ln2b = (const float*)d_in[12];
    const float* W1   = (const float*)d_in[13];
    const float* b1   = (const float*)d_in[14];
    const float* W2   = (const float*)d_in[15];
    const float* b2   = (const float*)d_in[16];
    const float* lnfg = (const float*)d_in[17];
    const float* lnfb = (const float*)d_in[18];
    const float* Wlm  = (const float*)d_in[19];
    const float* blm  = (const float*)d_in[20];
    float* out = (float*)d_out;

    float *px, *phf, *plog;
    __half *pqkv, *po16, *pm16;
    __half *wq, *wp, *w1, *w2;
    cudaGetSymbolAddress((void**)&px, g_x);
    cudaGetSymbolAddress((void**)&phf, g_hf);
    cudaGetSymbolAddress((void**)&plog, g_logits);
    cudaGetSymbolAddress((void**)&pqkv, g_qkv16);
    cudaGetSymbolAddress((void**)&po16, g_o16);
    cudaGetSymbolAddress((void**)&pm16, g_m16);
    cudaGetSymbolAddress((void**)&wq, g_wqkv);
    cudaGetSymbolAddress((void**)&wp, g_wpr);
    cudaGetSymbolAddress((void**)&w1, g_w1);
    cudaGetSymbolAddress((void**)&w2, g_w2);

    cudaFuncSetAttribute(flash_kernel, cudaFuncAttributeMaxDynamicSharedMemorySize, AT_SMEM);
    cudaFuncSetAttribute(gemm_res, cudaFuncAttributeMaxDynamicSharedMemorySize, HM_SMEM);
    cudaFuncSetAttribute(gemm_ln<0>, cudaFuncAttributeMaxDynamicSharedMemorySize, GLN_SMEM);
    cudaFuncSetAttribute(gemm_ln<2>, cudaFuncAttributeMaxDynamicSharedMemorySize, GLN_SMEM);

    prep_qkv_kernel<<<(NL * NQKV * NE + 255) / 256, 256>>>(Wq, Wk, Wv, wq);
    prep_t_kernel<<<(NL * NE * NE + 255) / 256, 256>>>(Wpr, wp, NE, NE);
    prep_t_kernel<<<(NL * NE * FF + 255) / 256, 256>>>(W1, w1, NE, FF);
    prep_t_kernel<<<(NL * FF * NE + 255) / 256, 256>>>(W2, w2, FF, NE);

    embed_kernel<<<(MTOT * NE + 255) / 256, 256>>>(idx, tok, pos);

    for (int l = 0; l < NL; l++) {
        gemm_ln<0><<<dim3(MTOT / 128, NQKV / 128), 512, GLN_SMEM>>>(
            px, ln1g + l * NE, ln1b + l * NE,
            wq + (size_t)l * NQKV * NE, nullptr, pqkv);
        flash_kernel<<<dim3(NB * NH, 2), 256, AT_SMEM>>>(pqkv, po16);
        gemm_res<<<dim3(MTOT / 128, NE / 128), 512, HM_SMEM>>>(
            po16, wp + (size_t)l * NE * NE, bpr + l * NE, px, px, NE);
        gemm_ln<2><<<dim3(MTOT / 128, FF / 128), 512, GLN_SMEM>>>(
            px, ln2g + l * NE, ln2b + l * NE,
            w1 + (size_t)l * FF * NE, b1 + l * FF, pm16);
        gemm_res<<<dim3(MTOT / 128, NE / 128), 512, HM_SMEM>>>(
            pm16, w2 + (size_t)l * NE * FF, b2 + l * NE, px, px, FF);
    }
    ln_kernel<<<MTOT, 128>>>(px, phf, lnfg, lnfb);

    const int NLOG = MTOT * NV;
    float* logits = (out_size >= NLOG) ? out : plog;
    gemm_lm_kernel<<<dim3(MTOT / 64, (NV + 63) / 64), 256>>>(phf, Wlm, blm, logits, NV, NE);

    zero_loss_kernel<<<1, 1>>>();
    loss_kernel<<<MTOT / 8, 256>>>(logits, tgt);
    if (out_size > NLOG)       finalize_loss_kernel<<<1, 1>>>(out + NLOG);
    else if (out_size >= 1 && out_size < NLOG) finalize_loss_kernel<<<1, 1>>>(out);
}